// round 8
// baseline (speedup 1.0000x reference)
#include <cuda_runtime.h>
#include <math.h>

// Problem constants
#define B_   2
#define S_   2048
#define HID_ 2560
#define H_   32
#define KV_  8
#define D_   80
#define G_   4
#define BS_  (B_*S_)      // 4096 total rows

// Scratch (device globals)
__device__ float g_Q[(size_t)BS_ * H_ * D_];
__device__ float g_K[(size_t)BS_ * KV_ * D_];
__device__ float g_V[(size_t)BS_ * KV_ * D_];
__device__ float g_ctx[(size_t)BS_ * H_ * D_];
__device__ float g_hs_r[(size_t)BS_ * HID_];
__device__ float g_Wq_r[(size_t)HID_ * H_ * D_];
__device__ float g_Wk_r[(size_t)HID_ * KV_ * D_];
__device__ float g_Wv_r[(size_t)HID_ * KV_ * D_];
__device__ float g_Wo_r[(size_t)H_ * D_ * HID_];

// ---------------------------------------------------------------------------
// Helpers
// ---------------------------------------------------------------------------
__device__ __forceinline__ unsigned smem_u32(const void* p) {
    return (unsigned)__cvta_generic_to_shared(p);
}
__device__ __forceinline__ void cp_async16(unsigned dst, const void* src) {
    asm volatile("cp.async.cg.shared.global [%0], [%1], 16;\n"
                 :: "r"(dst), "l"(src));
}
#define CP_COMMIT() asm volatile("cp.async.commit_group;\n" ::: "memory")
#define CP_WAIT0()  asm volatile("cp.async.wait_group 0;\n" ::: "memory")

__device__ __forceinline__ float tf32_rna(float v) {
    unsigned u;
    asm("cvt.rna.tf32.f32 %0, %1;" : "=r"(u) : "f"(v));
    return __uint_as_float(u);
}

__device__ __forceinline__ void mma_tf32(float* c, const unsigned* a, const unsigned* b) {
    asm volatile(
        "mma.sync.aligned.m16n8k8.row.col.f32.tf32.tf32.f32 "
        "{%0,%1,%2,%3}, {%4,%5,%6,%7}, {%8,%9}, {%0,%1,%2,%3};\n"
        : "+f"(c[0]), "+f"(c[1]), "+f"(c[2]), "+f"(c[3])
        : "r"(a[0]), "r"(a[1]), "r"(a[2]), "r"(a[3]), "r"(b[0]), "r"(b[1]));
}

// ---------------------------------------------------------------------------
// TF32 RNA rounding pre-pass
// ---------------------------------------------------------------------------
__global__ void round_tf32(const float4* __restrict__ in,
                           float4* __restrict__ out, int n4)
{
    int i = blockIdx.x * blockDim.x + threadIdx.x;
    if (i < n4) {
        float4 v = in[i];
        v.x = tf32_rna(v.x); v.y = tf32_rna(v.y);
        v.z = tf32_rna(v.z); v.w = tf32_rna(v.w);
        out[i] = v;
    }
}

// ---------------------------------------------------------------------------
// TF32 tensor-core GEMM. Round-2 layout (128x128 tile, 8 warps 2x4,
// double-buffered cp.async, 2 CTAs/SM) with BK widened 16 -> 32 to halve
// per-iteration drain/barrier overhead. A smem stride 36 (conflict-free:
// bank = (4r + kc) % 32 bijective over a warp); B stride 136 unchanged.
// ---------------------------------------------------------------------------
#define ASTR2 36
#define BSTR  136
#define GEMM_SMEM ((2 * 128 * ASTR2 + 2 * 32 * BSTR) * 4)   // 71680 B

__device__ __forceinline__ void gemm_core(
    const float* __restrict__ A, const float* __restrict__ Bm,
    float* __restrict__ C, int N, int K, int bm, int bn)
{
    extern __shared__ float gsm[];
    float* As = gsm;                         // 2 stages of 128*ASTR2
    float* Bs = gsm + 2 * 128 * ASTR2;       // 2 stages of 32*BSTR

    const int tid  = threadIdx.x;
    const int lane = tid & 31;
    const int w    = tid >> 5;
    const int wm   = (w >> 2) * 64;
    const int wn   = (w & 3) * 32;
    const int lr   = lane >> 2;
    const int lc   = lane & 3;

    const int a_r  = tid >> 1;           // 0..127
    const int a_c4 = (tid & 1) * 4;      // 0 or 4 (+ j*8)
    const int b_r  = tid >> 5;           // 0..7 (+ j*8)
    const int b_c4 = (tid & 31) * 4;     // 0..124

    float acc[4][4][4];
    #pragma unroll
    for (int mi = 0; mi < 4; mi++)
        #pragma unroll
        for (int nj = 0; nj < 4; nj++)
            #pragma unroll
            for (int u = 0; u < 4; u++) acc[mi][nj][u] = 0.f;

    const int T = K / 32;

    auto load_tile = [&](int kt, int buf) {
        float* as = As + buf * (128 * ASTR2);
        const float* ag = A + (size_t)(bm + a_r) * K + kt * 32 + a_c4;
        #pragma unroll
        for (int j = 0; j < 4; j++)
            cp_async16(smem_u32(&as[a_r * ASTR2 + a_c4 + j * 8]), ag + j * 8);
        float* bs = Bs + buf * (32 * BSTR);
        const float* bg = Bm + (size_t)(kt * 32 + b_r) * N + bn + b_c4;
        #pragma unroll
        for (int j = 0; j < 4; j++)
            cp_async16(smem_u32(&bs[(b_r + j * 8) * BSTR + b_c4]),
                       bg + (size_t)(j * 8) * N);
    };

    load_tile(0, 0);
    CP_COMMIT();

    for (int kt = 0; kt < T; kt++) {
        const int buf = kt & 1;
        CP_WAIT0();
        __syncthreads();
        if (kt + 1 < T) {
            load_tile(kt + 1, buf ^ 1);
            CP_COMMIT();
        }
        const float* as = As + buf * (128 * ASTR2);
        const float* bs = Bs + buf * (32 * BSTR);
        #pragma unroll
        for (int ks = 0; ks < 4; ks++) {
            const int kc = lc + ks * 8;
            unsigned af[4][4], bf[4][2];
            #pragma unroll
            for (int mi = 0; mi < 4; mi++) {
                int r = wm + mi * 16 + lr;
                af[mi][0] = __float_as_uint(as[r * ASTR2 + kc]);
                af[mi][1] = __float_as_uint(as[(r + 8) * ASTR2 + kc]);
                af[mi][2] = __float_as_uint(as[r * ASTR2 + kc + 4]);
                af[mi][3] = __float_as_uint(as[(r + 8) * ASTR2 + kc + 4]);
            }
            #pragma unroll
            for (int nj = 0; nj < 4; nj++) {
                int cn = wn + nj * 8 + lr;
                bf[nj][0] = __float_as_uint(bs[kc * BSTR + cn]);
                bf[nj][1] = __float_as_uint(bs[(kc + 4) * BSTR + cn]);
            }
            #pragma unroll
            for (int mi = 0; mi < 4; mi++)
                #pragma unroll
                for (int nj = 0; nj < 4; nj++)
                    mma_tf32(acc[mi][nj], af[mi], bf[nj]);
        }
        __syncthreads();
    }

    #pragma unroll
    for (int mi = 0; mi < 4; mi++) {
        int r0 = bm + wm + mi * 16 + lr;
        #pragma unroll
        for (int nj = 0; nj < 4; nj++) {
            int cn = bn + wn + nj * 8 + 2 * lc;
            *(float2*)&C[(size_t)r0 * N + cn] =
                make_float2(acc[mi][nj][0], acc[mi][nj][1]);
            *(float2*)&C[(size_t)(r0 + 8) * N + cn] =
                make_float2(acc[mi][nj][2], acc[mi][nj][3]);
        }
    }
}

__global__ __launch_bounds__(256, 2) void gemm_tf32(
    const float* __restrict__ A, const float* __restrict__ Bm,
    float* __restrict__ C, int N, int K)
{
    gemm_core(A, Bm, C, N, K, blockIdx.y * 128, blockIdx.x * 128);
}

__global__ __launch_bounds__(256, 2) void gemm_qkv(
    const float* __restrict__ A,
    const float* __restrict__ Wq, float* __restrict__ Qo,
    const float* __restrict__ Wk, float* __restrict__ Ko,
    const float* __restrict__ Wv, float* __restrict__ Vo)
{
    const int bx = blockIdx.x;
    const int bm = blockIdx.y * 128;
    if (bx < 20)       gemm_core(A, Wq, Qo, HID_,      HID_, bm, bx * 128);
    else if (bx < 25)  gemm_core(A, Wk, Ko, KV_ * D_,  HID_, bm, (bx - 20) * 128);
    else               gemm_core(A, Wv, Vo, KV_ * D_,  HID_, bm, (bx - 25) * 128);
}

// ---------------------------------------------------------------------------
// RoPE (in-place)
// ---------------------------------------------------------------------------
__global__ void rope_kernel(float* __restrict__ X,
                            const float* __restrict__ cosf,
                            const float* __restrict__ sinf,
                            int nheads, size_t total)
{
    size_t idx = (size_t)blockIdx.x * blockDim.x + threadIdx.x;
    if (idx >= total) return;
    int d = (int)(idx % 40);
    size_t t = idx / 40;
    int head = (int)(t % nheads);
    size_t row = t / nheads;
    int s = (int)(row % S_);

    float* base = X + row * ((size_t)nheads * D_) + (size_t)head * D_;
    float x1 = base[d];
    float x2 = base[d + 40];
    float c1 = cosf[(size_t)s * D_ + d];
    float s1 = sinf[(size_t)s * D_ + d];
    float c2 = cosf[(size_t)s * D_ + d + 40];
    float s2 = sinf[(size_t)s * D_ + d + 40];
    base[d]      = x1 * c1 - x2 * s1;
    base[d + 40] = x2 * c2 + x1 * s2;
}

// ---------------------------------------------------------------------------
// Flash attention, 2 query heads per block (GQA K/V sharing), with raw K/V
// prefetched via cp.async IN PLACE into Khi/Vhi (split happens at top of the
// next iteration). K prefetch issued once Khi is dead (post-QK barrier);
// V prefetch once Vhi is dead (post-PV barrier). Arithmetic identical to R7.
// ---------------------------------------------------------------------------
#define AQ 84
#define AV 88
#define AP 68

__global__ __launch_bounds__(256, 1) void attn_mma2(
    const float* __restrict__ Q, const float* __restrict__ K,
    const float* __restrict__ V, float* __restrict__ O)
{
    extern __shared__ float sm[];
    float* Qhi0 = sm;                    // 64*AQ each
    float* Qlo0 = Qhi0 + 64 * AQ;
    float* Qhi1 = Qlo0 + 64 * AQ;
    float* Qlo1 = Qhi1 + 64 * AQ;
    float* Khi  = Qlo1 + 64 * AQ;
    float* Klo  = Khi  + 64 * AQ;
    float* Vhi  = Klo  + 64 * AQ;        // 64*AV each
    float* Vlo  = Vhi  + 64 * AV;
    float* Ph0  = Vlo  + 64 * AV;        // 64*AP each
    float* Ph1  = Ph0  + 64 * AP;
    float* cr0  = Ph1  + 64 * AP;        // 64 each
    float* cr1  = cr0  + 64;

    const int tid  = threadIdx.x;
    const int lane = tid & 31;
    const int w    = tid >> 5;
    const int lr   = lane >> 2;
    const int lc   = lane & 3;
    const int wm   = (w >> 1) * 16;
    const int wnq  = (w & 1) * 32;
    const int wnp  = (w & 1) * 40;

    const int by  = blockIdx.y;          // 0..31
    const int b   = by >> 4;
    const int kvh = (by >> 1) & 7;
    const int hp  = by & 1;
    const int h0  = kvh * G_ + hp * 2;   // heads h0, h0+1
    const int q0  = blockIdx.x * 64;
    const float rscale = 0.11180339887498949f;

    // Prefetch raw K/V tile 0 into Khi/Vhi (split in-place at loop top)
    for (int i = tid; i < 64 * 20; i += 256) {
        int r = i / 20, c4 = (i % 20) * 4;
        size_t base = ((size_t)(b * S_ + r)) * (KV_ * D_) + kvh * D_ + c4;
        cp_async16(smem_u32(Khi + r * AQ + c4), K + base);
        cp_async16(smem_u32(Vhi + r * AV + c4), V + base);
    }
    CP_COMMIT();

    // Load + scale + split Q for both heads (overlaps with the prefetch)
    #pragma unroll
    for (int hh = 0; hh < 2; hh++) {
        float* qh = hh ? Qhi1 : Qhi0;
        float* ql = hh ? Qlo1 : Qlo0;
        for (int i = tid; i < 64 * 20; i += 256) {
            int r = i / 20, c4 = (i % 20) * 4;
            float4 v = *(const float4*)(Q + ((size_t)(b * S_ + q0 + r)) * (H_ * D_)
                                          + (h0 + hh) * D_ + c4);
            v.x *= rscale; v.y *= rscale; v.z *= rscale; v.w *= rscale;
            float4 hi, lo;
            hi.x = tf32_rna(v.x); lo.x = tf32_rna(v.x - hi.x);
            hi.y = tf32_rna(v.y); lo.y = tf32_rna(v.y - hi.y);
            hi.z = tf32_rna(v.z); lo.z = tf32_rna(v.z - hi.z);
            hi.w = tf32_rna(v.w); lo.w = tf32_rna(v.w - hi.w);
            *(float4*)(qh + r * AQ + c4) = hi;
            *(float4*)(ql + r * AQ + c4) = lo;
        }
    }

    const int myrow = tid >> 2;
    const int myg   = tid & 3;
    float mm[2] = {-1e30f, -1e30f};
    float ll[2] = {0.f, 0.f};

    float co[2][5][4];
    #pragma unroll
    for (int hh = 0; hh < 2; hh++)
        #pragma unroll
        for (int nj = 0; nj < 5; nj++)
            #pragma unroll
            for (int u = 0; u < 4; u++) co[hh][nj][u] = 0.f;

    for (int k0 = 0; k0 <= q0; k0 += 64) {
        CP_WAIT0();
        __syncthreads();   // raw K/V visible; Q writes visible (first iter)

        // In-place hi/lo split of raw K/V
        for (int i = tid; i < 64 * 20; i += 256) {
            int r = i / 20, c4 = (i % 20) * 4;
            float4 kv = *(const float4*)(Khi + r * AQ + c4);
            float4 vv = *(const float4*)(Vhi + r * AV + c4);
            float4 hi, lo;
            hi.x = tf32_rna(kv.x); lo.x = tf32_rna(kv.x - hi.x);
            hi.y = tf32_rna(kv.y); lo.y = tf32_rna(kv.y - hi.y);
            hi.z = tf32_rna(kv.z); lo.z = tf32_rna(kv.z - hi.z);
            hi.w = tf32_rna(kv.w); lo.w = tf32_rna(kv.w - hi.w);
            *(float4*)(Khi + r * AQ + c4) = hi;
            *(float4*)(Klo + r * AQ + c4) = lo;
            hi.x = tf32_rna(vv.x); lo.x = tf32_rna(vv.x - hi.x);
            hi.y = tf32_rna(vv.y); lo.y = tf32_rna(vv.y - hi.y);
            hi.z = tf32_rna(vv.z); lo.z = tf32_rna(vv.z - hi.z);
            hi.w = tf32_rna(vv.w); lo.w = tf32_rna(vv.w - hi.w);
            *(float4*)(Vhi + r * AV + c4) = hi;
            *(float4*)(Vlo + r * AV + c4) = lo;
        }
        __syncthreads();

        // QK^T for both heads
        #pragma unroll
        for (int hh = 0; hh < 2; hh++) {
            const float* Qh = hh ? Qhi1 : Qhi0;
            const float* Ql = hh ? Qlo1 : Qlo0;
            float* Ps = hh ? Ph1 : Ph0;

            float cq[4][4];
            #pragma unroll
            for (int nj = 0; nj < 4; nj++)
                #pragma unroll
                for (int u = 0; u < 4; u++) cq[nj][u] = 0.f;

            #pragma unroll
            for (int ks = 0; ks < 10; ks++) {
                const int kc = ks * 8 + lc;
                unsigned ah[4], al[4];
                ah[0] = __float_as_uint(Qh[(wm + lr) * AQ + kc]);
                ah[1] = __float_as_uint(Qh[(wm + lr + 8) * AQ + kc]);
                ah[2] = __float_as_uint(Qh[(wm + lr) * AQ + kc + 4]);
                ah[3] = __float_as_uint(Qh[(wm + lr + 8) * AQ + kc + 4]);
                al[0] = __float_as_uint(Ql[(wm + lr) * AQ + kc]);
                al[1] = __float_as_uint(Ql[(wm + lr + 8) * AQ + kc]);
                al[2] = __float_as_uint(Ql[(wm + lr) * AQ + kc + 4]);
                al[3] = __float_as_uint(Ql[(wm + lr + 8) * AQ + kc + 4]);
                #pragma unroll
                for (int nj = 0; nj < 4; nj++) {
                    int cn = wnq + nj * 8 + lr;
                    unsigned bh_[2], bl_[2];
                    bh_[0] = __float_as_uint(Khi[cn * AQ + kc]);
                    bh_[1] = __float_as_uint(Khi[cn * AQ + kc + 4]);
                    bl_[0] = __float_as_uint(Klo[cn * AQ + kc]);
                    bl_[1] = __float_as_uint(Klo[cn * AQ + kc + 4]);
                    mma_tf32(cq[nj], ah, bh_);
                    mma_tf32(cq[nj], al, bh_);
                    mma_tf32(cq[nj], ah, bl_);
                }
            }

            #pragma unroll
            for (int nj = 0; nj < 4; nj++) {
                int col = wnq + nj * 8 + 2 * lc;
                int r0 = wm + lr, r1 = wm + lr + 8;
                Ps[r0 * AP + col]     = (k0 + col     <= q0 + r0) ? cq[nj][0] : -1e30f;
                Ps[r0 * AP + col + 1] = (k0 + col + 1 <= q0 + r0) ? cq[nj][1] : -1e30f;
                Ps[r1 * AP + col]     = (k0 + col     <= q0 + r1) ? cq[nj][2] : -1e30f;
                Ps[r1 * AP + col + 1] = (k0 + col + 1 <= q0 + r1) ? cq[nj][3] : -1e30f;
            }
        }
        __syncthreads();   // Ph ready; Khi/Klo dead from here on

        // Prefetch raw K for next ktile into Khi
        if (k0 + 64 <= q0) {
            const int kn = k0 + 64;
            for (int i = tid; i < 64 * 20; i += 256) {
                int r = i / 20, c4 = (i % 20) * 4;
                size_t base = ((size_t)(b * S_ + kn + r)) * (KV_ * D_) + kvh * D_ + c4;
                cp_async16(smem_u32(Khi + r * AQ + c4), K + base);
            }
        }
        CP_COMMIT();

        // Online softmax, both heads
        #pragma unroll
        for (int hh = 0; hh < 2; hh++) {
            float* Ps = hh ? Ph1 : Ph0;
            float* crh = hh ? cr1 : cr0;
            float s[16];
            #pragma unroll
            for (int j4 = 0; j4 < 4; j4++) {
                float4 v4 = *(const float4*)(Ps + myrow * AP + myg * 16 + j4 * 4);
                s[j4 * 4 + 0] = v4.x; s[j4 * 4 + 1] = v4.y;
                s[j4 * 4 + 2] = v4.z; s[j4 * 4 + 3] = v4.w;
            }
            float mx = s[0];
            #pragma unroll
            for (int j = 1; j < 16; j++) mx = fmaxf(mx, s[j]);
            mx = fmaxf(mx, __shfl_xor_sync(0xffffffffu, mx, 1));
            mx = fmaxf(mx, __shfl_xor_sync(0xffffffffu, mx, 2));
            float mnew = fmaxf(mm[hh], mx);
            float corr = __expf(mm[hh] - mnew);
            float rs = 0.f;
            #pragma unroll
            for (int j = 0; j < 16; j++) {
                float p = __expf(s[j] - mnew);
                rs += p;
                Ps[myrow * AP + myg * 16 + j] = tf32_rna(p);
            }
            rs += __shfl_xor_sync(0xffffffffu, rs, 1);
            rs += __shfl_xor_sync(0xffffffffu, rs, 2);
            mm[hh] = mnew;
            ll[hh] = ll[hh] * corr + rs;
            if (myg == 0) crh[myrow] = corr;
        }
        __syncthreads();

        // Rescale + PV, both heads
        #pragma unroll
        for (int hh = 0; hh < 2; hh++) {
            const float* Ps = hh ? Ph1 : Ph0;
            const float* crh = hh ? cr1 : cr0;
            float c0 = crh[wm + lr], c1 = crh[wm + lr + 8];
            #pragma unroll
            for (int nj = 0; nj < 5; nj++) {
                co[hh][nj][0] *= c0; co[hh][nj][1] *= c0;
                co[hh][nj][2] *= c1; co[hh][nj][3] *= c1;
            }
            #pragma unroll
            for (int ks = 0; ks < 8; ks++) {
                const int kc = ks * 8 + lc;
                unsigned a[4];
                a[0] = __float_as_uint(Ps[(wm + lr) * AP + kc]);
                a[1] = __float_as_uint(Ps[(wm + lr + 8) * AP + kc]);
                a[2] = __float_as_uint(Ps[(wm + lr) * AP + kc + 4]);
                a[3] = __float_as_uint(Ps[(wm + lr + 8) * AP + kc + 4]);
                #pragma unroll
                for (int nj = 0; nj < 5; nj++) {
                    int cn = wnp + nj * 8 + lr;
                    unsigned bh_[2], bl_[2];
                    bh_[0] = __float_as_uint(Vhi[(kc)     * AV + cn]);
                    bh_[1] = __float_as_uint(Vhi[(kc + 4) * AV + cn]);
                    bl_[0] = __float_as_uint(Vlo[(kc)     * AV + cn]);
                    bl_[1] = __float_as_uint(Vlo[(kc + 4) * AV + cn]);
                    mma_tf32(co[hh][nj], a, bh_);
                    mma_tf32(co[hh][nj], a, bl_);
                }
            }
        }
        __syncthreads();   // all warps done with Vhi/Vlo (and Ph, cr)

        // Prefetch raw V for next ktile into Vhi
        if (k0 + 64 <= q0) {
            const int kn = k0 + 64;
            for (int i = tid; i < 64 * 20; i += 256) {
                int r = i / 20, c4 = (i % 20) * 4;
                size_t base = ((size_t)(b * S_ + kn + r)) * (KV_ * D_) + kvh * D_ + c4;
                cp_async16(smem_u32(Vhi + r * AV + c4), V + base);
            }
        }
        CP_COMMIT();
    }

    // Epilogue (post-PV barrier from the last iteration already executed)
    if (myg == 0) { cr0[myrow] = 1.f / ll[0]; cr1[myrow] = 1.f / ll[1]; }
    __syncthreads();
    #pragma unroll
    for (int hh = 0; hh < 2; hh++) {
        const float* crh = hh ? cr1 : cr0;
        float i0 = crh[wm + lr], i1 = crh[wm + lr + 8];
        size_t ro0 = ((size_t)(b * S_ + q0 + wm + lr)) * (H_ * D_) + (h0 + hh) * D_;
        size_t ro1 = ((size_t)(b * S_ + q0 + wm + lr + 8)) * (H_ * D_) + (h0 + hh) * D_;
        #pragma unroll
        for (int nj = 0; nj < 5; nj++) {
            int col = wnp + nj * 8 + 2 * lc;
            *(float2*)(O + ro0 + col) =
                make_float2(tf32_rna(co[hh][nj][0] * i0), tf32_rna(co[hh][nj][1] * i0));
            *(float2*)(O + ro1 + col) =
                make_float2(tf32_rna(co[hh][nj][2] * i1), tf32_rna(co[hh][nj][3] * i1));
        }
    }
}

// ---------------------------------------------------------------------------
// Launch
// ---------------------------------------------------------------------------
extern "C" void kernel_launch(void* const* d_in, const int* in_sizes, int n_in,
                              void* d_out, int out_size)
{
    const float* hs   = (const float*)d_in[0];
    const float* cosf = (const float*)d_in[1];
    const float* sinf = (const float*)d_in[2];
    const float* Wq   = (const float*)d_in[3];
    const float* Wk   = (const float*)d_in[4];
    const float* Wv   = (const float*)d_in[5];
    const float* Wo   = (const float*)d_in[6];
    float* out = (float*)d_out;

    float *Qp, *Kp, *Vp, *Cp, *HSr, *Wqr, *Wkr, *Wvr, *Wor;
    cudaGetSymbolAddress((void**)&Qp,  g_Q);
    cudaGetSymbolAddress((void**)&Kp,  g_K);
    cudaGetSymbolAddress((void**)&Vp,  g_V);
    cudaGetSymbolAddress((void**)&Cp,  g_ctx);
    cudaGetSymbolAddress((void**)&HSr, g_hs_r);
    cudaGetSymbolAddress((void**)&Wqr, g_Wq_r);
    cudaGetSymbolAddress((void**)&Wkr, g_Wk_r);
    cudaGetSymbolAddress((void**)&Wvr, g_Wv_r);
    cudaGetSymbolAddress((void**)&Wor, g_Wo_r);

    // TF32 RNA pre-rounding
    {
        auto rnd = [](const float* src, float* dst, size_t n) {
            int n4 = (int)(n / 4);
            round_tf32<<<(n4 + 255) / 256, 256>>>(
                (const float4*)src, (float4*)dst, n4);
        };
        rnd(hs, HSr, (size_t)BS_ * HID_);
        rnd(Wq, Wqr, (size_t)HID_ * H_ * D_);
        rnd(Wk, Wkr, (size_t)HID_ * KV_ * D_);
        rnd(Wv, Wvr, (size_t)HID_ * KV_ * D_);
        rnd(Wo, Wor, (size_t)H_ * D_ * HID_);
    }

    // GEMM smem attribute (dynamic, BK=32 double buffer)
    cudaFuncSetAttribute(gemm_qkv,
                         cudaFuncAttributeMaxDynamicSharedMemorySize, GEMM_SMEM);
    cudaFuncSetAttribute(gemm_tf32,
                         cudaFuncAttributeMaxDynamicSharedMemorySize, GEMM_SMEM);

    // Fused QKV projection
    {
        dim3 g(30, BS_ / 128);
        gemm_qkv<<<g, 256, GEMM_SMEM>>>(HSr, Wqr, Qp, Wkr, Kp, Wvr, Vp);
    }

    // RoPE on Q and K
    {
        size_t tq = (size_t)BS_ * H_ * 40;
        size_t tk = (size_t)BS_ * KV_ * 40;
        rope_kernel<<<(unsigned)((tq + 255) / 256), 256>>>(Qp, cosf, sinf, H_, tq);
        rope_kernel<<<(unsigned)((tk + 255) / 256), 256>>>(Kp, cosf, sinf, KV_, tk);
    }

    // Attention: 2 heads per block, GQA K/V sharing, cp.async K/V pipeline
    {
        const int smem = (6 * 64 * AQ + 2 * 64 * AV + 2 * 64 * AP + 128)
                         * (int)sizeof(float);   // 209,408 B
        cudaFuncSetAttribute(attn_mma2,
                             cudaFuncAttributeMaxDynamicSharedMemorySize, smem);
        dim3 ga(S_ / 64, B_ * KV_ * 2);          // (32, 32)
        attn_mma2<<<ga, 256, smem>>>(Qp, Kp, Vp, Cp);
    }

    // Output projection
    {
        dim3 go(HID_ / 128, BS_ / 128);
        gemm_tf32<<<go, 256, GEMM_SMEM>>>(Cp, Wor, out, HID_, HID_);
    }
}

// round 9
// speedup vs baseline: 1.0875x; 1.0875x over previous
#include <cuda_runtime.h>
#include <math.h>

// Problem constants
#define B_   2
#define S_   2048
#define HID_ 2560
#define H_   32
#define KV_  8
#define D_   80
#define G_   4
#define BS_  (B_*S_)      // 4096 total rows

// Scratch (device globals)
__device__ float g_Q[(size_t)BS_ * H_ * D_];
__device__ float g_K[(size_t)BS_ * KV_ * D_];
__device__ float g_V[(size_t)BS_ * KV_ * D_];
__device__ float g_ctx[(size_t)BS_ * H_ * D_];
__device__ float g_hs_r[(size_t)BS_ * HID_];
__device__ float g_Wq_r[(size_t)HID_ * H_ * D_];
__device__ float g_Wk_r[(size_t)HID_ * KV_ * D_];
__device__ float g_Wv_r[(size_t)HID_ * KV_ * D_];
__device__ float g_Wo_r[(size_t)H_ * D_ * HID_];

// ---------------------------------------------------------------------------
// Helpers
// ---------------------------------------------------------------------------
__device__ __forceinline__ unsigned smem_u32(const void* p) {
    return (unsigned)__cvta_generic_to_shared(p);
}
__device__ __forceinline__ void cp_async16(unsigned dst, const void* src) {
    asm volatile("cp.async.cg.shared.global [%0], [%1], 16;\n"
                 :: "r"(dst), "l"(src));
}
#define CP_COMMIT() asm volatile("cp.async.commit_group;\n" ::: "memory")
#define CP_WAIT0()  asm volatile("cp.async.wait_group 0;\n" ::: "memory")

__device__ __forceinline__ float tf32_rna(float v) {
    unsigned u;
    asm("cvt.rna.tf32.f32 %0, %1;" : "=r"(u) : "f"(v));
    return __uint_as_float(u);
}

__device__ __forceinline__ void mma_tf32(float* c, const unsigned* a, const unsigned* b) {
    asm volatile(
        "mma.sync.aligned.m16n8k8.row.col.f32.tf32.tf32.f32 "
        "{%0,%1,%2,%3}, {%4,%5,%6,%7}, {%8,%9}, {%0,%1,%2,%3};\n"
        : "+f"(c[0]), "+f"(c[1]), "+f"(c[2]), "+f"(c[3])
        : "r"(a[0]), "r"(a[1]), "r"(a[2]), "r"(a[3]), "r"(b[0]), "r"(b[1]));
}

// ---------------------------------------------------------------------------
// TF32 RNA rounding pre-passes
// ---------------------------------------------------------------------------
__global__ void round_tf32(const float4* __restrict__ in,
                           float4* __restrict__ out, int n4)
{
    int i = blockIdx.x * blockDim.x + threadIdx.x;
    if (i < n4) {
        float4 v = in[i];
        v.x = tf32_rna(v.x); v.y = tf32_rna(v.y);
        v.z = tf32_rna(v.z); v.w = tf32_rna(v.w);
        out[i] = v;
    }
}

// All 4 weight matrices in one launch. Ranges (in float4):
// Wq [0, 1638400), Wk [.., +409600), Wv [.., +409600), Wo [.., +1638400)
#define WQ4 1638400
#define WK4 409600
__global__ void round_weights(
    const float4* __restrict__ Wq, float4* __restrict__ Wqo,
    const float4* __restrict__ Wk, float4* __restrict__ Wko,
    const float4* __restrict__ Wv, float4* __restrict__ Wvo,
    const float4* __restrict__ Wo, float4* __restrict__ Woo)
{
    int i = blockIdx.x * blockDim.x + threadIdx.x;
    const float4* src; float4* dst; int off;
    if (i < WQ4)                         { src = Wq; dst = Wqo; off = 0; }
    else if (i < WQ4 + WK4)              { src = Wk; dst = Wko; off = WQ4; }
    else if (i < WQ4 + 2 * WK4)          { src = Wv; dst = Wvo; off = WQ4 + WK4; }
    else if (i < 2 * WQ4 + 2 * WK4)      { src = Wo; dst = Woo; off = WQ4 + 2 * WK4; }
    else return;
    int j = i - off;
    float4 v = src[j];
    v.x = tf32_rna(v.x); v.y = tf32_rna(v.y);
    v.z = tf32_rna(v.z); v.w = tf32_rna(v.w);
    dst[j] = v;
}

// ---------------------------------------------------------------------------
// TF32 tensor-core GEMM (round-2 proven config, untouched)
// ---------------------------------------------------------------------------
#define ASTR 20
#define BSTR 136

__device__ __forceinline__ void gemm_core(
    const float* __restrict__ A, const float* __restrict__ Bm,
    float* __restrict__ C, int N, int K, int bm, int bn)
{
    __shared__ float As[2][128 * ASTR];
    __shared__ float Bs[2][16 * BSTR];

    const int tid  = threadIdx.x;
    const int lane = tid & 31;
    const int w    = tid >> 5;
    const int wm   = (w >> 2) * 64;
    const int wn   = (w & 3) * 32;
    const int lr   = lane >> 2;
    const int lc   = lane & 3;

    const int a_row = tid >> 2;
    const int a_col = (tid & 3) * 4;
    const int b_row = tid >> 5;
    const int b_col = (tid & 31) * 4;

    float acc[4][4][4];
    #pragma unroll
    for (int mi = 0; mi < 4; mi++)
        #pragma unroll
        for (int nj = 0; nj < 4; nj++)
            #pragma unroll
            for (int u = 0; u < 4; u++) acc[mi][nj][u] = 0.f;

    const int T = K / 16;

    auto load_tile = [&](int kt, int buf) {
        const float* ag = A + (size_t)(bm + a_row) * K + kt * 16 + a_col;
        unsigned as0 = smem_u32(&As[buf][a_row * ASTR + a_col]);
        cp_async16(as0, ag);
        cp_async16(as0 + 64 * ASTR * 4, ag + (size_t)64 * K);
        const float* bg = Bm + (size_t)(kt * 16 + b_row) * N + bn + b_col;
        unsigned bs0 = smem_u32(&Bs[buf][b_row * BSTR + b_col]);
        cp_async16(bs0, bg);
        cp_async16(bs0 + 8 * BSTR * 4, bg + (size_t)8 * N);
    };

    load_tile(0, 0);
    CP_COMMIT();

    for (int kt = 0; kt < T; kt++) {
        const int buf = kt & 1;
        CP_WAIT0();
        __syncthreads();
        if (kt + 1 < T) {
            load_tile(kt + 1, buf ^ 1);
            CP_COMMIT();
        }
        #pragma unroll
        for (int ks = 0; ks < 2; ks++) {
            const int kc = lc + ks * 8;
            unsigned af[4][4], bf[4][2];
            #pragma unroll
            for (int mi = 0; mi < 4; mi++) {
                int r = wm + mi * 16 + lr;
                af[mi][0] = __float_as_uint(As[buf][r * ASTR + kc]);
                af[mi][1] = __float_as_uint(As[buf][(r + 8) * ASTR + kc]);
                af[mi][2] = __float_as_uint(As[buf][r * ASTR + kc + 4]);
                af[mi][3] = __float_as_uint(As[buf][(r + 8) * ASTR + kc + 4]);
            }
            #pragma unroll
            for (int nj = 0; nj < 4; nj++) {
                int cn = wn + nj * 8 + lr;
                bf[nj][0] = __float_as_uint(Bs[buf][kc * BSTR + cn]);
                bf[nj][1] = __float_as_uint(Bs[buf][(kc + 4) * BSTR + cn]);
            }
            #pragma unroll
            for (int mi = 0; mi < 4; mi++)
                #pragma unroll
                for (int nj = 0; nj < 4; nj++)
                    mma_tf32(acc[mi][nj], af[mi], bf[nj]);
        }
        __syncthreads();
    }

    #pragma unroll
    for (int mi = 0; mi < 4; mi++) {
        int r0 = bm + wm + mi * 16 + lr;
        #pragma unroll
        for (int nj = 0; nj < 4; nj++) {
            int cn = bn + wn + nj * 8 + 2 * lc;
            *(float2*)&C[(size_t)r0 * N + cn] =
                make_float2(acc[mi][nj][0], acc[mi][nj][1]);
            *(float2*)&C[(size_t)(r0 + 8) * N + cn] =
                make_float2(acc[mi][nj][2], acc[mi][nj][3]);
        }
    }
}

__global__ __launch_bounds__(256, 2) void gemm_tf32(
    const float* __restrict__ A, const float* __restrict__ Bm,
    float* __restrict__ C, int N, int K)
{
    gemm_core(A, Bm, C, N, K, blockIdx.y * 128, blockIdx.x * 128);
}

__global__ __launch_bounds__(256, 2) void gemm_qkv(
    const float* __restrict__ A,
    const float* __restrict__ Wq, float* __restrict__ Qo,
    const float* __restrict__ Wk, float* __restrict__ Ko,
    const float* __restrict__ Wv, float* __restrict__ Vo)
{
    const int bx = blockIdx.x;
    const int bm = blockIdx.y * 128;
    if (bx < 20)       gemm_core(A, Wq, Qo, HID_,      HID_, bm, bx * 128);
    else if (bx < 25)  gemm_core(A, Wk, Ko, KV_ * D_,  HID_, bm, (bx - 20) * 128);
    else               gemm_core(A, Wv, Vo, KV_ * D_,  HID_, bm, (bx - 25) * 128);
}

// ---------------------------------------------------------------------------
// RoPE (in-place)
// ---------------------------------------------------------------------------
__global__ void rope_kernel(float* __restrict__ X,
                            const float* __restrict__ cosf,
                            const float* __restrict__ sinf,
                            int nheads, size_t total)
{
    size_t idx = (size_t)blockIdx.x * blockDim.x + threadIdx.x;
    if (idx >= total) return;
    int d = (int)(idx % 40);
    size_t t = idx / 40;
    int head = (int)(t % nheads);
    size_t row = t / nheads;
    int s = (int)(row % S_);

    float* base = X + row * ((size_t)nheads * D_) + (size_t)head * D_;
    float x1 = base[d];
    float x2 = base[d + 40];
    float c1 = cosf[(size_t)s * D_ + d];
    float s1 = sinf[(size_t)s * D_ + d];
    float c2 = cosf[(size_t)s * D_ + d + 40];
    float s2 = sinf[(size_t)s * D_ + d + 40];
    base[d]      = x1 * c1 - x2 * s1;
    base[d + 40] = x2 * c2 + x1 * s2;
}

// ---------------------------------------------------------------------------
// Flash attention, 2 query heads per block (GQA K/V sharing).
// Next-tile raw K/V staged in REGISTERS: LDGs issued right after the QK
// barrier (hidden behind softmax+PV), split+smem-write after the post-PV
// barrier when Khi/Klo/Vhi/Vlo are dead. 4 barriers per ktile (same as R7).
// Arithmetic identical to R7/R8.
// ---------------------------------------------------------------------------
#define AQ 84
#define AV 88
#define AP 68

__global__ __launch_bounds__(256, 1) void attn_mma2(
    const float* __restrict__ Q, const float* __restrict__ K,
    const float* __restrict__ V, float* __restrict__ O)
{
    extern __shared__ float sm[];
    float* Qhi0 = sm;                    // 64*AQ each
    float* Qlo0 = Qhi0 + 64 * AQ;
    float* Qhi1 = Qlo0 + 64 * AQ;
    float* Qlo1 = Qhi1 + 64 * AQ;
    float* Khi  = Qlo1 + 64 * AQ;
    float* Klo  = Khi  + 64 * AQ;
    float* Vhi  = Klo  + 64 * AQ;        // 64*AV each
    float* Vlo  = Vhi  + 64 * AV;
    float* Ph0  = Vlo  + 64 * AV;        // 64*AP each
    float* Ph1  = Ph0  + 64 * AP;
    float* cr0  = Ph1  + 64 * AP;        // 64 each
    float* cr1  = cr0  + 64;

    const int tid  = threadIdx.x;
    const int lane = tid & 31;
    const int w    = tid >> 5;
    const int lr   = lane >> 2;
    const int lc   = lane & 3;
    const int wm   = (w >> 1) * 16;
    const int wnq  = (w & 1) * 32;
    const int wnp  = (w & 1) * 40;

    const int by  = blockIdx.y;          // 0..31
    const int b   = by >> 4;
    const int kvh = (by >> 1) & 7;
    const int hp  = by & 1;
    const int h0  = kvh * G_ + hp * 2;   // heads h0, h0+1
    const int q0  = blockIdx.x * 64;
    const float rscale = 0.11180339887498949f;

    // Per-thread slice for K/V staging: 5 float4 (i = tid + j*256)
    float4 kreg[5], vreg[5];

    auto load_kv = [&](int kt) {
        #pragma unroll
        for (int j = 0; j < 5; j++) {
            int i = tid + j * 256;
            int r = i / 20, c4 = (i % 20) * 4;
            size_t base = ((size_t)(b * S_ + kt + r)) * (KV_ * D_) + kvh * D_ + c4;
            kreg[j] = *(const float4*)(K + base);
            vreg[j] = *(const float4*)(V + base);
        }
    };
    auto split_kv = [&]() {
        #pragma unroll
        for (int j = 0; j < 5; j++) {
            int i = tid + j * 256;
            int r = i / 20, c4 = (i % 20) * 4;
            float4 kv = kreg[j], vv = vreg[j];
            float4 hi, lo;
            hi.x = tf32_rna(kv.x); lo.x = tf32_rna(kv.x - hi.x);
            hi.y = tf32_rna(kv.y); lo.y = tf32_rna(kv.y - hi.y);
            hi.z = tf32_rna(kv.z); lo.z = tf32_rna(kv.z - hi.z);
            hi.w = tf32_rna(kv.w); lo.w = tf32_rna(kv.w - hi.w);
            *(float4*)(Khi + r * AQ + c4) = hi;
            *(float4*)(Klo + r * AQ + c4) = lo;
            hi.x = tf32_rna(vv.x); lo.x = tf32_rna(vv.x - hi.x);
            hi.y = tf32_rna(vv.y); lo.y = tf32_rna(vv.y - hi.y);
            hi.z = tf32_rna(vv.z); lo.z = tf32_rna(vv.z - hi.z);
            hi.w = tf32_rna(vv.w); lo.w = tf32_rna(vv.w - hi.w);
            *(float4*)(Vhi + r * AV + c4) = hi;
            *(float4*)(Vlo + r * AV + c4) = lo;
        }
    };

    // Prologue: issue K/V(0) loads, split Q while they fly, then split K/V(0)
    load_kv(0);

    #pragma unroll
    for (int hh = 0; hh < 2; hh++) {
        float* qh = hh ? Qhi1 : Qhi0;
        float* ql = hh ? Qlo1 : Qlo0;
        for (int i = tid; i < 64 * 20; i += 256) {
            int r = i / 20, c4 = (i % 20) * 4;
            float4 v = *(const float4*)(Q + ((size_t)(b * S_ + q0 + r)) * (H_ * D_)
                                          + (h0 + hh) * D_ + c4);
            v.x *= rscale; v.y *= rscale; v.z *= rscale; v.w *= rscale;
            float4 hi, lo;
            hi.x = tf32_rna(v.x); lo.x = tf32_rna(v.x - hi.x);
            hi.y = tf32_rna(v.y); lo.y = tf32_rna(v.y - hi.y);
            hi.z = tf32_rna(v.z); lo.z = tf32_rna(v.z - hi.z);
            hi.w = tf32_rna(v.w); lo.w = tf32_rna(v.w - hi.w);
            *(float4*)(qh + r * AQ + c4) = hi;
            *(float4*)(ql + r * AQ + c4) = lo;
        }
    }
    split_kv();

    const int myrow = tid >> 2;
    const int myg   = tid & 3;
    float mm[2] = {-1e30f, -1e30f};
    float ll[2] = {0.f, 0.f};

    float co[2][5][4];
    #pragma unroll
    for (int hh = 0; hh < 2; hh++)
        #pragma unroll
        for (int nj = 0; nj < 5; nj++)
            #pragma unroll
            for (int u = 0; u < 4; u++) co[hh][nj][u] = 0.f;

    for (int k0 = 0; k0 <= q0; k0 += 64) {
        __syncthreads();   // K/V (and Q on first iter) smem writes visible

        // QK^T for both heads
        #pragma unroll
        for (int hh = 0; hh < 2; hh++) {
            const float* Qh = hh ? Qhi1 : Qhi0;
            const float* Ql = hh ? Qlo1 : Qlo0;
            float* Ps = hh ? Ph1 : Ph0;

            float cq[4][4];
            #pragma unroll
            for (int nj = 0; nj < 4; nj++)
                #pragma unroll
                for (int u = 0; u < 4; u++) cq[nj][u] = 0.f;

            #pragma unroll
            for (int ks = 0; ks < 10; ks++) {
                const int kc = ks * 8 + lc;
                unsigned ah[4], al[4];
                ah[0] = __float_as_uint(Qh[(wm + lr) * AQ + kc]);
                ah[1] = __float_as_uint(Qh[(wm + lr + 8) * AQ + kc]);
                ah[2] = __float_as_uint(Qh[(wm + lr) * AQ + kc + 4]);
                ah[3] = __float_as_uint(Qh[(wm + lr + 8) * AQ + kc + 4]);
                al[0] = __float_as_uint(Ql[(wm + lr) * AQ + kc]);
                al[1] = __float_as_uint(Ql[(wm + lr + 8) * AQ + kc]);
                al[2] = __float_as_uint(Ql[(wm + lr) * AQ + kc + 4]);
                al[3] = __float_as_uint(Ql[(wm + lr + 8) * AQ + kc + 4]);
                #pragma unroll
                for (int nj = 0; nj < 4; nj++) {
                    int cn = wnq + nj * 8 + lr;
                    unsigned bh_[2], bl_[2];
                    bh_[0] = __float_as_uint(Khi[cn * AQ + kc]);
                    bh_[1] = __float_as_uint(Khi[cn * AQ + kc + 4]);
                    bl_[0] = __float_as_uint(Klo[cn * AQ + kc]);
                    bl_[1] = __float_as_uint(Klo[cn * AQ + kc + 4]);
                    mma_tf32(cq[nj], ah, bh_);
                    mma_tf32(cq[nj], al, bh_);
                    mma_tf32(cq[nj], ah, bl_);
                }
            }

            #pragma unroll
            for (int nj = 0; nj < 4; nj++) {
                int col = wnq + nj * 8 + 2 * lc;
                int r0 = wm + lr, r1 = wm + lr + 8;
                Ps[r0 * AP + col]     = (k0 + col     <= q0 + r0) ? cq[nj][0] : -1e30f;
                Ps[r0 * AP + col + 1] = (k0 + col + 1 <= q0 + r0) ? cq[nj][1] : -1e30f;
                Ps[r1 * AP + col]     = (k0 + col     <= q0 + r1) ? cq[nj][2] : -1e30f;
                Ps[r1 * AP + col + 1] = (k0 + col + 1 <= q0 + r1) ? cq[nj][3] : -1e30f;
            }
        }
        __syncthreads();   // Ph ready

        // Issue next-tile K/V loads (registers); hidden behind softmax + PV
        const int kn = k0 + 64;
        const bool more = (kn <= q0);
        if (more) load_kv(kn);

        // Online softmax, both heads
        #pragma unroll
        for (int hh = 0; hh < 2; hh++) {
            float* Ps = hh ? Ph1 : Ph0;
            float* crh = hh ? cr1 : cr0;
            float s[16];
            #pragma unroll
            for (int j4 = 0; j4 < 4; j4++) {
                float4 v4 = *(const float4*)(Ps + myrow * AP + myg * 16 + j4 * 4);
                s[j4 * 4 + 0] = v4.x; s[j4 * 4 + 1] = v4.y;
                s[j4 * 4 + 2] = v4.z; s[j4 * 4 + 3] = v4.w;
            }
            float mx = s[0];
            #pragma unroll
            for (int j = 1; j < 16; j++) mx = fmaxf(mx, s[j]);
            mx = fmaxf(mx, __shfl_xor_sync(0xffffffffu, mx, 1));
            mx = fmaxf(mx, __shfl_xor_sync(0xffffffffu, mx, 2));
            float mnew = fmaxf(mm[hh], mx);
            float corr = __expf(mm[hh] - mnew);
            float rs = 0.f;
            #pragma unroll
            for (int j = 0; j < 16; j++) {
                float p = __expf(s[j] - mnew);
                rs += p;
                Ps[myrow * AP + myg * 16 + j] = tf32_rna(p);
            }
            rs += __shfl_xor_sync(0xffffffffu, rs, 1);
            rs += __shfl_xor_sync(0xffffffffu, rs, 2);
            mm[hh] = mnew;
            ll[hh] = ll[hh] * corr + rs;
            if (myg == 0) crh[myrow] = corr;
        }
        __syncthreads();

        // Rescale + PV, both heads
        #pragma unroll
        for (int hh = 0; hh < 2; hh++) {
            const float* Ps = hh ? Ph1 : Ph0;
            const float* crh = hh ? cr1 : cr0;
            float c0 = crh[wm + lr], c1 = crh[wm + lr + 8];
            #pragma unroll
            for (int nj = 0; nj < 5; nj++) {
                co[hh][nj][0] *= c0; co[hh][nj][1] *= c0;
                co[hh][nj][2] *= c1; co[hh][nj][3] *= c1;
            }
            #pragma unroll
            for (int ks = 0; ks < 8; ks++) {
                const int kc = ks * 8 + lc;
                unsigned a[4];
                a[0] = __float_as_uint(Ps[(wm + lr) * AP + kc]);
                a[1] = __float_as_uint(Ps[(wm + lr + 8) * AP + kc]);
                a[2] = __float_as_uint(Ps[(wm + lr) * AP + kc + 4]);
                a[3] = __float_as_uint(Ps[(wm + lr + 8) * AP + kc + 4]);
                #pragma unroll
                for (int nj = 0; nj < 5; nj++) {
                    int cn = wnp + nj * 8 + lr;
                    unsigned bh_[2], bl_[2];
                    bh_[0] = __float_as_uint(Vhi[(kc)     * AV + cn]);
                    bh_[1] = __float_as_uint(Vhi[(kc + 4) * AV + cn]);
                    bl_[0] = __float_as_uint(Vlo[(kc)     * AV + cn]);
                    bl_[1] = __float_as_uint(Vlo[(kc + 4) * AV + cn]);
                    mma_tf32(co[hh][nj], a, bh_);
                    mma_tf32(co[hh][nj], a, bl_);
                }
            }
        }
        __syncthreads();   // K/V smem buffers dead; safe to overwrite

        if (more) split_kv();   // write next-tile split K/V (visible after top sync)
    }

    // Epilogue
    if (myg == 0) { cr0[myrow] = 1.f / ll[0]; cr1[myrow] = 1.f / ll[1]; }
    __syncthreads();
    #pragma unroll
    for (int hh = 0; hh < 2; hh++) {
        const float* crh = hh ? cr1 : cr0;
        float i0 = crh[wm + lr], i1 = crh[wm + lr + 8];
        size_t ro0 = ((size_t)(b * S_ + q0 + wm + lr)) * (H_ * D_) + (h0 + hh) * D_;
        size_t ro1 = ((size_t)(b * S_ + q0 + wm + lr + 8)) * (H_ * D_) + (h0 + hh) * D_;
        #pragma unroll
        for (int nj = 0; nj < 5; nj++) {
            int col = wnp + nj * 8 + 2 * lc;
            *(float2*)(O + ro0 + col) =
                make_float2(tf32_rna(co[hh][nj][0] * i0), tf32_rna(co[hh][nj][1] * i0));
            *(float2*)(O + ro1 + col) =
                make_float2(tf32_rna(co[hh][nj][2] * i1), tf32_rna(co[hh][nj][3] * i1));
        }
    }
}

// ---------------------------------------------------------------------------
// Launch
// ---------------------------------------------------------------------------
extern "C" void kernel_launch(void* const* d_in, const int* in_sizes, int n_in,
                              void* d_out, int out_size)
{
    const float* hs   = (const float*)d_in[0];
    const float* cosf = (const float*)d_in[1];
    const float* sinf = (const float*)d_in[2];
    const float* Wq   = (const float*)d_in[3];
    const float* Wk   = (const float*)d_in[4];
    const float* Wv   = (const float*)d_in[5];
    const float* Wo   = (const float*)d_in[6];
    float* out = (float*)d_out;

    float *Qp, *Kp, *Vp, *Cp, *HSr, *Wqr, *Wkr, *Wvr, *Wor;
    cudaGetSymbolAddress((void**)&Qp,  g_Q);
    cudaGetSymbolAddress((void**)&Kp,  g_K);
    cudaGetSymbolAddress((void**)&Vp,  g_V);
    cudaGetSymbolAddress((void**)&Cp,  g_ctx);
    cudaGetSymbolAddress((void**)&HSr, g_hs_r);
    cudaGetSymbolAddress((void**)&Wqr, g_Wq_r);
    cudaGetSymbolAddress((void**)&Wkr, g_Wk_r);
    cudaGetSymbolAddress((void**)&Wvr, g_Wv_r);
    cudaGetSymbolAddress((void**)&Wor, g_Wo_r);

    // TF32 RNA pre-rounding: hs (1 launch) + all weights (1 launch)
    {
        int n4 = (int)((size_t)BS_ * HID_ / 4);
        round_tf32<<<(n4 + 255) / 256, 256>>>((const float4*)hs, (float4*)HSr, n4);
        int total4 = 2 * WQ4 + 2 * WK4;   // 4,096,000
        round_weights<<<(total4 + 255) / 256, 256>>>(
            (const float4*)Wq, (float4*)Wqr, (const float4*)Wk, (float4*)Wkr,
            (const float4*)Wv, (float4*)Wvr, (const float4*)Wo, (float4*)Wor);
    }

    // Fused QKV projection
    {
        dim3 g(30, BS_ / 128);
        gemm_qkv<<<g, 256>>>(HSr, Wqr, Qp, Wkr, Kp, Wvr, Vp);
    }

    // RoPE on Q and K
    {
        size_t tq = (size_t)BS_ * H_ * 40;
        size_t tk = (size_t)BS_ * KV_ * 40;
        rope_kernel<<<(unsigned)((tq + 255) / 256), 256>>>(Qp, cosf, sinf, H_, tq);
        rope_kernel<<<(unsigned)((tk + 255) / 256), 256>>>(Kp, cosf, sinf, KV_, tk);
    }

    // Attention: 2 heads per block, GQA K/V sharing, register-staged K/V
    {
        const int smem = (6 * 64 * AQ + 2 * 64 * AV + 2 * 64 * AP + 128)
                         * (int)sizeof(float);   // 209,408 B
        cudaFuncSetAttribute(attn_mma2,
                             cudaFuncAttributeMaxDynamicSharedMemorySize, smem);
        dim3 ga(S_ / 64, B_ * KV_ * 2);          // (32, 32)
        attn_mma2<<<ga, 256, smem>>>(Qp, Kp, Vp, Cp);
    }

    // Output projection
    {
        dim3 go(HID_ / 128, BS_ / 128);
        gemm_tf32<<<go, 256>>>(Cp, Wor, out, HID_, HID_);
    }
}

// round 10
// speedup vs baseline: 1.3839x; 1.2725x over previous
#include <cuda_runtime.h>
#include <cuda_fp16.h>
#include <math.h>

// Problem constants
#define B_   2
#define S_   2048
#define HID_ 2560
#define H_   32
#define KV_  8
#define D_   80
#define G_   4
#define BS_  (B_*S_)      // 4096 total rows

// Scratch (device globals)
__device__ float  g_Q[(size_t)BS_ * H_ * D_];
__device__ float  g_K[(size_t)BS_ * KV_ * D_];
__device__ float  g_V[(size_t)BS_ * KV_ * D_];
__device__ __half g_ctx_h[(size_t)BS_ * H_ * D_];
__device__ __half g_hs_h[(size_t)BS_ * HID_];
__device__ __half g_WqT[(size_t)HID_ * H_ * D_];   // [N=2560][K=2560]
__device__ __half g_WkT[(size_t)KV_ * D_ * HID_];  // [640][2560]
__device__ __half g_WvT[(size_t)KV_ * D_ * HID_];
__device__ __half g_WoT[(size_t)HID_ * H_ * D_];   // [2560][2560]

// ---------------------------------------------------------------------------
// Helpers
// ---------------------------------------------------------------------------
__device__ __forceinline__ unsigned smem_u32(const void* p) {
    return (unsigned)__cvta_generic_to_shared(p);
}
__device__ __forceinline__ void cp_async16(unsigned dst, const void* src) {
    asm volatile("cp.async.cg.shared.global [%0], [%1], 16;\n"
                 :: "r"(dst), "l"(src));
}
#define CP_COMMIT() asm volatile("cp.async.commit_group;\n" ::: "memory")
#define CP_WAIT0()  asm volatile("cp.async.wait_group 0;\n" ::: "memory")

__device__ __forceinline__ float tf32_rna(float v) {
    unsigned u;
    asm("cvt.rna.tf32.f32 %0, %1;" : "=r"(u) : "f"(v));
    return __uint_as_float(u);
}

__device__ __forceinline__ void mma_tf32(float* c, const unsigned* a, const unsigned* b) {
    asm volatile(
        "mma.sync.aligned.m16n8k8.row.col.f32.tf32.tf32.f32 "
        "{%0,%1,%2,%3}, {%4,%5,%6,%7}, {%8,%9}, {%0,%1,%2,%3};\n"
        : "+f"(c[0]), "+f"(c[1]), "+f"(c[2]), "+f"(c[3])
        : "r"(a[0]), "r"(a[1]), "r"(a[2]), "r"(a[3]), "r"(b[0]), "r"(b[1]));
}

__device__ __forceinline__ void mma_f16(float* c, const unsigned* a, const unsigned* b) {
    asm volatile(
        "mma.sync.aligned.m16n8k16.row.col.f32.f16.f16.f32 "
        "{%0,%1,%2,%3}, {%4,%5,%6,%7}, {%8,%9}, {%0,%1,%2,%3};\n"
        : "+f"(c[0]), "+f"(c[1]), "+f"(c[2]), "+f"(c[3])
        : "r"(a[0]), "r"(a[1]), "r"(a[2]), "r"(a[3]), "r"(b[0]), "r"(b[1]));
}

// ---------------------------------------------------------------------------
// Pre-passes: hs -> half ; weights -> transposed half [N][K]
// ---------------------------------------------------------------------------
__global__ void convert_half(const float4* __restrict__ in,
                             __half2* __restrict__ out, int n4)
{
    int i = blockIdx.x * blockDim.x + threadIdx.x;
    if (i < n4) {
        float4 v = in[i];
        out[2 * i]     = __floats2half2_rn(v.x, v.y);
        out[2 * i + 1] = __floats2half2_rn(v.z, v.w);
    }
}

// W [Kd][Nd] f32 -> WT [Nd][Kd] half.  grid(Nd/32, Kd/32), block(32,8)
__global__ void transpose_h(const float* __restrict__ W,
                            __half* __restrict__ WT, int Kd, int Nd)
{
    __shared__ float t[32][33];
    int n0 = blockIdx.x * 32, k0 = blockIdx.y * 32;
    int tx = threadIdx.x, ty = threadIdx.y;
    #pragma unroll
    for (int i = 0; i < 4; i++)
        t[ty + i * 8][tx] = W[(size_t)(k0 + ty + i * 8) * Nd + n0 + tx];
    __syncthreads();
    #pragma unroll
    for (int i = 0; i < 4; i++)
        WT[(size_t)(n0 + ty + i * 8) * Kd + k0 + tx] =
            __float2half_rn(t[tx][ty + i * 8]);
}

// ---------------------------------------------------------------------------
// FP16 tensor-core GEMM: C[M,N] = A[M,K] @ BT[N,K]^T, fp32 accumulate.
// 128x128 tile, BK=32 halves, 8 warps (2x4), double-buffered cp.async,
// 2 CTAs/SM. Smem stride 40 halves (=20 words): frag pattern (lr*20+lc)%32
// bijective -> conflict-free for all four fragment offsets.
// ---------------------------------------------------------------------------
#define HSTR 40

__device__ __forceinline__ void gemm_core_h(
    const __half* __restrict__ A, const __half* __restrict__ BT,
    float* __restrict__ C, int N, int K, int bm, int bn)
{
    __shared__ __half As[2][128 * HSTR];
    __shared__ __half Bs[2][128 * HSTR];

    const int tid  = threadIdx.x;
    const int lane = tid & 31;
    const int w    = tid >> 5;
    const int wm   = (w >> 2) * 64;
    const int wn   = (w & 3) * 32;
    const int lr   = lane >> 2;          // 0..7
    const int lc   = lane & 3;           // 0..3

    const int l_r = tid >> 2;            // 0..63 (and +64)
    const int l_c = (tid & 3) * 8;       // halves: 0,8,16,24 (16B chunks)

    float acc[4][4][4];
    #pragma unroll
    for (int mi = 0; mi < 4; mi++)
        #pragma unroll
        for (int nj = 0; nj < 4; nj++)
            #pragma unroll
            for (int u = 0; u < 4; u++) acc[mi][nj][u] = 0.f;

    const int T = K / 32;

    auto load_tile = [&](int kt, int buf) {
        const __half* ag = A + (size_t)(bm + l_r) * K + kt * 32 + l_c;
        cp_async16(smem_u32(&As[buf][l_r * HSTR + l_c]), ag);
        cp_async16(smem_u32(&As[buf][(l_r + 64) * HSTR + l_c]), ag + (size_t)64 * K);
        const __half* bg = BT + (size_t)(bn + l_r) * K + kt * 32 + l_c;
        cp_async16(smem_u32(&Bs[buf][l_r * HSTR + l_c]), bg);
        cp_async16(smem_u32(&Bs[buf][(l_r + 64) * HSTR + l_c]), bg + (size_t)64 * K);
    };

    load_tile(0, 0);
    CP_COMMIT();

    for (int kt = 0; kt < T; kt++) {
        const int buf = kt & 1;
        CP_WAIT0();
        __syncthreads();
        if (kt + 1 < T) {
            load_tile(kt + 1, buf ^ 1);
            CP_COMMIT();
        }
        const __half* as = As[buf];
        const __half* bs = Bs[buf];
        #pragma unroll
        for (int ks = 0; ks < 2; ks++) {
            const int ko = ks * 16 + 2 * lc;
            unsigned af[4][4], bf[4][2];
            #pragma unroll
            for (int mi = 0; mi < 4; mi++) {
                int r = wm + mi * 16 + lr;
                af[mi][0] = *(const unsigned*)&as[r * HSTR + ko];
                af[mi][1] = *(const unsigned*)&as[(r + 8) * HSTR + ko];
                af[mi][2] = *(const unsigned*)&as[r * HSTR + ko + 8];
                af[mi][3] = *(const unsigned*)&as[(r + 8) * HSTR + ko + 8];
            }
            #pragma unroll
            for (int nj = 0; nj < 4; nj++) {
                int cn = wn + nj * 8 + lr;
                bf[nj][0] = *(const unsigned*)&bs[cn * HSTR + ko];
                bf[nj][1] = *(const unsigned*)&bs[cn * HSTR + ko + 8];
            }
            #pragma unroll
            for (int mi = 0; mi < 4; mi++)
                #pragma unroll
                for (int nj = 0; nj < 4; nj++)
                    mma_f16(acc[mi][nj], af[mi], bf[nj]);
        }
        __syncthreads();
    }

    #pragma unroll
    for (int mi = 0; mi < 4; mi++) {
        int r0 = bm + wm + mi * 16 + lr;
        #pragma unroll
        for (int nj = 0; nj < 4; nj++) {
            int cn = bn + wn + nj * 8 + 2 * lc;
            *(float2*)&C[(size_t)r0 * N + cn] =
                make_float2(acc[mi][nj][0], acc[mi][nj][1]);
            *(float2*)&C[(size_t)(r0 + 8) * N + cn] =
                make_float2(acc[mi][nj][2], acc[mi][nj][3]);
        }
    }
}

__global__ __launch_bounds__(256, 2) void gemm_h(
    const __half* __restrict__ A, const __half* __restrict__ BT,
    float* __restrict__ C, int N, int K)
{
    gemm_core_h(A, BT, C, N, K, blockIdx.y * 128, blockIdx.x * 128);
}

__global__ __launch_bounds__(256, 2) void gemm_qkv_h(
    const __half* __restrict__ A,
    const __half* __restrict__ WqT, float* __restrict__ Qo,
    const __half* __restrict__ WkT, float* __restrict__ Ko,
    const __half* __restrict__ WvT, float* __restrict__ Vo)
{
    const int bx = blockIdx.x;
    const int bm = blockIdx.y * 128;
    if (bx < 20)       gemm_core_h(A, WqT, Qo, HID_,     HID_, bm, bx * 128);
    else if (bx < 25)  gemm_core_h(A, WkT, Ko, KV_ * D_, HID_, bm, (bx - 20) * 128);
    else               gemm_core_h(A, WvT, Vo, KV_ * D_, HID_, bm, (bx - 25) * 128);
}

// ---------------------------------------------------------------------------
// RoPE (in-place, fp32 Q/K)
// ---------------------------------------------------------------------------
__global__ void rope_kernel(float* __restrict__ X,
                            const float* __restrict__ cosf,
                            const float* __restrict__ sinf,
                            int nheads, size_t total)
{
    size_t idx = (size_t)blockIdx.x * blockDim.x + threadIdx.x;
    if (idx >= total) return;
    int d = (int)(idx % 40);
    size_t t = idx / 40;
    int head = (int)(t % nheads);
    size_t row = t / nheads;
    int s = (int)(row % S_);

    float* base = X + row * ((size_t)nheads * D_) + (size_t)head * D_;
    float x1 = base[d];
    float x2 = base[d + 40];
    float c1 = cosf[(size_t)s * D_ + d];
    float s1 = sinf[(size_t)s * D_ + d];
    float c2 = cosf[(size_t)s * D_ + d + 40];
    float s2 = sinf[(size_t)s * D_ + d + 40];
    base[d]      = x1 * c1 - x2 * s1;
    base[d + 40] = x2 * c2 + x1 * s2;
}

// ---------------------------------------------------------------------------
// Flash attention (identical to round 9) — epilogue now stores half ctx.
// ---------------------------------------------------------------------------
#define AQ 84
#define AV 88
#define AP 68

__global__ __launch_bounds__(256, 1) void attn_mma2(
    const float* __restrict__ Q, const float* __restrict__ K,
    const float* __restrict__ V, __half* __restrict__ O)
{
    extern __shared__ float sm[];
    float* Qhi0 = sm;
    float* Qlo0 = Qhi0 + 64 * AQ;
    float* Qhi1 = Qlo0 + 64 * AQ;
    float* Qlo1 = Qhi1 + 64 * AQ;
    float* Khi  = Qlo1 + 64 * AQ;
    float* Klo  = Khi  + 64 * AQ;
    float* Vhi  = Klo  + 64 * AQ;
    float* Vlo  = Vhi  + 64 * AV;
    float* Ph0  = Vlo  + 64 * AV;
    float* Ph1  = Ph0  + 64 * AP;
    float* cr0  = Ph1  + 64 * AP;
    float* cr1  = cr0  + 64;

    const int tid  = threadIdx.x;
    const int lane = tid & 31;
    const int w    = tid >> 5;
    const int lr   = lane >> 2;
    const int lc   = lane & 3;
    const int wm   = (w >> 1) * 16;
    const int wnq  = (w & 1) * 32;
    const int wnp  = (w & 1) * 40;

    const int by  = blockIdx.y;
    const int b   = by >> 4;
    const int kvh = (by >> 1) & 7;
    const int hp  = by & 1;
    const int h0  = kvh * G_ + hp * 2;
    const int q0  = blockIdx.x * 64;
    const float rscale = 0.11180339887498949f;

    float4 kreg[5], vreg[5];

    auto load_kv = [&](int kt) {
        #pragma unroll
        for (int j = 0; j < 5; j++) {
            int i = tid + j * 256;
            int r = i / 20, c4 = (i % 20) * 4;
            size_t base = ((size_t)(b * S_ + kt + r)) * (KV_ * D_) + kvh * D_ + c4;
            kreg[j] = *(const float4*)(K + base);
            vreg[j] = *(const float4*)(V + base);
        }
    };
    auto split_kv = [&]() {
        #pragma unroll
        for (int j = 0; j < 5; j++) {
            int i = tid + j * 256;
            int r = i / 20, c4 = (i % 20) * 4;
            float4 kv = kreg[j], vv = vreg[j];
            float4 hi, lo;
            hi.x = tf32_rna(kv.x); lo.x = tf32_rna(kv.x - hi.x);
            hi.y = tf32_rna(kv.y); lo.y = tf32_rna(kv.y - hi.y);
            hi.z = tf32_rna(kv.z); lo.z = tf32_rna(kv.z - hi.z);
            hi.w = tf32_rna(kv.w); lo.w = tf32_rna(kv.w - hi.w);
            *(float4*)(Khi + r * AQ + c4) = hi;
            *(float4*)(Klo + r * AQ + c4) = lo;
            hi.x = tf32_rna(vv.x); lo.x = tf32_rna(vv.x - hi.x);
            hi.y = tf32_rna(vv.y); lo.y = tf32_rna(vv.y - hi.y);
            hi.z = tf32_rna(vv.z); lo.z = tf32_rna(vv.z - hi.z);
            hi.w = tf32_rna(vv.w); lo.w = tf32_rna(vv.w - hi.w);
            *(float4*)(Vhi + r * AV + c4) = hi;
            *(float4*)(Vlo + r * AV + c4) = lo;
        }
    };

    load_kv(0);

    #pragma unroll
    for (int hh = 0; hh < 2; hh++) {
        float* qh = hh ? Qhi1 : Qhi0;
        float* ql = hh ? Qlo1 : Qlo0;
        for (int i = tid; i < 64 * 20; i += 256) {
            int r = i / 20, c4 = (i % 20) * 4;
            float4 v = *(const float4*)(Q + ((size_t)(b * S_ + q0 + r)) * (H_ * D_)
                                          + (h0 + hh) * D_ + c4);
            v.x *= rscale; v.y *= rscale; v.z *= rscale; v.w *= rscale;
            float4 hi, lo;
            hi.x = tf32_rna(v.x); lo.x = tf32_rna(v.x - hi.x);
            hi.y = tf32_rna(v.y); lo.y = tf32_rna(v.y - hi.y);
            hi.z = tf32_rna(v.z); lo.z = tf32_rna(v.z - hi.z);
            hi.w = tf32_rna(v.w); lo.w = tf32_rna(v.w - hi.w);
            *(float4*)(qh + r * AQ + c4) = hi;
            *(float4*)(ql + r * AQ + c4) = lo;
        }
    }
    split_kv();

    const int myrow = tid >> 2;
    const int myg   = tid & 3;
    float mm[2] = {-1e30f, -1e30f};
    float ll[2] = {0.f, 0.f};

    float co[2][5][4];
    #pragma unroll
    for (int hh = 0; hh < 2; hh++)
        #pragma unroll
        for (int nj = 0; nj < 5; nj++)
            #pragma unroll
            for (int u = 0; u < 4; u++) co[hh][nj][u] = 0.f;

    for (int k0 = 0; k0 <= q0; k0 += 64) {
        __syncthreads();

        #pragma unroll
        for (int hh = 0; hh < 2; hh++) {
            const float* Qh = hh ? Qhi1 : Qhi0;
            const float* Ql = hh ? Qlo1 : Qlo0;
            float* Ps = hh ? Ph1 : Ph0;

            float cq[4][4];
            #pragma unroll
            for (int nj = 0; nj < 4; nj++)
                #pragma unroll
                for (int u = 0; u < 4; u++) cq[nj][u] = 0.f;

            #pragma unroll
            for (int ks = 0; ks < 10; ks++) {
                const int kc = ks * 8 + lc;
                unsigned ah[4], al[4];
                ah[0] = __float_as_uint(Qh[(wm + lr) * AQ + kc]);
                ah[1] = __float_as_uint(Qh[(wm + lr + 8) * AQ + kc]);
                ah[2] = __float_as_uint(Qh[(wm + lr) * AQ + kc + 4]);
                ah[3] = __float_as_uint(Qh[(wm + lr + 8) * AQ + kc + 4]);
                al[0] = __float_as_uint(Ql[(wm + lr) * AQ + kc]);
                al[1] = __float_as_uint(Ql[(wm + lr + 8) * AQ + kc]);
                al[2] = __float_as_uint(Ql[(wm + lr) * AQ + kc + 4]);
                al[3] = __float_as_uint(Ql[(wm + lr + 8) * AQ + kc + 4]);
                #pragma unroll
                for (int nj = 0; nj < 4; nj++) {
                    int cn = wnq + nj * 8 + lr;
                    unsigned bh_[2], bl_[2];
                    bh_[0] = __float_as_uint(Khi[cn * AQ + kc]);
                    bh_[1] = __float_as_uint(Khi[cn * AQ + kc + 4]);
                    bl_[0] = __float_as_uint(Klo[cn * AQ + kc]);
                    bl_[1] = __float_as_uint(Klo[cn * AQ + kc + 4]);
                    mma_tf32(cq[nj], ah, bh_);
                    mma_tf32(cq[nj], al, bh_);
                    mma_tf32(cq[nj], ah, bl_);
                }
            }

            #pragma unroll
            for (int nj = 0; nj < 4; nj++) {
                int col = wnq + nj * 8 + 2 * lc;
                int r0 = wm + lr, r1 = wm + lr + 8;
                Ps[r0 * AP + col]     = (k0 + col     <= q0 + r0) ? cq[nj][0] : -1e30f;
                Ps[r0 * AP + col + 1] = (k0 + col + 1 <= q0 + r0) ? cq[nj][1] : -1e30f;
                Ps[r1 * AP + col]     = (k0 + col     <= q0 + r1) ? cq[nj][2] : -1e30f;
                Ps[r1 * AP + col + 1] = (k0 + col + 1 <= q0 + r1) ? cq[nj][3] : -1e30f;
            }
        }
        __syncthreads();

        const int kn = k0 + 64;
        const bool more = (kn <= q0);
        if (more) load_kv(kn);

        #pragma unroll
        for (int hh = 0; hh < 2; hh++) {
            float* Ps = hh ? Ph1 : Ph0;
            float* crh = hh ? cr1 : cr0;
            float s[16];
            #pragma unroll
            for (int j4 = 0; j4 < 4; j4++) {
                float4 v4 = *(const float4*)(Ps + myrow * AP + myg * 16 + j4 * 4);
                s[j4 * 4 + 0] = v4.x; s[j4 * 4 + 1] = v4.y;
                s[j4 * 4 + 2] = v4.z; s[j4 * 4 + 3] = v4.w;
            }
            float mx = s[0];
            #pragma unroll
            for (int j = 1; j < 16; j++) mx = fmaxf(mx, s[j]);
            mx = fmaxf(mx, __shfl_xor_sync(0xffffffffu, mx, 1));
            mx = fmaxf(mx, __shfl_xor_sync(0xffffffffu, mx, 2));
            float mnew = fmaxf(mm[hh], mx);
            float corr = __expf(mm[hh] - mnew);
            float rs = 0.f;
            #pragma unroll
            for (int j = 0; j < 16; j++) {
                float p = __expf(s[j] - mnew);
                rs += p;
                Ps[myrow * AP + myg * 16 + j] = tf32_rna(p);
            }
            rs += __shfl_xor_sync(0xffffffffu, rs, 1);
            rs += __shfl_xor_sync(0xffffffffu, rs, 2);
            mm[hh] = mnew;
            ll[hh] = ll[hh] * corr + rs;
            if (myg == 0) crh[myrow] = corr;
        }
        __syncthreads();

        #pragma unroll
        for (int hh = 0; hh < 2; hh++) {
            const float* Ps = hh ? Ph1 : Ph0;
            const float* crh = hh ? cr1 : cr0;
            float c0 = crh[wm + lr], c1 = crh[wm + lr + 8];
            #pragma unroll
            for (int nj = 0; nj < 5; nj++) {
                co[hh][nj][0] *= c0; co[hh][nj][1] *= c0;
                co[hh][nj][2] *= c1; co[hh][nj][3] *= c1;
            }
            #pragma unroll
            for (int ks = 0; ks < 8; ks++) {
                const int kc = ks * 8 + lc;
                unsigned a[4];
                a[0] = __float_as_uint(Ps[(wm + lr) * AP + kc]);
                a[1] = __float_as_uint(Ps[(wm + lr + 8) * AP + kc]);
                a[2] = __float_as_uint(Ps[(wm + lr) * AP + kc + 4]);
                a[3] = __float_as_uint(Ps[(wm + lr + 8) * AP + kc + 4]);
                #pragma unroll
                for (int nj = 0; nj < 5; nj++) {
                    int cn = wnp + nj * 8 + lr;
                    unsigned bh_[2], bl_[2];
                    bh_[0] = __float_as_uint(Vhi[(kc)     * AV + cn]);
                    bh_[1] = __float_as_uint(Vhi[(kc + 4) * AV + cn]);
                    bl_[0] = __float_as_uint(Vlo[(kc)     * AV + cn]);
                    bl_[1] = __float_as_uint(Vlo[(kc + 4) * AV + cn]);
                    mma_tf32(co[hh][nj], a, bh_);
                    mma_tf32(co[hh][nj], a, bl_);
                }
            }
        }
        __syncthreads();

        if (more) split_kv();
    }

    // Epilogue: write half ctx
    if (myg == 0) { cr0[myrow] = 1.f / ll[0]; cr1[myrow] = 1.f / ll[1]; }
    __syncthreads();
    #pragma unroll
    for (int hh = 0; hh < 2; hh++) {
        const float* crh = hh ? cr1 : cr0;
        float i0 = crh[wm + lr], i1 = crh[wm + lr + 8];
        size_t ro0 = ((size_t)(b * S_ + q0 + wm + lr)) * (H_ * D_) + (h0 + hh) * D_;
        size_t ro1 = ((size_t)(b * S_ + q0 + wm + lr + 8)) * (H_ * D_) + (h0 + hh) * D_;
        #pragma unroll
        for (int nj = 0; nj < 5; nj++) {
            int col = wnp + nj * 8 + 2 * lc;
            *(__half2*)(O + ro0 + col) =
                __floats2half2_rn(co[hh][nj][0] * i0, co[hh][nj][1] * i0);
            *(__half2*)(O + ro1 + col) =
                __floats2half2_rn(co[hh][nj][2] * i1, co[hh][nj][3] * i1);
        }
    }
}

// ---------------------------------------------------------------------------
// Launch
// ---------------------------------------------------------------------------
extern "C" void kernel_launch(void* const* d_in, const int* in_sizes, int n_in,
                              void* d_out, int out_size)
{
    const float* hs   = (const float*)d_in[0];
    const float* cosf = (const float*)d_in[1];
    const float* sinf = (const float*)d_in[2];
    const float* Wq   = (const float*)d_in[3];
    const float* Wk   = (const float*)d_in[4];
    const float* Wv   = (const float*)d_in[5];
    const float* Wo   = (const float*)d_in[6];
    float* out = (float*)d_out;

    float *Qp, *Kp, *Vp;
    __half *Cph, *HSh, *WqT, *WkT, *WvT, *WoT;
    cudaGetSymbolAddress((void**)&Qp,  g_Q);
    cudaGetSymbolAddress((void**)&Kp,  g_K);
    cudaGetSymbolAddress((void**)&Vp,  g_V);
    cudaGetSymbolAddress((void**)&Cph, g_ctx_h);
    cudaGetSymbolAddress((void**)&HSh, g_hs_h);
    cudaGetSymbolAddress((void**)&WqT, g_WqT);
    cudaGetSymbolAddress((void**)&WkT, g_WkT);
    cudaGetSymbolAddress((void**)&WvT, g_WvT);
    cudaGetSymbolAddress((void**)&WoT, g_WoT);

    // Pre-passes: hs -> half; weights -> transposed half [N][K]
    {
        int n4 = (int)((size_t)BS_ * HID_ / 4);
        convert_half<<<(n4 + 255) / 256, 256>>>(
            (const float4*)hs, (__half2*)HSh, n4);
        dim3 tb(32, 8);
        transpose_h<<<dim3(HID_ / 32, HID_ / 32), tb>>>(Wq, WqT, HID_, HID_);
        transpose_h<<<dim3((KV_ * D_) / 32, HID_ / 32), tb>>>(Wk, WkT, HID_, KV_ * D_);
        transpose_h<<<dim3((KV_ * D_) / 32, HID_ / 32), tb>>>(Wv, WvT, HID_, KV_ * D_);
        transpose_h<<<dim3(HID_ / 32, HID_ / 32), tb>>>(Wo, WoT, HID_, HID_);
    }

    // Fused QKV projection (fp16 tensor cores)
    {
        dim3 g(30, BS_ / 128);
        gemm_qkv_h<<<g, 256>>>(HSh, WqT, Qp, WkT, Kp, WvT, Vp);
    }

    // RoPE on Q and K (fp32)
    {
        size_t tq = (size_t)BS_ * H_ * 40;
        size_t tk = (size_t)BS_ * KV_ * 40;
        rope_kernel<<<(unsigned)((tq + 255) / 256), 256>>>(Qp, cosf, sinf, H_, tq);
        rope_kernel<<<(unsigned)((tk + 255) / 256), 256>>>(Kp, cosf, sinf, KV_, tk);
    }

    // Attention: 2 heads per block, GQA K/V sharing, register-staged K/V
    {
        const int smem = (6 * 64 * AQ + 2 * 64 * AV + 2 * 64 * AP + 128)
                         * (int)sizeof(float);   // 209,408 B
        cudaFuncSetAttribute(attn_mma2,
                             cudaFuncAttributeMaxDynamicSharedMemorySize, smem);
        dim3 ga(S_ / 64, B_ * KV_ * 2);          // (32, 32)
        attn_mma2<<<ga, 256, smem>>>(Qp, Kp, Vp, Cph);
    }

    // Output projection (fp16 tensor cores)
    {
        dim3 go(HID_ / 128, BS_ / 128);
        gemm_h<<<go, 256>>>(Cph, WoT, out, HID_, HID_);
    }
}

// round 11
// speedup vs baseline: 1.6465x; 1.1898x over previous
#include <cuda_runtime.h>
#include <cuda_fp16.h>
#include <math.h>

// Problem constants
#define B_   2
#define S_   2048
#define HID_ 2560
#define H_   32
#define KV_  8
#define D_   80
#define G_   4
#define BS_  (B_*S_)      // 4096 total rows

// Scratch (device globals)
__device__ float  g_Q[(size_t)BS_ * H_ * D_];
__device__ float  g_K[(size_t)BS_ * KV_ * D_];
__device__ float  g_V[(size_t)BS_ * KV_ * D_];
__device__ __half g_ctx_h[(size_t)BS_ * H_ * D_];
__device__ __half g_hs_h[(size_t)BS_ * HID_];
__device__ __half g_WqT[(size_t)HID_ * H_ * D_];   // [N=2560][K=2560]
__device__ __half g_WkT[(size_t)KV_ * D_ * HID_];  // [640][2560]
__device__ __half g_WvT[(size_t)KV_ * D_ * HID_];
__device__ __half g_WoT[(size_t)HID_ * H_ * D_];   // [2560][2560]

// ---------------------------------------------------------------------------
// Helpers
// ---------------------------------------------------------------------------
__device__ __forceinline__ unsigned smem_u32(const void* p) {
    return (unsigned)__cvta_generic_to_shared(p);
}
__device__ __forceinline__ void cp_async16(unsigned dst, const void* src) {
    asm volatile("cp.async.cg.shared.global [%0], [%1], 16;\n"
                 :: "r"(dst), "l"(src));
}
#define CP_COMMIT() asm volatile("cp.async.commit_group;\n" ::: "memory")
#define CP_WAIT1()  asm volatile("cp.async.wait_group 1;\n" ::: "memory")

__device__ __forceinline__ float tf32_rna(float v) {
    unsigned u;
    asm("cvt.rna.tf32.f32 %0, %1;" : "=r"(u) : "f"(v));
    return __uint_as_float(u);
}

__device__ __forceinline__ void mma_tf32(float* c, const unsigned* a, const unsigned* b) {
    asm volatile(
        "mma.sync.aligned.m16n8k8.row.col.f32.tf32.tf32.f32 "
        "{%0,%1,%2,%3}, {%4,%5,%6,%7}, {%8,%9}, {%0,%1,%2,%3};\n"
        : "+f"(c[0]), "+f"(c[1]), "+f"(c[2]), "+f"(c[3])
        : "r"(a[0]), "r"(a[1]), "r"(a[2]), "r"(a[3]), "r"(b[0]), "r"(b[1]));
}

__device__ __forceinline__ void mma_f16(float* c, const unsigned* a, const unsigned* b) {
    asm volatile(
        "mma.sync.aligned.m16n8k16.row.col.f32.f16.f16.f32 "
        "{%0,%1,%2,%3}, {%4,%5,%6,%7}, {%8,%9}, {%0,%1,%2,%3};\n"
        : "+f"(c[0]), "+f"(c[1]), "+f"(c[2]), "+f"(c[3])
        : "r"(a[0]), "r"(a[1]), "r"(a[2]), "r"(a[3]), "r"(b[0]), "r"(b[1]));
}

// ---------------------------------------------------------------------------
// Pre-passes: hs -> half ; weights -> transposed half [N][K]
// ---------------------------------------------------------------------------
__global__ void convert_half(const float4* __restrict__ in,
                             __half2* __restrict__ out, int n4)
{
    int i = blockIdx.x * blockDim.x + threadIdx.x;
    if (i < n4) {
        float4 v = in[i];
        out[2 * i]     = __floats2half2_rn(v.x, v.y);
        out[2 * i + 1] = __floats2half2_rn(v.z, v.w);
    }
}

__global__ void transpose_h(const float* __restrict__ W,
                            __half* __restrict__ WT, int Kd, int Nd)
{
    __shared__ float t[32][33];
    int n0 = blockIdx.x * 32, k0 = blockIdx.y * 32;
    int tx = threadIdx.x, ty = threadIdx.y;
    #pragma unroll
    for (int i = 0; i < 4; i++)
        t[ty + i * 8][tx] = W[(size_t)(k0 + ty + i * 8) * Nd + n0 + tx];
    __syncthreads();
    #pragma unroll
    for (int i = 0; i < 4; i++)
        WT[(size_t)(n0 + ty + i * 8) * Kd + k0 + tx] =
            __float2half_rn(t[tx][ty + i * 8]);
}

// ---------------------------------------------------------------------------
// FP16 tensor-core GEMM: 128x128 tile, BK=32 halves, 8 warps (2x4),
// THREE-stage cp.async pipeline (wait_group 1), 2 CTAs/SM, one sync/iter.
// ---------------------------------------------------------------------------
#define HSTR 40
#define GSTG (128 * HSTR * 2)                    // halves per stage (A+B)
#define GEMM_SMEM (3 * GSTG * 2)                 // bytes = 61440

__device__ __forceinline__ void gemm_core_h(
    const __half* __restrict__ A, const __half* __restrict__ BT,
    float* __restrict__ C, int N, int K, int bm, int bn)
{
    extern __shared__ __half gsm[];

    const int tid  = threadIdx.x;
    const int lane = tid & 31;
    const int w    = tid >> 5;
    const int wm   = (w >> 2) * 64;
    const int wn   = (w & 3) * 32;
    const int lr   = lane >> 2;
    const int lc   = lane & 3;

    const int l_r = tid >> 2;            // 0..63 (and +64)
    const int l_c = (tid & 3) * 8;       // halves

    float acc[4][4][4];
    #pragma unroll
    for (int mi = 0; mi < 4; mi++)
        #pragma unroll
        for (int nj = 0; nj < 4; nj++)
            #pragma unroll
            for (int u = 0; u < 4; u++) acc[mi][nj][u] = 0.f;

    const int T = K / 32;

    auto load_tile = [&](int kt, int buf) {
        __half* as = gsm + buf * GSTG;
        __half* bs = as + 128 * HSTR;
        const __half* ag = A + (size_t)(bm + l_r) * K + kt * 32 + l_c;
        cp_async16(smem_u32(&as[l_r * HSTR + l_c]), ag);
        cp_async16(smem_u32(&as[(l_r + 64) * HSTR + l_c]), ag + (size_t)64 * K);
        const __half* bg = BT + (size_t)(bn + l_r) * K + kt * 32 + l_c;
        cp_async16(smem_u32(&bs[l_r * HSTR + l_c]), bg);
        cp_async16(smem_u32(&bs[(l_r + 64) * HSTR + l_c]), bg + (size_t)64 * K);
    };

    load_tile(0, 0); CP_COMMIT();
    load_tile(1, 1); CP_COMMIT();

    for (int kt = 0; kt < T; kt++) {
        const int buf = kt % 3;
        CP_WAIT1();
        __syncthreads();       // publishes stage kt; retires stage kt-1 reads
        if (kt + 2 < T) load_tile(kt + 2, (kt + 2) % 3);
        CP_COMMIT();           // exactly one group per iteration

        const __half* as = gsm + buf * GSTG;
        const __half* bs = as + 128 * HSTR;
        #pragma unroll
        for (int ks = 0; ks < 2; ks++) {
            const int ko = ks * 16 + 2 * lc;
            unsigned af[4][4], bf[4][2];
            #pragma unroll
            for (int mi = 0; mi < 4; mi++) {
                int r = wm + mi * 16 + lr;
                af[mi][0] = *(const unsigned*)&as[r * HSTR + ko];
                af[mi][1] = *(const unsigned*)&as[(r + 8) * HSTR + ko];
                af[mi][2] = *(const unsigned*)&as[r * HSTR + ko + 8];
                af[mi][3] = *(const unsigned*)&as[(r + 8) * HSTR + ko + 8];
            }
            #pragma unroll
            for (int nj = 0; nj < 4; nj++) {
                int cn = wn + nj * 8 + lr;
                bf[nj][0] = *(const unsigned*)&bs[cn * HSTR + ko];
                bf[nj][1] = *(const unsigned*)&bs[cn * HSTR + ko + 8];
            }
            #pragma unroll
            for (int mi = 0; mi < 4; mi++)
                #pragma unroll
                for (int nj = 0; nj < 4; nj++)
                    mma_f16(acc[mi][nj], af[mi], bf[nj]);
        }
    }

    #pragma unroll
    for (int mi = 0; mi < 4; mi++) {
        int r0 = bm + wm + mi * 16 + lr;
        #pragma unroll
        for (int nj = 0; nj < 4; nj++) {
            int cn = bn + wn + nj * 8 + 2 * lc;
            *(float2*)&C[(size_t)r0 * N + cn] =
                make_float2(acc[mi][nj][0], acc[mi][nj][1]);
            *(float2*)&C[(size_t)(r0 + 8) * N + cn] =
                make_float2(acc[mi][nj][2], acc[mi][nj][3]);
        }
    }
}

__global__ __launch_bounds__(256, 2) void gemm_h(
    const __half* __restrict__ A, const __half* __restrict__ BT,
    float* __restrict__ C, int N, int K)
{
    gemm_core_h(A, BT, C, N, K, blockIdx.y * 128, blockIdx.x * 128);
}

__global__ __launch_bounds__(256, 2) void gemm_qkv_h(
    const __half* __restrict__ A,
    const __half* __restrict__ WqT, float* __restrict__ Qo,
    const __half* __restrict__ WkT, float* __restrict__ Ko,
    const __half* __restrict__ WvT, float* __restrict__ Vo)
{
    const int bx = blockIdx.x;
    const int bm = blockIdx.y * 128;
    if (bx < 20)       gemm_core_h(A, WqT, Qo, HID_,     HID_, bm, bx * 128);
    else if (bx < 25)  gemm_core_h(A, WkT, Ko, KV_ * D_, HID_, bm, (bx - 20) * 128);
    else               gemm_core_h(A, WvT, Vo, KV_ * D_, HID_, bm, (bx - 25) * 128);
}

// ---------------------------------------------------------------------------
// RoPE (in-place, fp32 Q/K)
// ---------------------------------------------------------------------------
__global__ void rope_kernel(float* __restrict__ X,
                            const float* __restrict__ cosf,
                            const float* __restrict__ sinf,
                            int nheads, size_t total)
{
    size_t idx = (size_t)blockIdx.x * blockDim.x + threadIdx.x;
    if (idx >= total) return;
    int d = (int)(idx % 40);
    size_t t = idx / 40;
    int head = (int)(t % nheads);
    size_t row = t / nheads;
    int s = (int)(row % S_);

    float* base = X + row * ((size_t)nheads * D_) + (size_t)head * D_;
    float x1 = base[d];
    float x2 = base[d + 40];
    float c1 = cosf[(size_t)s * D_ + d];
    float s1 = sinf[(size_t)s * D_ + d];
    float c2 = cosf[(size_t)s * D_ + d + 40];
    float s2 = sinf[(size_t)s * D_ + d + 40];
    base[d]      = x1 * c1 - x2 * s1;
    base[d + 40] = x2 * c2 + x1 * s2;
}

// ---------------------------------------------------------------------------
// Flash attention: QK now fp16 (hi+lo split, 3-term, m16n8k16);
// softmax fp32; PV tf32 (Phi·Vhi + Phi·Vlo) unchanged.
// 2 heads/block, register-staged K/V prefetch (round-9 structure).
// ---------------------------------------------------------------------------
#define AQH 88   // half stride for Q/K tiles
#define AV  88   // float stride for V tiles
#define AP  68   // float stride for score tiles

__device__ __forceinline__ unsigned h2u(__half a, __half b) {
    __half2 p = __halves2half2(a, b);
    return *(unsigned*)&p;
}

__global__ __launch_bounds__(256, 1) void attn_mma2(
    const float* __restrict__ Q, const float* __restrict__ K,
    const float* __restrict__ V, __half* __restrict__ O)
{
    extern __shared__ char smb[];
    __half* Qh0 = (__half*)smb;              // 64*AQH halves each
    __half* Ql0 = Qh0 + 64 * AQH;
    __half* Qh1 = Ql0 + 64 * AQH;
    __half* Ql1 = Qh1 + 64 * AQH;
    __half* Khh = Ql1 + 64 * AQH;
    __half* Khl = Khh + 64 * AQH;
    float*  Vhi = (float*)(Khl + 64 * AQH);  // offset 6*64*88*2 = 67584 B
    float*  Vlo = Vhi + 64 * AV;
    float*  Ph0 = Vlo + 64 * AV;
    float*  Ph1 = Ph0 + 64 * AP;
    float*  cr0 = Ph1 + 64 * AP;
    float*  cr1 = cr0 + 64;

    const int tid  = threadIdx.x;
    const int lane = tid & 31;
    const int w    = tid >> 5;
    const int lr   = lane >> 2;
    const int lc   = lane & 3;
    const int wm   = (w >> 1) * 16;
    const int wnq  = (w & 1) * 32;
    const int wnp  = (w & 1) * 40;

    const int by  = blockIdx.y;
    const int b   = by >> 4;
    const int kvh = (by >> 1) & 7;
    const int hp  = by & 1;
    const int h0  = kvh * G_ + hp * 2;
    const int q0  = blockIdx.x * 64;
    const float rscale = 0.11180339887498949f;

    float4 kreg[5], vreg[5];

    auto load_kv = [&](int kt) {
        #pragma unroll
        for (int j = 0; j < 5; j++) {
            int i = tid + j * 256;
            int r = i / 20, c4 = (i % 20) * 4;
            size_t base = ((size_t)(b * S_ + kt + r)) * (KV_ * D_) + kvh * D_ + c4;
            kreg[j] = *(const float4*)(K + base);
            vreg[j] = *(const float4*)(V + base);
        }
    };
    auto split_kv = [&]() {
        #pragma unroll
        for (int j = 0; j < 5; j++) {
            int i = tid + j * 256;
            int r = i / 20, c4 = (i % 20) * 4;
            float4 kv = kreg[j], vv = vreg[j];
            // K: fp16 hi/lo
            __half hx = __float2half_rn(kv.x), hy = __float2half_rn(kv.y);
            __half hz = __float2half_rn(kv.z), hw = __float2half_rn(kv.w);
            __half lx = __float2half_rn(kv.x - __half2float(hx));
            __half ly = __float2half_rn(kv.y - __half2float(hy));
            __half lz = __float2half_rn(kv.z - __half2float(hz));
            __half lw = __float2half_rn(kv.w - __half2float(hw));
            *(uint2*)(Khh + r * AQH + c4) = make_uint2(h2u(hx, hy), h2u(hz, hw));
            *(uint2*)(Khl + r * AQH + c4) = make_uint2(h2u(lx, ly), h2u(lz, lw));
            // V: tf32 hi/lo (unchanged)
            float4 hi, lo;
            hi.x = tf32_rna(vv.x); lo.x = tf32_rna(vv.x - hi.x);
            hi.y = tf32_rna(vv.y); lo.y = tf32_rna(vv.y - hi.y);
            hi.z = tf32_rna(vv.z); lo.z = tf32_rna(vv.z - hi.z);
            hi.w = tf32_rna(vv.w); lo.w = tf32_rna(vv.w - hi.w);
            *(float4*)(Vhi + r * AV + c4) = hi;
            *(float4*)(Vlo + r * AV + c4) = lo;
        }
    };

    load_kv(0);

    // Q: scale + fp16 hi/lo split for both heads
    #pragma unroll
    for (int hh = 0; hh < 2; hh++) {
        __half* qh = hh ? Qh1 : Qh0;
        __half* ql = hh ? Ql1 : Ql0;
        for (int i = tid; i < 64 * 20; i += 256) {
            int r = i / 20, c4 = (i % 20) * 4;
            float4 v = *(const float4*)(Q + ((size_t)(b * S_ + q0 + r)) * (H_ * D_)
                                          + (h0 + hh) * D_ + c4);
            v.x *= rscale; v.y *= rscale; v.z *= rscale; v.w *= rscale;
            __half hx = __float2half_rn(v.x), hy = __float2half_rn(v.y);
            __half hz = __float2half_rn(v.z), hw = __float2half_rn(v.w);
            __half lx = __float2half_rn(v.x - __half2float(hx));
            __half ly = __float2half_rn(v.y - __half2float(hy));
            __half lz = __float2half_rn(v.z - __half2float(hz));
            __half lw = __float2half_rn(v.w - __half2float(hw));
            *(uint2*)(qh + r * AQH + c4) = make_uint2(h2u(hx, hy), h2u(hz, hw));
            *(uint2*)(ql + r * AQH + c4) = make_uint2(h2u(lx, ly), h2u(lz, lw));
        }
    }
    split_kv();

    const int myrow = tid >> 2;
    const int myg   = tid & 3;
    float mm[2] = {-1e30f, -1e30f};
    float ll[2] = {0.f, 0.f};

    float co[2][5][4];
    #pragma unroll
    for (int hh = 0; hh < 2; hh++)
        #pragma unroll
        for (int nj = 0; nj < 5; nj++)
            #pragma unroll
            for (int u = 0; u < 4; u++) co[hh][nj][u] = 0.f;

    for (int k0 = 0; k0 <= q0; k0 += 64) {
        __syncthreads();

        // QK^T (fp16, 3-term) for both heads
        #pragma unroll
        for (int hh = 0; hh < 2; hh++) {
            const __half* Qh = hh ? Qh1 : Qh0;
            const __half* Ql = hh ? Ql1 : Ql0;
            float* Ps = hh ? Ph1 : Ph0;

            float cq[4][4];
            #pragma unroll
            for (int nj = 0; nj < 4; nj++)
                #pragma unroll
                for (int u = 0; u < 4; u++) cq[nj][u] = 0.f;

            #pragma unroll
            for (int ks = 0; ks < 5; ks++) {
                const int ko = ks * 16 + 2 * lc;
                unsigned ah[4], al[4];
                ah[0] = *(const unsigned*)&Qh[(wm + lr) * AQH + ko];
                ah[1] = *(const unsigned*)&Qh[(wm + lr + 8) * AQH + ko];
                ah[2] = *(const unsigned*)&Qh[(wm + lr) * AQH + ko + 8];
                ah[3] = *(const unsigned*)&Qh[(wm + lr + 8) * AQH + ko + 8];
                al[0] = *(const unsigned*)&Ql[(wm + lr) * AQH + ko];
                al[1] = *(const unsigned*)&Ql[(wm + lr + 8) * AQH + ko];
                al[2] = *(const unsigned*)&Ql[(wm + lr) * AQH + ko + 8];
                al[3] = *(const unsigned*)&Ql[(wm + lr + 8) * AQH + ko + 8];
                #pragma unroll
                for (int nj = 0; nj < 4; nj++) {
                    int cn = wnq + nj * 8 + lr;
                    unsigned bh_[2], bl_[2];
                    bh_[0] = *(const unsigned*)&Khh[cn * AQH + ko];
                    bh_[1] = *(const unsigned*)&Khh[cn * AQH + ko + 8];
                    bl_[0] = *(const unsigned*)&Khl[cn * AQH + ko];
                    bl_[1] = *(const unsigned*)&Khl[cn * AQH + ko + 8];
                    mma_f16(cq[nj], ah, bh_);
                    mma_f16(cq[nj], al, bh_);
                    mma_f16(cq[nj], ah, bl_);
                }
            }

            #pragma unroll
            for (int nj = 0; nj < 4; nj++) {
                int col = wnq + nj * 8 + 2 * lc;
                int r0 = wm + lr, r1 = wm + lr + 8;
                Ps[r0 * AP + col]     = (k0 + col     <= q0 + r0) ? cq[nj][0] : -1e30f;
                Ps[r0 * AP + col + 1] = (k0 + col + 1 <= q0 + r0) ? cq[nj][1] : -1e30f;
                Ps[r1 * AP + col]     = (k0 + col     <= q0 + r1) ? cq[nj][2] : -1e30f;
                Ps[r1 * AP + col + 1] = (k0 + col + 1 <= q0 + r1) ? cq[nj][3] : -1e30f;
            }
        }
        __syncthreads();

        const int kn = k0 + 64;
        const bool more = (kn <= q0);
        if (more) load_kv(kn);

        // Online softmax, both heads
        #pragma unroll
        for (int hh = 0; hh < 2; hh++) {
            float* Ps = hh ? Ph1 : Ph0;
            float* crh = hh ? cr1 : cr0;
            float s[16];
            #pragma unroll
            for (int j4 = 0; j4 < 4; j4++) {
                float4 v4 = *(const float4*)(Ps + myrow * AP + myg * 16 + j4 * 4);
                s[j4 * 4 + 0] = v4.x; s[j4 * 4 + 1] = v4.y;
                s[j4 * 4 + 2] = v4.z; s[j4 * 4 + 3] = v4.w;
            }
            float mx = s[0];
            #pragma unroll
            for (int j = 1; j < 16; j++) mx = fmaxf(mx, s[j]);
            mx = fmaxf(mx, __shfl_xor_sync(0xffffffffu, mx, 1));
            mx = fmaxf(mx, __shfl_xor_sync(0xffffffffu, mx, 2));
            float mnew = fmaxf(mm[hh], mx);
            float corr = __expf(mm[hh] - mnew);
            float rs = 0.f;
            #pragma unroll
            for (int j = 0; j < 16; j++) {
                float p = __expf(s[j] - mnew);
                rs += p;
                Ps[myrow * AP + myg * 16 + j] = tf32_rna(p);
            }
            rs += __shfl_xor_sync(0xffffffffu, rs, 1);
            rs += __shfl_xor_sync(0xffffffffu, rs, 2);
            mm[hh] = mnew;
            ll[hh] = ll[hh] * corr + rs;
            if (myg == 0) crh[myrow] = corr;
        }
        __syncthreads();

        // Rescale + PV (tf32, unchanged), both heads
        #pragma unroll
        for (int hh = 0; hh < 2; hh++) {
            const float* Ps = hh ? Ph1 : Ph0;
            const float* crh = hh ? cr1 : cr0;
            float c0 = crh[wm + lr], c1 = crh[wm + lr + 8];
            #pragma unroll
            for (int nj = 0; nj < 5; nj++) {
                co[hh][nj][0] *= c0; co[hh][nj][1] *= c0;
                co[hh][nj][2] *= c1; co[hh][nj][3] *= c1;
            }
            #pragma unroll
            for (int ks = 0; ks < 8; ks++) {
                const int kc = ks * 8 + lc;
                unsigned a[4];
                a[0] = __float_as_uint(Ps[(wm + lr) * AP + kc]);
                a[1] = __float_as_uint(Ps[(wm + lr + 8) * AP + kc]);
                a[2] = __float_as_uint(Ps[(wm + lr) * AP + kc + 4]);
                a[3] = __float_as_uint(Ps[(wm + lr + 8) * AP + kc + 4]);
                #pragma unroll
                for (int nj = 0; nj < 5; nj++) {
                    int cn = wnp + nj * 8 + lr;
                    unsigned bh_[2], bl_[2];
                    bh_[0] = __float_as_uint(Vhi[(kc)     * AV + cn]);
                    bh_[1] = __float_as_uint(Vhi[(kc + 4) * AV + cn]);
                    bl_[0] = __float_as_uint(Vlo[(kc)     * AV + cn]);
                    bl_[1] = __float_as_uint(Vlo[(kc + 4) * AV + cn]);
                    mma_tf32(co[hh][nj], a, bh_);
                    mma_tf32(co[hh][nj], a, bl_);
                }
            }
        }
        __syncthreads();

        if (more) split_kv();
    }

    // Epilogue: write half ctx
    if (myg == 0) { cr0[myrow] = 1.f / ll[0]; cr1[myrow] = 1.f / ll[1]; }
    __syncthreads();
    #pragma unroll
    for (int hh = 0; hh < 2; hh++) {
        const float* crh = hh ? cr1 : cr0;
        float i0 = crh[wm + lr], i1 = crh[wm + lr + 8];
        size_t ro0 = ((size_t)(b * S_ + q0 + wm + lr)) * (H_ * D_) + (h0 + hh) * D_;
        size_t ro1 = ((size_t)(b * S_ + q0 + wm + lr + 8)) * (H_ * D_) + (h0 + hh) * D_;
        #pragma unroll
        for (int nj = 0; nj < 5; nj++) {
            int col = wnp + nj * 8 + 2 * lc;
            *(__half2*)(O + ro0 + col) =
                __floats2half2_rn(co[hh][nj][0] * i0, co[hh][nj][1] * i0);
            *(__half2*)(O + ro1 + col) =
                __floats2half2_rn(co[hh][nj][2] * i1, co[hh][nj][3] * i1);
        }
    }
}

// ---------------------------------------------------------------------------
// Launch
// ---------------------------------------------------------------------------
extern "C" void kernel_launch(void* const* d_in, const int* in_sizes, int n_in,
                              void* d_out, int out_size)
{
    const float* hs   = (const float*)d_in[0];
    const float* cosf = (const float*)d_in[1];
    const float* sinf = (const float*)d_in[2];
    const float* Wq   = (const float*)d_in[3];
    const float* Wk   = (const float*)d_in[4];
    const float* Wv   = (const float*)d_in[5];
    const float* Wo   = (const float*)d_in[6];
    float* out = (float*)d_out;

    float *Qp, *Kp, *Vp;
    __half *Cph, *HSh, *WqT, *WkT, *WvT, *WoT;
    cudaGetSymbolAddress((void**)&Qp,  g_Q);
    cudaGetSymbolAddress((void**)&Kp,  g_K);
    cudaGetSymbolAddress((void**)&Vp,  g_V);
    cudaGetSymbolAddress((void**)&Cph, g_ctx_h);
    cudaGetSymbolAddress((void**)&HSh, g_hs_h);
    cudaGetSymbolAddress((void**)&WqT, g_WqT);
    cudaGetSymbolAddress((void**)&WkT, g_WkT);
    cudaGetSymbolAddress((void**)&WvT, g_WvT);
    cudaGetSymbolAddress((void**)&WoT, g_WoT);

    // Pre-passes
    {
        int n4 = (int)((size_t)BS_ * HID_ / 4);
        convert_half<<<(n4 + 255) / 256, 256>>>(
            (const float4*)hs, (__half2*)HSh, n4);
        dim3 tb(32, 8);
        transpose_h<<<dim3(HID_ / 32, HID_ / 32), tb>>>(Wq, WqT, HID_, HID_);
        transpose_h<<<dim3((KV_ * D_) / 32, HID_ / 32), tb>>>(Wk, WkT, HID_, KV_ * D_);
        transpose_h<<<dim3((KV_ * D_) / 32, HID_ / 32), tb>>>(Wv, WvT, HID_, KV_ * D_);
        transpose_h<<<dim3(HID_ / 32, HID_ / 32), tb>>>(Wo, WoT, HID_, HID_);
    }

    cudaFuncSetAttribute(gemm_qkv_h,
                         cudaFuncAttributeMaxDynamicSharedMemorySize, GEMM_SMEM);
    cudaFuncSetAttribute(gemm_h,
                         cudaFuncAttributeMaxDynamicSharedMemorySize, GEMM_SMEM);

    // Fused QKV projection (fp16, 3-stage)
    {
        dim3 g(30, BS_ / 128);
        gemm_qkv_h<<<g, 256, GEMM_SMEM>>>(HSh, WqT, Qp, WkT, Kp, WvT, Vp);
    }

    // RoPE on Q and K (fp32)
    {
        size_t tq = (size_t)BS_ * H_ * 40;
        size_t tk = (size_t)BS_ * KV_ * 40;
        rope_kernel<<<(unsigned)((tq + 255) / 256), 256>>>(Qp, cosf, sinf, H_, tq);
        rope_kernel<<<(unsigned)((tk + 255) / 256), 256>>>(Kp, cosf, sinf, KV_, tk);
    }

    // Attention
    {
        const int smem = 6 * 64 * AQH * 2                      // Q/K halves
                       + (2 * 64 * AV + 2 * 64 * AP + 128) * 4; // V, scores, cr
        cudaFuncSetAttribute(attn_mma2,
                             cudaFuncAttributeMaxDynamicSharedMemorySize, smem);
        dim3 ga(S_ / 64, B_ * KV_ * 2);          // (32, 32)
        attn_mma2<<<ga, 256, smem>>>(Qp, Kp, Vp, Cph);
    }

    // Output projection (fp16, 3-stage)
    {
        dim3 go(HID_ / 128, BS_ / 128);
        gemm_h<<<go, 256, GEMM_SMEM>>>(Cph, WoT, out, HID_, HID_);
    }
}

// round 12
// speedup vs baseline: 1.8290x; 1.1109x over previous
#include <cuda_runtime.h>
#include <cuda_fp16.h>
#include <math.h>

// Problem constants
#define B_   2
#define S_   2048
#define HID_ 2560
#define H_   32
#define KV_  8
#define D_   80
#define G_   4
#define BS_  (B_*S_)      // 4096 total rows

// Scratch (device globals)
__device__ float  g_Q[(size_t)BS_ * H_ * D_];
__device__ float  g_K[(size_t)BS_ * KV_ * D_];
__device__ float  g_V[(size_t)BS_ * KV_ * D_];
__device__ __half g_ctx_h[(size_t)BS_ * H_ * D_];
__device__ __half g_hs_h[(size_t)BS_ * HID_];
__device__ __half g_WqT[(size_t)HID_ * H_ * D_];   // [N=2560][K=2560]
__device__ __half g_WkT[(size_t)KV_ * D_ * HID_];  // [640][2560]
__device__ __half g_WvT[(size_t)KV_ * D_ * HID_];
__device__ __half g_WoT[(size_t)HID_ * H_ * D_];   // [2560][2560]

// ---------------------------------------------------------------------------
// Helpers
// ---------------------------------------------------------------------------
__device__ __forceinline__ unsigned smem_u32(const void* p) {
    return (unsigned)__cvta_generic_to_shared(p);
}
__device__ __forceinline__ void cp_async16(unsigned dst, const void* src) {
    asm volatile("cp.async.cg.shared.global [%0], [%1], 16;\n"
                 :: "r"(dst), "l"(src));
}
#define CP_COMMIT() asm volatile("cp.async.commit_group;\n" ::: "memory")
#define CP_WAIT1()  asm volatile("cp.async.wait_group 1;\n" ::: "memory")

__device__ __forceinline__ void mma_f16(float* c, const unsigned* a, const unsigned* b) {
    asm volatile(
        "mma.sync.aligned.m16n8k16.row.col.f32.f16.f16.f32 "
        "{%0,%1,%2,%3}, {%4,%5,%6,%7}, {%8,%9}, {%0,%1,%2,%3};\n"
        : "+f"(c[0]), "+f"(c[1]), "+f"(c[2]), "+f"(c[3])
        : "r"(a[0]), "r"(a[1]), "r"(a[2]), "r"(a[3]), "r"(b[0]), "r"(b[1]));
}

// ---------------------------------------------------------------------------
// Pre-passes: hs -> half ; weights -> transposed half [N][K]
// ---------------------------------------------------------------------------
__global__ void convert_half(const float4* __restrict__ in,
                             __half2* __restrict__ out, int n4)
{
    int i = blockIdx.x * blockDim.x + threadIdx.x;
    if (i < n4) {
        float4 v = in[i];
        out[2 * i]     = __floats2half2_rn(v.x, v.y);
        out[2 * i + 1] = __floats2half2_rn(v.z, v.w);
    }
}

__global__ void transpose_h(const float* __restrict__ W,
                            __half* __restrict__ WT, int Kd, int Nd)
{
    __shared__ float t[32][33];
    int n0 = blockIdx.x * 32, k0 = blockIdx.y * 32;
    int tx = threadIdx.x, ty = threadIdx.y;
    #pragma unroll
    for (int i = 0; i < 4; i++)
        t[ty + i * 8][tx] = W[(size_t)(k0 + ty + i * 8) * Nd + n0 + tx];
    __syncthreads();
    #pragma unroll
    for (int i = 0; i < 4; i++)
        WT[(size_t)(n0 + ty + i * 8) * Kd + k0 + tx] =
            __float2half_rn(t[tx][ty + i * 8]);
}

// ---------------------------------------------------------------------------
// FP16 tensor-core GEMM (round-11 proven config, untouched):
// 128x128 tile, BK=32 halves, 8 warps, 3-stage cp.async, 2 CTAs/SM.
// ---------------------------------------------------------------------------
#define HSTR 40
#define GSTG (128 * HSTR * 2)                    // halves per stage (A+B)
#define GEMM_SMEM (3 * GSTG * 2)                 // bytes = 61440

__device__ __forceinline__ void gemm_core_h(
    const __half* __restrict__ A, const __half* __restrict__ BT,
    float* __restrict__ C, int N, int K, int bm, int bn)
{
    extern __shared__ __half gsm[];

    const int tid  = threadIdx.x;
    const int lane = tid & 31;
    const int w    = tid >> 5;
    const int wm   = (w >> 2) * 64;
    const int wn   = (w & 3) * 32;
    const int lr   = lane >> 2;
    const int lc   = lane & 3;

    const int l_r = tid >> 2;
    const int l_c = (tid & 3) * 8;

    float acc[4][4][4];
    #pragma unroll
    for (int mi = 0; mi < 4; mi++)
        #pragma unroll
        for (int nj = 0; nj < 4; nj++)
            #pragma unroll
            for (int u = 0; u < 4; u++) acc[mi][nj][u] = 0.f;

    const int T = K / 32;

    auto load_tile = [&](int kt, int buf) {
        __half* as = gsm + buf * GSTG;
        __half* bs = as + 128 * HSTR;
        const __half* ag = A + (size_t)(bm + l_r) * K + kt * 32 + l_c;
        cp_async16(smem_u32(&as[l_r * HSTR + l_c]), ag);
        cp_async16(smem_u32(&as[(l_r + 64) * HSTR + l_c]), ag + (size_t)64 * K);
        const __half* bg = BT + (size_t)(bn + l_r) * K + kt * 32 + l_c;
        cp_async16(smem_u32(&bs[l_r * HSTR + l_c]), bg);
        cp_async16(smem_u32(&bs[(l_r + 64) * HSTR + l_c]), bg + (size_t)64 * K);
    };

    load_tile(0, 0); CP_COMMIT();
    load_tile(1, 1); CP_COMMIT();

    for (int kt = 0; kt < T; kt++) {
        const int buf = kt % 3;
        CP_WAIT1();
        __syncthreads();
        if (kt + 2 < T) load_tile(kt + 2, (kt + 2) % 3);
        CP_COMMIT();

        const __half* as = gsm + buf * GSTG;
        const __half* bs = as + 128 * HSTR;
        #pragma unroll
        for (int ks = 0; ks < 2; ks++) {
            const int ko = ks * 16 + 2 * lc;
            unsigned af[4][4], bf[4][2];
            #pragma unroll
            for (int mi = 0; mi < 4; mi++) {
                int r = wm + mi * 16 + lr;
                af[mi][0] = *(const unsigned*)&as[r * HSTR + ko];
                af[mi][1] = *(const unsigned*)&as[(r + 8) * HSTR + ko];
                af[mi][2] = *(const unsigned*)&as[r * HSTR + ko + 8];
                af[mi][3] = *(const unsigned*)&as[(r + 8) * HSTR + ko + 8];
            }
            #pragma unroll
            for (int nj = 0; nj < 4; nj++) {
                int cn = wn + nj * 8 + lr;
                bf[nj][0] = *(const unsigned*)&bs[cn * HSTR + ko];
                bf[nj][1] = *(const unsigned*)&bs[cn * HSTR + ko + 8];
            }
            #pragma unroll
            for (int mi = 0; mi < 4; mi++)
                #pragma unroll
                for (int nj = 0; nj < 4; nj++)
                    mma_f16(acc[mi][nj], af[mi], bf[nj]);
        }
    }

    #pragma unroll
    for (int mi = 0; mi < 4; mi++) {
        int r0 = bm + wm + mi * 16 + lr;
        #pragma unroll
        for (int nj = 0; nj < 4; nj++) {
            int cn = bn + wn + nj * 8 + 2 * lc;
            *(float2*)&C[(size_t)r0 * N + cn] =
                make_float2(acc[mi][nj][0], acc[mi][nj][1]);
            *(float2*)&C[(size_t)(r0 + 8) * N + cn] =
                make_float2(acc[mi][nj][2], acc[mi][nj][3]);
        }
    }
}

__global__ __launch_bounds__(256, 2) void gemm_h(
    const __half* __restrict__ A, const __half* __restrict__ BT,
    float* __restrict__ C, int N, int K)
{
    gemm_core_h(A, BT, C, N, K, blockIdx.y * 128, blockIdx.x * 128);
}

__global__ __launch_bounds__(256, 2) void gemm_qkv_h(
    const __half* __restrict__ A,
    const __half* __restrict__ WqT, float* __restrict__ Qo,
    const __half* __restrict__ WkT, float* __restrict__ Ko,
    const __half* __restrict__ WvT, float* __restrict__ Vo)
{
    const int bx = blockIdx.x;
    const int bm = blockIdx.y * 128;
    if (bx < 20)       gemm_core_h(A, WqT, Qo, HID_,     HID_, bm, bx * 128);
    else if (bx < 25)  gemm_core_h(A, WkT, Ko, KV_ * D_, HID_, bm, (bx - 20) * 128);
    else               gemm_core_h(A, WvT, Vo, KV_ * D_, HID_, bm, (bx - 25) * 128);
}

// ---------------------------------------------------------------------------
// RoPE (in-place, fp32 Q/K)
// ---------------------------------------------------------------------------
__global__ void rope_kernel(float* __restrict__ X,
                            const float* __restrict__ cosf,
                            const float* __restrict__ sinf,
                            int nheads, size_t total)
{
    size_t idx = (size_t)blockIdx.x * blockDim.x + threadIdx.x;
    if (idx >= total) return;
    int d = (int)(idx % 40);
    size_t t = idx / 40;
    int head = (int)(t % nheads);
    size_t row = t / nheads;
    int s = (int)(row % S_);

    float* base = X + row * ((size_t)nheads * D_) + (size_t)head * D_;
    float x1 = base[d];
    float x2 = base[d + 40];
    float c1 = cosf[(size_t)s * D_ + d];
    float s1 = sinf[(size_t)s * D_ + d];
    float c2 = cosf[(size_t)s * D_ + d + 40];
    float s2 = sinf[(size_t)s * D_ + d + 40];
    base[d]      = x1 * c1 - x2 * s1;
    base[d + 40] = x2 * c2 + x1 * s2;
}

// ---------------------------------------------------------------------------
// Flash attention: QK fp16 3-term (hi+lo, round-11); PV now fp16 SINGLE-term
// (P half, V half transposed [d][k]); softmax fp32. 2 heads/block,
// register-staged K/V prefetch. 4 barriers/ktile.
// ---------------------------------------------------------------------------
#define AQH 88   // half stride for Q/K tiles
#define VTS 72   // half stride (k-dim) for transposed V [d][k]
#define APH 72   // half stride for P tiles
#define AP  68   // float stride for raw score tiles

__device__ __forceinline__ unsigned h2u(__half a, __half b) {
    __half2 p = __halves2half2(a, b);
    return *(unsigned*)&p;
}

__global__ __launch_bounds__(256, 1) void attn_mma2(
    const float* __restrict__ Q, const float* __restrict__ K,
    const float* __restrict__ V, __half* __restrict__ O)
{
    extern __shared__ char smb[];
    __half* Qh0 = (__half*)smb;              // 64*AQH halves each
    __half* Ql0 = Qh0 + 64 * AQH;
    __half* Qh1 = Ql0 + 64 * AQH;
    __half* Ql1 = Qh1 + 64 * AQH;
    __half* Khh = Ql1 + 64 * AQH;
    __half* Khl = Khh + 64 * AQH;
    __half* Vt  = Khl + 64 * AQH;            // 80 rows (d) x VTS (k) halves
    __half* Pm0 = Vt  + 80 * VTS;            // 64*APH halves each
    __half* Pm1 = Pm0 + 64 * APH;
    float*  Sf0 = (float*)(Pm1 + 64 * APH);  // 64*AP floats each
    float*  Sf1 = Sf0 + 64 * AP;
    float*  cr0 = Sf1 + 64 * AP;             // 64 each
    float*  cr1 = cr0 + 64;

    const int tid  = threadIdx.x;
    const int lane = tid & 31;
    const int w    = tid >> 5;
    const int lr   = lane >> 2;
    const int lc   = lane & 3;
    const int wm   = (w >> 1) * 16;
    const int wnq  = (w & 1) * 32;
    const int wnp  = (w & 1) * 40;

    const int by  = blockIdx.y;
    const int b   = by >> 4;
    const int kvh = (by >> 1) & 7;
    const int hp  = by & 1;
    const int h0  = kvh * G_ + hp * 2;
    const int q0  = blockIdx.x * 64;
    const float rscale = 0.11180339887498949f;

    float4 kreg[5], vreg[5];

    auto load_kv = [&](int kt) {
        #pragma unroll
        for (int j = 0; j < 5; j++) {
            int i = tid + j * 256;
            int r = i / 20, c4 = (i % 20) * 4;
            size_t base = ((size_t)(b * S_ + kt + r)) * (KV_ * D_) + kvh * D_ + c4;
            kreg[j] = *(const float4*)(K + base);
            vreg[j] = *(const float4*)(V + base);
        }
    };
    auto split_kv = [&]() {
        #pragma unroll
        for (int j = 0; j < 5; j++) {
            int i = tid + j * 256;
            int r = i / 20, c4 = (i % 20) * 4;   // r = k index, c4 = d base
            float4 kv = kreg[j], vv = vreg[j];
            // K: fp16 hi/lo (row-major [k][d])
            __half hx = __float2half_rn(kv.x), hy = __float2half_rn(kv.y);
            __half hz = __float2half_rn(kv.z), hw = __float2half_rn(kv.w);
            __half lx = __float2half_rn(kv.x - __half2float(hx));
            __half ly = __float2half_rn(kv.y - __half2float(hy));
            __half lz = __float2half_rn(kv.z - __half2float(hz));
            __half lw = __float2half_rn(kv.w - __half2float(hw));
            *(uint2*)(Khh + r * AQH + c4) = make_uint2(h2u(hx, hy), h2u(hz, hw));
            *(uint2*)(Khl + r * AQH + c4) = make_uint2(h2u(lx, ly), h2u(lz, lw));
            // V: single fp16, TRANSPOSED [d][k]
            Vt[(c4 + 0) * VTS + r] = __float2half_rn(vv.x);
            Vt[(c4 + 1) * VTS + r] = __float2half_rn(vv.y);
            Vt[(c4 + 2) * VTS + r] = __float2half_rn(vv.z);
            Vt[(c4 + 3) * VTS + r] = __float2half_rn(vv.w);
        }
    };

    load_kv(0);

    // Q: scale + fp16 hi/lo split for both heads
    #pragma unroll
    for (int hh = 0; hh < 2; hh++) {
        __half* qh = hh ? Qh1 : Qh0;
        __half* ql = hh ? Ql1 : Ql0;
        for (int i = tid; i < 64 * 20; i += 256) {
            int r = i / 20, c4 = (i % 20) * 4;
            float4 v = *(const float4*)(Q + ((size_t)(b * S_ + q0 + r)) * (H_ * D_)
                                          + (h0 + hh) * D_ + c4);
            v.x *= rscale; v.y *= rscale; v.z *= rscale; v.w *= rscale;
            __half hx = __float2half_rn(v.x), hy = __float2half_rn(v.y);
            __half hz = __float2half_rn(v.z), hw = __float2half_rn(v.w);
            __half lx = __float2half_rn(v.x - __half2float(hx));
            __half ly = __float2half_rn(v.y - __half2float(hy));
            __half lz = __float2half_rn(v.z - __half2float(hz));
            __half lw = __float2half_rn(v.w - __half2float(hw));
            *(uint2*)(qh + r * AQH + c4) = make_uint2(h2u(hx, hy), h2u(hz, hw));
            *(uint2*)(ql + r * AQH + c4) = make_uint2(h2u(lx, ly), h2u(lz, lw));
        }
    }
    split_kv();

    const int myrow = tid >> 2;
    const int myg   = tid & 3;
    float mm[2] = {-1e30f, -1e30f};
    float ll[2] = {0.f, 0.f};

    float co[2][5][4];
    #pragma unroll
    for (int hh = 0; hh < 2; hh++)
        #pragma unroll
        for (int nj = 0; nj < 5; nj++)
            #pragma unroll
            for (int u = 0; u < 4; u++) co[hh][nj][u] = 0.f;

    for (int k0 = 0; k0 <= q0; k0 += 64) {
        __syncthreads();

        // QK^T (fp16, 3-term) for both heads
        #pragma unroll
        for (int hh = 0; hh < 2; hh++) {
            const __half* Qh = hh ? Qh1 : Qh0;
            const __half* Ql = hh ? Ql1 : Ql0;
            float* Ps = hh ? Sf1 : Sf0;

            float cq[4][4];
            #pragma unroll
            for (int nj = 0; nj < 4; nj++)
                #pragma unroll
                for (int u = 0; u < 4; u++) cq[nj][u] = 0.f;

            #pragma unroll
            for (int ks = 0; ks < 5; ks++) {
                const int ko = ks * 16 + 2 * lc;
                unsigned ah[4], al[4];
                ah[0] = *(const unsigned*)&Qh[(wm + lr) * AQH + ko];
                ah[1] = *(const unsigned*)&Qh[(wm + lr + 8) * AQH + ko];
                ah[2] = *(const unsigned*)&Qh[(wm + lr) * AQH + ko + 8];
                ah[3] = *(const unsigned*)&Qh[(wm + lr + 8) * AQH + ko + 8];
                al[0] = *(const unsigned*)&Ql[(wm + lr) * AQH + ko];
                al[1] = *(const unsigned*)&Ql[(wm + lr + 8) * AQH + ko];
                al[2] = *(const unsigned*)&Ql[(wm + lr) * AQH + ko + 8];
                al[3] = *(const unsigned*)&Ql[(wm + lr + 8) * AQH + ko + 8];
                #pragma unroll
                for (int nj = 0; nj < 4; nj++) {
                    int cn = wnq + nj * 8 + lr;
                    unsigned bh_[2], bl_[2];
                    bh_[0] = *(const unsigned*)&Khh[cn * AQH + ko];
                    bh_[1] = *(const unsigned*)&Khh[cn * AQH + ko + 8];
                    bl_[0] = *(const unsigned*)&Khl[cn * AQH + ko];
                    bl_[1] = *(const unsigned*)&Khl[cn * AQH + ko + 8];
                    mma_f16(cq[nj], ah, bh_);
                    mma_f16(cq[nj], al, bh_);
                    mma_f16(cq[nj], ah, bl_);
                }
            }

            #pragma unroll
            for (int nj = 0; nj < 4; nj++) {
                int col = wnq + nj * 8 + 2 * lc;
                int r0 = wm + lr, r1 = wm + lr + 8;
                Ps[r0 * AP + col]     = (k0 + col     <= q0 + r0) ? cq[nj][0] : -1e30f;
                Ps[r0 * AP + col + 1] = (k0 + col + 1 <= q0 + r0) ? cq[nj][1] : -1e30f;
                Ps[r1 * AP + col]     = (k0 + col     <= q0 + r1) ? cq[nj][2] : -1e30f;
                Ps[r1 * AP + col + 1] = (k0 + col + 1 <= q0 + r1) ? cq[nj][3] : -1e30f;
            }
        }
        __syncthreads();

        const int kn = k0 + 64;
        const bool more = (kn <= q0);
        if (more) load_kv(kn);

        // Online softmax (fp32 scores -> fp16 P), both heads
        #pragma unroll
        for (int hh = 0; hh < 2; hh++) {
            float* Ps = hh ? Sf1 : Sf0;
            __half* Pm = hh ? Pm1 : Pm0;
            float* crh = hh ? cr1 : cr0;
            float s[16];
            #pragma unroll
            for (int j4 = 0; j4 < 4; j4++) {
                float4 v4 = *(const float4*)(Ps + myrow * AP + myg * 16 + j4 * 4);
                s[j4 * 4 + 0] = v4.x; s[j4 * 4 + 1] = v4.y;
                s[j4 * 4 + 2] = v4.z; s[j4 * 4 + 3] = v4.w;
            }
            float mx = s[0];
            #pragma unroll
            for (int j = 1; j < 16; j++) mx = fmaxf(mx, s[j]);
            mx = fmaxf(mx, __shfl_xor_sync(0xffffffffu, mx, 1));
            mx = fmaxf(mx, __shfl_xor_sync(0xffffffffu, mx, 2));
            float mnew = fmaxf(mm[hh], mx);
            float corr = __expf(mm[hh] - mnew);
            float rs = 0.f;
            #pragma unroll
            for (int j = 0; j < 16; j += 2) {
                float p0 = __expf(s[j] - mnew);
                float p1 = __expf(s[j + 1] - mnew);
                rs += p0 + p1;
                *(__half2*)(Pm + myrow * APH + myg * 16 + j) =
                    __floats2half2_rn(p0, p1);
            }
            rs += __shfl_xor_sync(0xffffffffu, rs, 1);
            rs += __shfl_xor_sync(0xffffffffu, rs, 2);
            mm[hh] = mnew;
            ll[hh] = ll[hh] * corr + rs;
            if (myg == 0) crh[myrow] = corr;
        }
        __syncthreads();

        // Rescale + PV (fp16 single-term), both heads
        #pragma unroll
        for (int hh = 0; hh < 2; hh++) {
            const __half* Pm = hh ? Pm1 : Pm0;
            const float* crh = hh ? cr1 : cr0;
            float c0 = crh[wm + lr], c1 = crh[wm + lr + 8];
            #pragma unroll
            for (int nj = 0; nj < 5; nj++) {
                co[hh][nj][0] *= c0; co[hh][nj][1] *= c0;
                co[hh][nj][2] *= c1; co[hh][nj][3] *= c1;
            }
            #pragma unroll
            for (int ks = 0; ks < 4; ks++) {
                const int ko = ks * 16 + 2 * lc;
                unsigned a[4];
                a[0] = *(const unsigned*)&Pm[(wm + lr) * APH + ko];
                a[1] = *(const unsigned*)&Pm[(wm + lr + 8) * APH + ko];
                a[2] = *(const unsigned*)&Pm[(wm + lr) * APH + ko + 8];
                a[3] = *(const unsigned*)&Pm[(wm + lr + 8) * APH + ko + 8];
                #pragma unroll
                for (int nj = 0; nj < 5; nj++) {
                    int cn = wnp + nj * 8 + lr;
                    unsigned bb[2];
                    bb[0] = *(const unsigned*)&Vt[cn * VTS + ko];
                    bb[1] = *(const unsigned*)&Vt[cn * VTS + ko + 8];
                    mma_f16(co[hh][nj], a, bb);
                }
            }
        }
        __syncthreads();

        if (more) split_kv();
    }

    // Epilogue: write half ctx
    if (myg == 0) { cr0[myrow] = 1.f / ll[0]; cr1[myrow] = 1.f / ll[1]; }
    __syncthreads();
    #pragma unroll
    for (int hh = 0; hh < 2; hh++) {
        const float* crh = hh ? cr1 : cr0;
        float i0 = crh[wm + lr], i1 = crh[wm + lr + 8];
        size_t ro0 = ((size_t)(b * S_ + q0 + wm + lr)) * (H_ * D_) + (h0 + hh) * D_;
        size_t ro1 = ((size_t)(b * S_ + q0 + wm + lr + 8)) * (H_ * D_) + (h0 + hh) * D_;
        #pragma unroll
        for (int nj = 0; nj < 5; nj++) {
            int col = wnp + nj * 8 + 2 * lc;
            *(__half2*)(O + ro0 + col) =
                __floats2half2_rn(co[hh][nj][0] * i0, co[hh][nj][1] * i0);
            *(__half2*)(O + ro1 + col) =
                __floats2half2_rn(co[hh][nj][2] * i1, co[hh][nj][3] * i1);
        }
    }
}

// ---------------------------------------------------------------------------
// Launch
// ---------------------------------------------------------------------------
extern "C" void kernel_launch(void* const* d_in, const int* in_sizes, int n_in,
                              void* d_out, int out_size)
{
    const float* hs   = (const float*)d_in[0];
    const float* cosf = (const float*)d_in[1];
    const float* sinf = (const float*)d_in[2];
    const float* Wq   = (const float*)d_in[3];
    const float* Wk   = (const float*)d_in[4];
    const float* Wv   = (const float*)d_in[5];
    const float* Wo   = (const float*)d_in[6];
    float* out = (float*)d_out;

    float *Qp, *Kp, *Vp;
    __half *Cph, *HSh, *WqT, *WkT, *WvT, *WoT;
    cudaGetSymbolAddress((void**)&Qp,  g_Q);
    cudaGetSymbolAddress((void**)&Kp,  g_K);
    cudaGetSymbolAddress((void**)&Vp,  g_V);
    cudaGetSymbolAddress((void**)&Cph, g_ctx_h);
    cudaGetSymbolAddress((void**)&HSh, g_hs_h);
    cudaGetSymbolAddress((void**)&WqT, g_WqT);
    cudaGetSymbolAddress((void**)&WkT, g_WkT);
    cudaGetSymbolAddress((void**)&WvT, g_WvT);
    cudaGetSymbolAddress((void**)&WoT, g_WoT);

    // Pre-passes
    {
        int n4 = (int)((size_t)BS_ * HID_ / 4);
        convert_half<<<(n4 + 255) / 256, 256>>>(
            (const float4*)hs, (__half2*)HSh, n4);
        dim3 tb(32, 8);
        transpose_h<<<dim3(HID_ / 32, HID_ / 32), tb>>>(Wq, WqT, HID_, HID_);
        transpose_h<<<dim3((KV_ * D_) / 32, HID_ / 32), tb>>>(Wk, WkT, HID_, KV_ * D_);
        transpose_h<<<dim3((KV_ * D_) / 32, HID_ / 32), tb>>>(Wv, WvT, HID_, KV_ * D_);
        transpose_h<<<dim3(HID_ / 32, HID_ / 32), tb>>>(Wo, WoT, HID_, HID_);
    }

    cudaFuncSetAttribute(gemm_qkv_h,
                         cudaFuncAttributeMaxDynamicSharedMemorySize, GEMM_SMEM);
    cudaFuncSetAttribute(gemm_h,
                         cudaFuncAttributeMaxDynamicSharedMemorySize, GEMM_SMEM);

    // Fused QKV projection (fp16, 3-stage)
    {
        dim3 g(30, BS_ / 128);
        gemm_qkv_h<<<g, 256, GEMM_SMEM>>>(HSh, WqT, Qp, WkT, Kp, WvT, Vp);
    }

    // RoPE on Q and K (fp32)
    {
        size_t tq = (size_t)BS_ * H_ * 40;
        size_t tk = (size_t)BS_ * KV_ * 40;
        rope_kernel<<<(unsigned)((tq + 255) / 256), 256>>>(Qp, cosf, sinf, H_, tq);
        rope_kernel<<<(unsigned)((tk + 255) / 256), 256>>>(Kp, cosf, sinf, KV_, tk);
    }

    // Attention
    {
        const int smem =
            (6 * 64 * AQH + 80 * VTS + 2 * 64 * APH) * 2   // halves
          + (2 * 64 * AP + 128) * 4;                        // floats
        cudaFuncSetAttribute(attn_mma2,
                             cudaFuncAttributeMaxDynamicSharedMemorySize, smem);
        dim3 ga(S_ / 64, B_ * KV_ * 2);          // (32, 32)
        attn_mma2<<<ga, 256, smem>>>(Qp, Kp, Vp, Cph);
    }

    // Output projection (fp16, 3-stage)
    {
        dim3 go(HID_ / 128, BS_ / 128);
        gemm_h<<<go, 256, GEMM_SMEM>>>(Cph, WoT, out, HID_, HID_);
    }
}

// round 13
// speedup vs baseline: 2.0157x; 1.1021x over previous
#include <cuda_runtime.h>
#include <cuda_fp16.h>
#include <math.h>

// Problem constants
#define B_   2
#define S_   2048
#define HID_ 2560
#define H_   32
#define KV_  8
#define D_   80
#define G_   4
#define BS_  (B_*S_)      // 4096 total rows

// Scratch (device globals)
__device__ float  g_Q[(size_t)BS_ * H_ * D_];
__device__ float  g_K[(size_t)BS_ * KV_ * D_];
__device__ float  g_V[(size_t)BS_ * KV_ * D_];
__device__ __half g_ctx_h[(size_t)BS_ * H_ * D_];
__device__ __half g_hs_h[(size_t)BS_ * HID_];
__device__ __half g_WqT[(size_t)HID_ * H_ * D_];   // [N=2560][K=2560]
__device__ __half g_WkT[(size_t)KV_ * D_ * HID_];  // [640][2560]
__device__ __half g_WvT[(size_t)KV_ * D_ * HID_];
__device__ __half g_WoT[(size_t)HID_ * H_ * D_];   // [2560][2560]

// ---------------------------------------------------------------------------
// Helpers
// ---------------------------------------------------------------------------
__device__ __forceinline__ unsigned smem_u32(const void* p) {
    return (unsigned)__cvta_generic_to_shared(p);
}
__device__ __forceinline__ void cp_async16(unsigned dst, const void* src) {
    asm volatile("cp.async.cg.shared.global [%0], [%1], 16;\n"
                 :: "r"(dst), "l"(src));
}
#define CP_COMMIT() asm volatile("cp.async.commit_group;\n" ::: "memory")
#define CP_WAIT1()  asm volatile("cp.async.wait_group 1;\n" ::: "memory")

__device__ __forceinline__ void mma_f16(float* c, const unsigned* a, const unsigned* b) {
    asm volatile(
        "mma.sync.aligned.m16n8k16.row.col.f32.f16.f16.f32 "
        "{%0,%1,%2,%3}, {%4,%5,%6,%7}, {%8,%9}, {%0,%1,%2,%3};\n"
        : "+f"(c[0]), "+f"(c[1]), "+f"(c[2]), "+f"(c[3])
        : "r"(a[0]), "r"(a[1]), "r"(a[2]), "r"(a[3]), "r"(b[0]), "r"(b[1]));
}

// ---------------------------------------------------------------------------
// Pre-passes: hs -> half ; weights -> transposed half [N][K]
// ---------------------------------------------------------------------------
__global__ void convert_half(const float4* __restrict__ in,
                             __half2* __restrict__ out, int n4)
{
    int i = blockIdx.x * blockDim.x + threadIdx.x;
    if (i < n4) {
        float4 v = in[i];
        out[2 * i]     = __floats2half2_rn(v.x, v.y);
        out[2 * i + 1] = __floats2half2_rn(v.z, v.w);
    }
}

__global__ void transpose_h(const float* __restrict__ W,
                            __half* __restrict__ WT, int Kd, int Nd)
{
    __shared__ float t[32][33];
    int n0 = blockIdx.x * 32, k0 = blockIdx.y * 32;
    int tx = threadIdx.x, ty = threadIdx.y;
    #pragma unroll
    for (int i = 0; i < 4; i++)
        t[ty + i * 8][tx] = W[(size_t)(k0 + ty + i * 8) * Nd + n0 + tx];
    __syncthreads();
    #pragma unroll
    for (int i = 0; i < 4; i++)
        WT[(size_t)(n0 + ty + i * 8) * Kd + k0 + tx] =
            __float2half_rn(t[tx][ty + i * 8]);
}

// ---------------------------------------------------------------------------
// FP16 tensor-core GEMM (round-11 proven config, untouched):
// 128x128 tile, BK=32 halves, 8 warps, 3-stage cp.async, 2 CTAs/SM.
// ---------------------------------------------------------------------------
#define HSTR 40
#define GSTG (128 * HSTR * 2)                    // halves per stage (A+B)
#define GEMM_SMEM (3 * GSTG * 2)                 // bytes = 61440

__device__ __forceinline__ void gemm_core_h(
    const __half* __restrict__ A, const __half* __restrict__ BT,
    float* __restrict__ C, int N, int K, int bm, int bn)
{
    extern __shared__ __half gsm[];

    const int tid  = threadIdx.x;
    const int lane = tid & 31;
    const int w    = tid >> 5;
    const int wm   = (w >> 2) * 64;
    const int wn   = (w & 3) * 32;
    const int lr   = lane >> 2;
    const int lc   = lane & 3;

    const int l_r = tid >> 2;
    const int l_c = (tid & 3) * 8;

    float acc[4][4][4];
    #pragma unroll
    for (int mi = 0; mi < 4; mi++)
        #pragma unroll
        for (int nj = 0; nj < 4; nj++)
            #pragma unroll
            for (int u = 0; u < 4; u++) acc[mi][nj][u] = 0.f;

    const int T = K / 32;

    auto load_tile = [&](int kt, int buf) {
        __half* as = gsm + buf * GSTG;
        __half* bs = as + 128 * HSTR;
        const __half* ag = A + (size_t)(bm + l_r) * K + kt * 32 + l_c;
        cp_async16(smem_u32(&as[l_r * HSTR + l_c]), ag);
        cp_async16(smem_u32(&as[(l_r + 64) * HSTR + l_c]), ag + (size_t)64 * K);
        const __half* bg = BT + (size_t)(bn + l_r) * K + kt * 32 + l_c;
        cp_async16(smem_u32(&bs[l_r * HSTR + l_c]), bg);
        cp_async16(smem_u32(&bs[(l_r + 64) * HSTR + l_c]), bg + (size_t)64 * K);
    };

    load_tile(0, 0); CP_COMMIT();
    load_tile(1, 1); CP_COMMIT();

    for (int kt = 0; kt < T; kt++) {
        const int buf = kt % 3;
        CP_WAIT1();
        __syncthreads();
        if (kt + 2 < T) load_tile(kt + 2, (kt + 2) % 3);
        CP_COMMIT();

        const __half* as = gsm + buf * GSTG;
        const __half* bs = as + 128 * HSTR;
        #pragma unroll
        for (int ks = 0; ks < 2; ks++) {
            const int ko = ks * 16 + 2 * lc;
            unsigned af[4][4], bf[4][2];
            #pragma unroll
            for (int mi = 0; mi < 4; mi++) {
                int r = wm + mi * 16 + lr;
                af[mi][0] = *(const unsigned*)&as[r * HSTR + ko];
                af[mi][1] = *(const unsigned*)&as[(r + 8) * HSTR + ko];
                af[mi][2] = *(const unsigned*)&as[r * HSTR + ko + 8];
                af[mi][3] = *(const unsigned*)&as[(r + 8) * HSTR + ko + 8];
            }
            #pragma unroll
            for (int nj = 0; nj < 4; nj++) {
                int cn = wn + nj * 8 + lr;
                bf[nj][0] = *(const unsigned*)&bs[cn * HSTR + ko];
                bf[nj][1] = *(const unsigned*)&bs[cn * HSTR + ko + 8];
            }
            #pragma unroll
            for (int mi = 0; mi < 4; mi++)
                #pragma unroll
                for (int nj = 0; nj < 4; nj++)
                    mma_f16(acc[mi][nj], af[mi], bf[nj]);
        }
    }

    #pragma unroll
    for (int mi = 0; mi < 4; mi++) {
        int r0 = bm + wm + mi * 16 + lr;
        #pragma unroll
        for (int nj = 0; nj < 4; nj++) {
            int cn = bn + wn + nj * 8 + 2 * lc;
            *(float2*)&C[(size_t)r0 * N + cn] =
                make_float2(acc[mi][nj][0], acc[mi][nj][1]);
            *(float2*)&C[(size_t)(r0 + 8) * N + cn] =
                make_float2(acc[mi][nj][2], acc[mi][nj][3]);
        }
    }
}

__global__ __launch_bounds__(256, 2) void gemm_h(
    const __half* __restrict__ A, const __half* __restrict__ BT,
    float* __restrict__ C, int N, int K)
{
    gemm_core_h(A, BT, C, N, K, blockIdx.y * 128, blockIdx.x * 128);
}

__global__ __launch_bounds__(256, 2) void gemm_qkv_h(
    const __half* __restrict__ A,
    const __half* __restrict__ WqT, float* __restrict__ Qo,
    const __half* __restrict__ WkT, float* __restrict__ Ko,
    const __half* __restrict__ WvT, float* __restrict__ Vo)
{
    const int bx = blockIdx.x;
    const int bm = blockIdx.y * 128;
    if (bx < 20)       gemm_core_h(A, WqT, Qo, HID_,     HID_, bm, bx * 128);
    else if (bx < 25)  gemm_core_h(A, WkT, Ko, KV_ * D_, HID_, bm, (bx - 20) * 128);
    else               gemm_core_h(A, WvT, Vo, KV_ * D_, HID_, bm, (bx - 25) * 128);
}

// ---------------------------------------------------------------------------
// RoPE (in-place, fp32 Q/K)
// ---------------------------------------------------------------------------
__global__ void rope_kernel(float* __restrict__ X,
                            const float* __restrict__ cosf,
                            const float* __restrict__ sinf,
                            int nheads, size_t total)
{
    size_t idx = (size_t)blockIdx.x * blockDim.x + threadIdx.x;
    if (idx >= total) return;
    int d = (int)(idx % 40);
    size_t t = idx / 40;
    int head = (int)(t % nheads);
    size_t row = t / nheads;
    int s = (int)(row % S_);

    float* base = X + row * ((size_t)nheads * D_) + (size_t)head * D_;
    float x1 = base[d];
    float x2 = base[d + 40];
    float c1 = cosf[(size_t)s * D_ + d];
    float s1 = sinf[(size_t)s * D_ + d];
    float c2 = cosf[(size_t)s * D_ + d + 40];
    float s2 = sinf[(size_t)s * D_ + d + 40];
    base[d]      = x1 * c1 - x2 * s1;
    base[d + 40] = x2 * c2 + x1 * s2;
}

// ---------------------------------------------------------------------------
// Flash attention: QK fp16 SINGLE-term; PV fp16 single-term; softmax fp32.
// 2 heads/block, register-staged K/V prefetch. 4 barriers/ktile.
// ---------------------------------------------------------------------------
#define AQH 88   // half stride for Q/K tiles
#define VTS 72   // half stride (k-dim) for transposed V [d][k]
#define APH 72   // half stride for P tiles
#define AP  68   // float stride for raw score tiles

__device__ __forceinline__ unsigned h2u(__half a, __half b) {
    __half2 p = __halves2half2(a, b);
    return *(unsigned*)&p;
}

__global__ __launch_bounds__(256, 1) void attn_mma2(
    const float* __restrict__ Q, const float* __restrict__ K,
    const float* __restrict__ V, __half* __restrict__ O)
{
    extern __shared__ char smb[];
    __half* Qh0 = (__half*)smb;              // 64*AQH halves each
    __half* Qh1 = Qh0 + 64 * AQH;
    __half* Khh = Qh1 + 64 * AQH;
    __half* Vt  = Khh + 64 * AQH;            // 80 rows (d) x VTS (k) halves
    __half* Pm0 = Vt  + 80 * VTS;            // 64*APH halves each
    __half* Pm1 = Pm0 + 64 * APH;
    float*  Sf0 = (float*)(Pm1 + 64 * APH);  // 64*AP floats each
    float*  Sf1 = Sf0 + 64 * AP;
    float*  cr0 = Sf1 + 64 * AP;             // 64 each
    float*  cr1 = cr0 + 64;

    const int tid  = threadIdx.x;
    const int lane = tid & 31;
    const int w    = tid >> 5;
    const int lr   = lane >> 2;
    const int lc   = lane & 3;
    const int wm   = (w >> 1) * 16;
    const int wnq  = (w & 1) * 32;
    const int wnp  = (w & 1) * 40;

    const int by  = blockIdx.y;
    const int b   = by >> 4;
    const int kvh = (by >> 1) & 7;
    const int hp  = by & 1;
    const int h0  = kvh * G_ + hp * 2;
    const int q0  = blockIdx.x * 64;
    const float rscale = 0.11180339887498949f;

    float4 kreg[5], vreg[5];

    auto load_kv = [&](int kt) {
        #pragma unroll
        for (int j = 0; j < 5; j++) {
            int i = tid + j * 256;
            int r = i / 20, c4 = (i % 20) * 4;
            size_t base = ((size_t)(b * S_ + kt + r)) * (KV_ * D_) + kvh * D_ + c4;
            kreg[j] = *(const float4*)(K + base);
            vreg[j] = *(const float4*)(V + base);
        }
    };
    auto split_kv = [&]() {
        #pragma unroll
        for (int j = 0; j < 5; j++) {
            int i = tid + j * 256;
            int r = i / 20, c4 = (i % 20) * 4;   // r = k index, c4 = d base
            float4 kv = kreg[j], vv = vreg[j];
            // K: single fp16 (row-major [k][d])
            *(uint2*)(Khh + r * AQH + c4) = make_uint2(
                h2u(__float2half_rn(kv.x), __float2half_rn(kv.y)),
                h2u(__float2half_rn(kv.z), __float2half_rn(kv.w)));
            // V: single fp16, TRANSPOSED [d][k]
            Vt[(c4 + 0) * VTS + r] = __float2half_rn(vv.x);
            Vt[(c4 + 1) * VTS + r] = __float2half_rn(vv.y);
            Vt[(c4 + 2) * VTS + r] = __float2half_rn(vv.z);
            Vt[(c4 + 3) * VTS + r] = __float2half_rn(vv.w);
        }
    };

    load_kv(0);

    // Q: scale + single fp16 for both heads
    #pragma unroll
    for (int hh = 0; hh < 2; hh++) {
        __half* qh = hh ? Qh1 : Qh0;
        for (int i = tid; i < 64 * 20; i += 256) {
            int r = i / 20, c4 = (i % 20) * 4;
            float4 v = *(const float4*)(Q + ((size_t)(b * S_ + q0 + r)) * (H_ * D_)
                                          + (h0 + hh) * D_ + c4);
            *(uint2*)(qh + r * AQH + c4) = make_uint2(
                h2u(__float2half_rn(v.x * rscale), __float2half_rn(v.y * rscale)),
                h2u(__float2half_rn(v.z * rscale), __float2half_rn(v.w * rscale)));
        }
    }
    split_kv();

    const int myrow = tid >> 2;
    const int myg   = tid & 3;
    float mm[2] = {-1e30f, -1e30f};
    float ll[2] = {0.f, 0.f};

    float co[2][5][4];
    #pragma unroll
    for (int hh = 0; hh < 2; hh++)
        #pragma unroll
        for (int nj = 0; nj < 5; nj++)
            #pragma unroll
            for (int u = 0; u < 4; u++) co[hh][nj][u] = 0.f;

    for (int k0 = 0; k0 <= q0; k0 += 64) {
        __syncthreads();

        // QK^T (fp16, single-term) for both heads
        #pragma unroll
        for (int hh = 0; hh < 2; hh++) {
            const __half* Qh = hh ? Qh1 : Qh0;
            float* Ps = hh ? Sf1 : Sf0;

            float cq[4][4];
            #pragma unroll
            for (int nj = 0; nj < 4; nj++)
                #pragma unroll
                for (int u = 0; u < 4; u++) cq[nj][u] = 0.f;

            #pragma unroll
            for (int ks = 0; ks < 5; ks++) {
                const int ko = ks * 16 + 2 * lc;
                unsigned ah[4];
                ah[0] = *(const unsigned*)&Qh[(wm + lr) * AQH + ko];
                ah[1] = *(const unsigned*)&Qh[(wm + lr + 8) * AQH + ko];
                ah[2] = *(const unsigned*)&Qh[(wm + lr) * AQH + ko + 8];
                ah[3] = *(const unsigned*)&Qh[(wm + lr + 8) * AQH + ko + 8];
                #pragma unroll
                for (int nj = 0; nj < 4; nj++) {
                    int cn = wnq + nj * 8 + lr;
                    unsigned bh_[2];
                    bh_[0] = *(const unsigned*)&Khh[cn * AQH + ko];
                    bh_[1] = *(const unsigned*)&Khh[cn * AQH + ko + 8];
                    mma_f16(cq[nj], ah, bh_);
                }
            }

            #pragma unroll
            for (int nj = 0; nj < 4; nj++) {
                int col = wnq + nj * 8 + 2 * lc;
                int r0 = wm + lr, r1 = wm + lr + 8;
                Ps[r0 * AP + col]     = (k0 + col     <= q0 + r0) ? cq[nj][0] : -1e30f;
                Ps[r0 * AP + col + 1] = (k0 + col + 1 <= q0 + r0) ? cq[nj][1] : -1e30f;
                Ps[r1 * AP + col]     = (k0 + col     <= q0 + r1) ? cq[nj][2] : -1e30f;
                Ps[r1 * AP + col + 1] = (k0 + col + 1 <= q0 + r1) ? cq[nj][3] : -1e30f;
            }
        }
        __syncthreads();

        const int kn = k0 + 64;
        const bool more = (kn <= q0);
        if (more) load_kv(kn);

        // Online softmax (fp32 scores -> fp16 P), both heads
        #pragma unroll
        for (int hh = 0; hh < 2; hh++) {
            float* Ps = hh ? Sf1 : Sf0;
            __half* Pm = hh ? Pm1 : Pm0;
            float* crh = hh ? cr1 : cr0;
            float s[16];
            #pragma unroll
            for (int j4 = 0; j4 < 4; j4++) {
                float4 v4 = *(const float4*)(Ps + myrow * AP + myg * 16 + j4 * 4);
                s[j4 * 4 + 0] = v4.x; s[j4 * 4 + 1] = v4.y;
                s[j4 * 4 + 2] = v4.z; s[j4 * 4 + 3] = v4.w;
            }
            float mx = s[0];
            #pragma unroll
            for (int j = 1; j < 16; j++) mx = fmaxf(mx, s[j]);
            mx = fmaxf(mx, __shfl_xor_sync(0xffffffffu, mx, 1));
            mx = fmaxf(mx, __shfl_xor_sync(0xffffffffu, mx, 2));
            float mnew = fmaxf(mm[hh], mx);
            float corr = __expf(mm[hh] - mnew);
            float rs = 0.f;
            #pragma unroll
            for (int j = 0; j < 16; j += 2) {
                float p0 = __expf(s[j] - mnew);
                float p1 = __expf(s[j + 1] - mnew);
                rs += p0 + p1;
                *(__half2*)(Pm + myrow * APH + myg * 16 + j) =
                    __floats2half2_rn(p0, p1);
            }
            rs += __shfl_xor_sync(0xffffffffu, rs, 1);
            rs += __shfl_xor_sync(0xffffffffu, rs, 2);
            mm[hh] = mnew;
            ll[hh] = ll[hh] * corr + rs;
            if (myg == 0) crh[myrow] = corr;
        }
        __syncthreads();

        // Rescale + PV (fp16 single-term), both heads
        #pragma unroll
        for (int hh = 0; hh < 2; hh++) {
            const __half* Pm = hh ? Pm1 : Pm0;
            const float* crh = hh ? cr1 : cr0;
            float c0 = crh[wm + lr], c1 = crh[wm + lr + 8];
            #pragma unroll
            for (int nj = 0; nj < 5; nj++) {
                co[hh][nj][0] *= c0; co[hh][nj][1] *= c0;
                co[hh][nj][2] *= c1; co[hh][nj][3] *= c1;
            }
            #pragma unroll
            for (int ks = 0; ks < 4; ks++) {
                const int ko = ks * 16 + 2 * lc;
                unsigned a[4];
                a[0] = *(const unsigned*)&Pm[(wm + lr) * APH + ko];
                a[1] = *(const unsigned*)&Pm[(wm + lr + 8) * APH + ko];
                a[2] = *(const unsigned*)&Pm[(wm + lr) * APH + ko + 8];
                a[3] = *(const unsigned*)&Pm[(wm + lr + 8) * APH + ko + 8];
                #pragma unroll
                for (int nj = 0; nj < 5; nj++) {
                    int cn = wnp + nj * 8 + lr;
                    unsigned bb[2];
                    bb[0] = *(const unsigned*)&Vt[cn * VTS + ko];
                    bb[1] = *(const unsigned*)&Vt[cn * VTS + ko + 8];
                    mma_f16(co[hh][nj], a, bb);
                }
            }
        }
        __syncthreads();

        if (more) split_kv();
    }

    // Epilogue: write half ctx
    if (myg == 0) { cr0[myrow] = 1.f / ll[0]; cr1[myrow] = 1.f / ll[1]; }
    __syncthreads();
    #pragma unroll
    for (int hh = 0; hh < 2; hh++) {
        const float* crh = hh ? cr1 : cr0;
        float i0 = crh[wm + lr], i1 = crh[wm + lr + 8];
        size_t ro0 = ((size_t)(b * S_ + q0 + wm + lr)) * (H_ * D_) + (h0 + hh) * D_;
        size_t ro1 = ((size_t)(b * S_ + q0 + wm + lr + 8)) * (H_ * D_) + (h0 + hh) * D_;
        #pragma unroll
        for (int nj = 0; nj < 5; nj++) {
            int col = wnp + nj * 8 + 2 * lc;
            *(__half2*)(O + ro0 + col) =
                __floats2half2_rn(co[hh][nj][0] * i0, co[hh][nj][1] * i0);
            *(__half2*)(O + ro1 + col) =
                __floats2half2_rn(co[hh][nj][2] * i1, co[hh][nj][3] * i1);
        }
    }
}

// ---------------------------------------------------------------------------
// Launch
// ---------------------------------------------------------------------------
extern "C" void kernel_launch(void* const* d_in, const int* in_sizes, int n_in,
                              void* d_out, int out_size)
{
    const float* hs   = (const float*)d_in[0];
    const float* cosf = (const float*)d_in[1];
    const float* sinf = (const float*)d_in[2];
    const float* Wq   = (const float*)d_in[3];
    const float* Wk   = (const float*)d_in[4];
    const float* Wv   = (const float*)d_in[5];
    const float* Wo   = (const float*)d_in[6];
    float* out = (float*)d_out;

    float *Qp, *Kp, *Vp;
    __half *Cph, *HSh, *WqT, *WkT, *WvT, *WoT;
    cudaGetSymbolAddress((void**)&Qp,  g_Q);
    cudaGetSymbolAddress((void**)&Kp,  g_K);
    cudaGetSymbolAddress((void**)&Vp,  g_V);
    cudaGetSymbolAddress((void**)&Cph, g_ctx_h);
    cudaGetSymbolAddress((void**)&HSh, g_hs_h);
    cudaGetSymbolAddress((void**)&WqT, g_WqT);
    cudaGetSymbolAddress((void**)&WkT, g_WkT);
    cudaGetSymbolAddress((void**)&WvT, g_WvT);
    cudaGetSymbolAddress((void**)&WoT, g_WoT);

    // Pre-passes
    {
        int n4 = (int)((size_t)BS_ * HID_ / 4);
        convert_half<<<(n4 + 255) / 256, 256>>>(
            (const float4*)hs, (__half2*)HSh, n4);
        dim3 tb(32, 8);
        transpose_h<<<dim3(HID_ / 32, HID_ / 32), tb>>>(Wq, WqT, HID_, HID_);
        transpose_h<<<dim3((KV_ * D_) / 32, HID_ / 32), tb>>>(Wk, WkT, HID_, KV_ * D_);
        transpose_h<<<dim3((KV_ * D_) / 32, HID_ / 32), tb>>>(Wv, WvT, HID_, KV_ * D_);
        transpose_h<<<dim3(HID_ / 32, HID_ / 32), tb>>>(Wo, WoT, HID_, HID_);
    }

    cudaFuncSetAttribute(gemm_qkv_h,
                         cudaFuncAttributeMaxDynamicSharedMemorySize, GEMM_SMEM);
    cudaFuncSetAttribute(gemm_h,
                         cudaFuncAttributeMaxDynamicSharedMemorySize, GEMM_SMEM);

    // Fused QKV projection (fp16, 3-stage)
    {
        dim3 g(30, BS_ / 128);
        gemm_qkv_h<<<g, 256, GEMM_SMEM>>>(HSh, WqT, Qp, WkT, Kp, WvT, Vp);
    }

    // RoPE on Q and K (fp32)
    {
        size_t tq = (size_t)BS_ * H_ * 40;
        size_t tk = (size_t)BS_ * KV_ * 40;
        rope_kernel<<<(unsigned)((tq + 255) / 256), 256>>>(Qp, cosf, sinf, H_, tq);
        rope_kernel<<<(unsigned)((tk + 255) / 256), 256>>>(Kp, cosf, sinf, KV_, tk);
    }

    // Attention
    {
        const int smem =
            (3 * 64 * AQH + 80 * VTS + 2 * 64 * APH) * 2   // halves
          + (2 * 64 * AP + 128) * 4;                        // floats
        cudaFuncSetAttribute(attn_mma2,
                             cudaFuncAttributeMaxDynamicSharedMemorySize, smem);
        dim3 ga(S_ / 64, B_ * KV_ * 2);          // (32, 32)
        attn_mma2<<<ga, 256, smem>>>(Qp, Kp, Vp, Cph);
    }

    // Output projection (fp16, 3-stage)
    {
        dim3 go(HID_ / 128, BS_ / 128);
        gemm_h<<<go, 256, GEMM_SMEM>>>(Cph, WoT, out, HID_, HID_);
    }
}

// round 14
// speedup vs baseline: 2.0621x; 1.0230x over previous
#include <cuda_runtime.h>
#include <cuda_fp16.h>
#include <math.h>

// Problem constants
#define B_   2
#define S_   2048
#define HID_ 2560
#define H_   32
#define KV_  8
#define D_   80
#define G_   4
#define BS_  (B_*S_)      // 4096 total rows

// Scratch (device globals)
__device__ float  g_Q[(size_t)BS_ * H_ * D_];
__device__ float  g_K[(size_t)BS_ * KV_ * D_];
__device__ float  g_V[(size_t)BS_ * KV_ * D_];
__device__ __half g_ctx_h[(size_t)BS_ * H_ * D_];
__device__ __half g_hs_h[(size_t)BS_ * HID_];
__device__ __half g_WqT[(size_t)HID_ * H_ * D_];   // [N=2560][K=2560]
__device__ __half g_WkT[(size_t)KV_ * D_ * HID_];  // [640][2560]
__device__ __half g_WvT[(size_t)KV_ * D_ * HID_];
__device__ __half g_WoT[(size_t)HID_ * H_ * D_];   // [2560][2560]

// ---------------------------------------------------------------------------
// Helpers
// ---------------------------------------------------------------------------
__device__ __forceinline__ unsigned smem_u32(const void* p) {
    return (unsigned)__cvta_generic_to_shared(p);
}
__device__ __forceinline__ void cp_async16(unsigned dst, const void* src) {
    asm volatile("cp.async.cg.shared.global [%0], [%1], 16;\n"
                 :: "r"(dst), "l"(src));
}
#define CP_COMMIT() asm volatile("cp.async.commit_group;\n" ::: "memory")
#define CP_WAIT1()  asm volatile("cp.async.wait_group 1;\n" ::: "memory")

__device__ __forceinline__ void mma_f16(float* c, const unsigned* a, const unsigned* b) {
    asm volatile(
        "mma.sync.aligned.m16n8k16.row.col.f32.f16.f16.f32 "
        "{%0,%1,%2,%3}, {%4,%5,%6,%7}, {%8,%9}, {%0,%1,%2,%3};\n"
        : "+f"(c[0]), "+f"(c[1]), "+f"(c[2]), "+f"(c[3])
        : "r"(a[0]), "r"(a[1]), "r"(a[2]), "r"(a[3]), "r"(b[0]), "r"(b[1]));
}

// ---------------------------------------------------------------------------
// Pre-passes: hs -> half ; weights -> transposed half [N][K]
// ---------------------------------------------------------------------------
__global__ void convert_half(const float4* __restrict__ in,
                             __half2* __restrict__ out, int n4)
{
    int i = blockIdx.x * blockDim.x + threadIdx.x;
    if (i < n4) {
        float4 v = in[i];
        out[2 * i]     = __floats2half2_rn(v.x, v.y);
        out[2 * i + 1] = __floats2half2_rn(v.z, v.w);
    }
}

__global__ void transpose_h(const float* __restrict__ W,
                            __half* __restrict__ WT, int Kd, int Nd)
{
    __shared__ float t[32][33];
    int n0 = blockIdx.x * 32, k0 = blockIdx.y * 32;
    int tx = threadIdx.x, ty = threadIdx.y;
    #pragma unroll
    for (int i = 0; i < 4; i++)
        t[ty + i * 8][tx] = W[(size_t)(k0 + ty + i * 8) * Nd + n0 + tx];
    __syncthreads();
    #pragma unroll
    for (int i = 0; i < 4; i++)
        WT[(size_t)(n0 + ty + i * 8) * Kd + k0 + tx] =
            __float2half_rn(t[tx][ty + i * 8]);
}

// ---------------------------------------------------------------------------
// FP16 tensor-core GEMM (round-11 proven config, untouched):
// 128x128 tile, BK=32 halves, 8 warps, 3-stage cp.async, 2 CTAs/SM.
// ---------------------------------------------------------------------------
#define HSTR 40
#define GSTG (128 * HSTR * 2)                    // halves per stage (A+B)
#define GEMM_SMEM (3 * GSTG * 2)                 // bytes = 61440

__device__ __forceinline__ void gemm_core_h(
    const __half* __restrict__ A, const __half* __restrict__ BT,
    float* __restrict__ C, int N, int K, int bm, int bn)
{
    extern __shared__ __half gsm[];

    const int tid  = threadIdx.x;
    const int lane = tid & 31;
    const int w    = tid >> 5;
    const int wm   = (w >> 2) * 64;
    const int wn   = (w & 3) * 32;
    const int lr   = lane >> 2;
    const int lc   = lane & 3;

    const int l_r = tid >> 2;
    const int l_c = (tid & 3) * 8;

    float acc[4][4][4];
    #pragma unroll
    for (int mi = 0; mi < 4; mi++)
        #pragma unroll
        for (int nj = 0; nj < 4; nj++)
            #pragma unroll
            for (int u = 0; u < 4; u++) acc[mi][nj][u] = 0.f;

    const int T = K / 32;

    auto load_tile = [&](int kt, int buf) {
        __half* as = gsm + buf * GSTG;
        __half* bs = as + 128 * HSTR;
        const __half* ag = A + (size_t)(bm + l_r) * K + kt * 32 + l_c;
        cp_async16(smem_u32(&as[l_r * HSTR + l_c]), ag);
        cp_async16(smem_u32(&as[(l_r + 64) * HSTR + l_c]), ag + (size_t)64 * K);
        const __half* bg = BT + (size_t)(bn + l_r) * K + kt * 32 + l_c;
        cp_async16(smem_u32(&bs[l_r * HSTR + l_c]), bg);
        cp_async16(smem_u32(&bs[(l_r + 64) * HSTR + l_c]), bg + (size_t)64 * K);
    };

    load_tile(0, 0); CP_COMMIT();
    load_tile(1, 1); CP_COMMIT();

    for (int kt = 0; kt < T; kt++) {
        const int buf = kt % 3;
        CP_WAIT1();
        __syncthreads();
        if (kt + 2 < T) load_tile(kt + 2, (kt + 2) % 3);
        CP_COMMIT();

        const __half* as = gsm + buf * GSTG;
        const __half* bs = as + 128 * HSTR;
        #pragma unroll
        for (int ks = 0; ks < 2; ks++) {
            const int ko = ks * 16 + 2 * lc;
            unsigned af[4][4], bf[4][2];
            #pragma unroll
            for (int mi = 0; mi < 4; mi++) {
                int r = wm + mi * 16 + lr;
                af[mi][0] = *(const unsigned*)&as[r * HSTR + ko];
                af[mi][1] = *(const unsigned*)&as[(r + 8) * HSTR + ko];
                af[mi][2] = *(const unsigned*)&as[r * HSTR + ko + 8];
                af[mi][3] = *(const unsigned*)&as[(r + 8) * HSTR + ko + 8];
            }
            #pragma unroll
            for (int nj = 0; nj < 4; nj++) {
                int cn = wn + nj * 8 + lr;
                bf[nj][0] = *(const unsigned*)&bs[cn * HSTR + ko];
                bf[nj][1] = *(const unsigned*)&bs[cn * HSTR + ko + 8];
            }
            #pragma unroll
            for (int mi = 0; mi < 4; mi++)
                #pragma unroll
                for (int nj = 0; nj < 4; nj++)
                    mma_f16(acc[mi][nj], af[mi], bf[nj]);
        }
    }

    #pragma unroll
    for (int mi = 0; mi < 4; mi++) {
        int r0 = bm + wm + mi * 16 + lr;
        #pragma unroll
        for (int nj = 0; nj < 4; nj++) {
            int cn = bn + wn + nj * 8 + 2 * lc;
            *(float2*)&C[(size_t)r0 * N + cn] =
                make_float2(acc[mi][nj][0], acc[mi][nj][1]);
            *(float2*)&C[(size_t)(r0 + 8) * N + cn] =
                make_float2(acc[mi][nj][2], acc[mi][nj][3]);
        }
    }
}

__global__ __launch_bounds__(256, 2) void gemm_h(
    const __half* __restrict__ A, const __half* __restrict__ BT,
    float* __restrict__ C, int N, int K)
{
    gemm_core_h(A, BT, C, N, K, blockIdx.y * 128, blockIdx.x * 128);
}

__global__ __launch_bounds__(256, 2) void gemm_qkv_h(
    const __half* __restrict__ A,
    const __half* __restrict__ WqT, float* __restrict__ Qo,
    const __half* __restrict__ WkT, float* __restrict__ Ko,
    const __half* __restrict__ WvT, float* __restrict__ Vo)
{
    const int bx = blockIdx.x;
    const int bm = blockIdx.y * 128;
    if (bx < 20)       gemm_core_h(A, WqT, Qo, HID_,     HID_, bm, bx * 128);
    else if (bx < 25)  gemm_core_h(A, WkT, Ko, KV_ * D_, HID_, bm, (bx - 20) * 128);
    else               gemm_core_h(A, WvT, Vo, KV_ * D_, HID_, bm, (bx - 25) * 128);
}

// ---------------------------------------------------------------------------
// RoPE (in-place, fp32 Q/K)
// ---------------------------------------------------------------------------
__global__ void rope_kernel(float* __restrict__ X,
                            const float* __restrict__ cosf,
                            const float* __restrict__ sinf,
                            int nheads, size_t total)
{
    size_t idx = (size_t)blockIdx.x * blockDim.x + threadIdx.x;
    if (idx >= total) return;
    int d = (int)(idx % 40);
    size_t t = idx / 40;
    int head = (int)(t % nheads);
    size_t row = t / nheads;
    int s = (int)(row % S_);

    float* base = X + row * ((size_t)nheads * D_) + (size_t)head * D_;
    float x1 = base[d];
    float x2 = base[d + 40];
    float c1 = cosf[(size_t)s * D_ + d];
    float s1 = sinf[(size_t)s * D_ + d];
    float c2 = cosf[(size_t)s * D_ + d + 40];
    float s2 = sinf[(size_t)s * D_ + d + 40];
    base[d]      = x1 * c1 - x2 * s1;
    base[d + 40] = x2 * c2 + x1 * s2;
}

// ---------------------------------------------------------------------------
// Flash attention: FOUR query heads per block (full GQA group shares K/V).
// QK fp16 single-term; PV fp16 single-term; softmax fp32.
// Register-staged K/V prefetch, 4 barriers/ktile. Arithmetic identical to R13.
// ---------------------------------------------------------------------------
#define AQH 88   // half stride for Q/K tiles
#define VTS 72   // half stride (k-dim) for transposed V [d][k]
#define APH 72   // half stride for P tiles
#define AP  68   // float stride for raw score tiles

__device__ __forceinline__ unsigned h2u(__half a, __half b) {
    __half2 p = __halves2half2(a, b);
    return *(unsigned*)&p;
}

__global__ __launch_bounds__(256, 1) void attn_mma4(
    const float* __restrict__ Q, const float* __restrict__ K,
    const float* __restrict__ V, __half* __restrict__ O)
{
    extern __shared__ char smb[];
    __half* Qh[4];
    Qh[0] = (__half*)smb;
    Qh[1] = Qh[0] + 64 * AQH;
    Qh[2] = Qh[1] + 64 * AQH;
    Qh[3] = Qh[2] + 64 * AQH;
    __half* Khh = Qh[3] + 64 * AQH;
    __half* Vt  = Khh + 64 * AQH;            // 80 rows (d) x VTS (k)
    __half* Pm[4];
    Pm[0] = Vt + 80 * VTS;
    Pm[1] = Pm[0] + 64 * APH;
    Pm[2] = Pm[1] + 64 * APH;
    Pm[3] = Pm[2] + 64 * APH;
    float* Sf[4];
    Sf[0] = (float*)(Pm[3] + 64 * APH);
    Sf[1] = Sf[0] + 64 * AP;
    Sf[2] = Sf[1] + 64 * AP;
    Sf[3] = Sf[2] + 64 * AP;
    float* cr[4];
    cr[0] = Sf[3] + 64 * AP;
    cr[1] = cr[0] + 64;
    cr[2] = cr[1] + 64;
    cr[3] = cr[2] + 64;

    const int tid  = threadIdx.x;
    const int lane = tid & 31;
    const int w    = tid >> 5;
    const int lr   = lane >> 2;
    const int lc   = lane & 3;
    const int wm   = (w >> 1) * 16;
    const int wnq  = (w & 1) * 32;
    const int wnp  = (w & 1) * 40;

    const int by  = blockIdx.y;              // 0..15
    const int b   = by >> 3;
    const int kvh = by & 7;
    const int h0  = kvh * G_;                // heads h0..h0+3
    const int q0  = blockIdx.x * 64;
    const float rscale = 0.11180339887498949f;

    float4 kreg[5], vreg[5];

    auto load_kv = [&](int kt) {
        #pragma unroll
        for (int j = 0; j < 5; j++) {
            int i = tid + j * 256;
            int r = i / 20, c4 = (i % 20) * 4;
            size_t base = ((size_t)(b * S_ + kt + r)) * (KV_ * D_) + kvh * D_ + c4;
            kreg[j] = *(const float4*)(K + base);
            vreg[j] = *(const float4*)(V + base);
        }
    };
    auto split_kv = [&]() {
        #pragma unroll
        for (int j = 0; j < 5; j++) {
            int i = tid + j * 256;
            int r = i / 20, c4 = (i % 20) * 4;
            float4 kv = kreg[j], vv = vreg[j];
            *(uint2*)(Khh + r * AQH + c4) = make_uint2(
                h2u(__float2half_rn(kv.x), __float2half_rn(kv.y)),
                h2u(__float2half_rn(kv.z), __float2half_rn(kv.w)));
            Vt[(c4 + 0) * VTS + r] = __float2half_rn(vv.x);
            Vt[(c4 + 1) * VTS + r] = __float2half_rn(vv.y);
            Vt[(c4 + 2) * VTS + r] = __float2half_rn(vv.z);
            Vt[(c4 + 3) * VTS + r] = __float2half_rn(vv.w);
        }
    };

    load_kv(0);

    // Q: scale + fp16 for all 4 heads
    #pragma unroll
    for (int hh = 0; hh < 4; hh++) {
        __half* qh = Qh[hh];
        for (int i = tid; i < 64 * 20; i += 256) {
            int r = i / 20, c4 = (i % 20) * 4;
            float4 v = *(const float4*)(Q + ((size_t)(b * S_ + q0 + r)) * (H_ * D_)
                                          + (h0 + hh) * D_ + c4);
            *(uint2*)(qh + r * AQH + c4) = make_uint2(
                h2u(__float2half_rn(v.x * rscale), __float2half_rn(v.y * rscale)),
                h2u(__float2half_rn(v.z * rscale), __float2half_rn(v.w * rscale)));
        }
    }
    split_kv();

    const int myrow = tid >> 2;
    const int myg   = tid & 3;
    float mm[4] = {-1e30f, -1e30f, -1e30f, -1e30f};
    float ll[4] = {0.f, 0.f, 0.f, 0.f};

    float co[4][5][4];
    #pragma unroll
    for (int hh = 0; hh < 4; hh++)
        #pragma unroll
        for (int nj = 0; nj < 5; nj++)
            #pragma unroll
            for (int u = 0; u < 4; u++) co[hh][nj][u] = 0.f;

    for (int k0 = 0; k0 <= q0; k0 += 64) {
        __syncthreads();

        // QK^T (fp16, single-term) for all heads
        #pragma unroll
        for (int hh = 0; hh < 4; hh++) {
            const __half* Qhp = Qh[hh];
            float* Ps = Sf[hh];

            float cq[4][4];
            #pragma unroll
            for (int nj = 0; nj < 4; nj++)
                #pragma unroll
                for (int u = 0; u < 4; u++) cq[nj][u] = 0.f;

            #pragma unroll
            for (int ks = 0; ks < 5; ks++) {
                const int ko = ks * 16 + 2 * lc;
                unsigned ah[4];
                ah[0] = *(const unsigned*)&Qhp[(wm + lr) * AQH + ko];
                ah[1] = *(const unsigned*)&Qhp[(wm + lr + 8) * AQH + ko];
                ah[2] = *(const unsigned*)&Qhp[(wm + lr) * AQH + ko + 8];
                ah[3] = *(const unsigned*)&Qhp[(wm + lr + 8) * AQH + ko + 8];
                #pragma unroll
                for (int nj = 0; nj < 4; nj++) {
                    int cn = wnq + nj * 8 + lr;
                    unsigned bh_[2];
                    bh_[0] = *(const unsigned*)&Khh[cn * AQH + ko];
                    bh_[1] = *(const unsigned*)&Khh[cn * AQH + ko + 8];
                    mma_f16(cq[nj], ah, bh_);
                }
            }

            #pragma unroll
            for (int nj = 0; nj < 4; nj++) {
                int col = wnq + nj * 8 + 2 * lc;
                int r0 = wm + lr, r1 = wm + lr + 8;
                Ps[r0 * AP + col]     = (k0 + col     <= q0 + r0) ? cq[nj][0] : -1e30f;
                Ps[r0 * AP + col + 1] = (k0 + col + 1 <= q0 + r0) ? cq[nj][1] : -1e30f;
                Ps[r1 * AP + col]     = (k0 + col     <= q0 + r1) ? cq[nj][2] : -1e30f;
                Ps[r1 * AP + col + 1] = (k0 + col + 1 <= q0 + r1) ? cq[nj][3] : -1e30f;
            }
        }
        __syncthreads();

        const int kn = k0 + 64;
        const bool more = (kn <= q0);
        if (more) load_kv(kn);

        // Online softmax (fp32 -> fp16 P), all heads
        #pragma unroll
        for (int hh = 0; hh < 4; hh++) {
            float* Ps = Sf[hh];
            __half* Pmp = Pm[hh];
            float s[16];
            #pragma unroll
            for (int j4 = 0; j4 < 4; j4++) {
                float4 v4 = *(const float4*)(Ps + myrow * AP + myg * 16 + j4 * 4);
                s[j4 * 4 + 0] = v4.x; s[j4 * 4 + 1] = v4.y;
                s[j4 * 4 + 2] = v4.z; s[j4 * 4 + 3] = v4.w;
            }
            float mx = s[0];
            #pragma unroll
            for (int j = 1; j < 16; j++) mx = fmaxf(mx, s[j]);
            mx = fmaxf(mx, __shfl_xor_sync(0xffffffffu, mx, 1));
            mx = fmaxf(mx, __shfl_xor_sync(0xffffffffu, mx, 2));
            float mnew = fmaxf(mm[hh], mx);
            float corr = __expf(mm[hh] - mnew);
            float rs = 0.f;
            #pragma unroll
            for (int j = 0; j < 16; j += 2) {
                float p0 = __expf(s[j] - mnew);
                float p1 = __expf(s[j + 1] - mnew);
                rs += p0 + p1;
                *(__half2*)(Pmp + myrow * APH + myg * 16 + j) =
                    __floats2half2_rn(p0, p1);
            }
            rs += __shfl_xor_sync(0xffffffffu, rs, 1);
            rs += __shfl_xor_sync(0xffffffffu, rs, 2);
            mm[hh] = mnew;
            ll[hh] = ll[hh] * corr + rs;
            if (myg == 0) cr[hh][myrow] = corr;
        }
        __syncthreads();

        // Rescale + PV (fp16 single-term), all heads
        #pragma unroll
        for (int hh = 0; hh < 4; hh++) {
            const __half* Pmp = Pm[hh];
            float c0 = cr[hh][wm + lr], c1 = cr[hh][wm + lr + 8];
            #pragma unroll
            for (int nj = 0; nj < 5; nj++) {
                co[hh][nj][0] *= c0; co[hh][nj][1] *= c0;
                co[hh][nj][2] *= c1; co[hh][nj][3] *= c1;
            }
            #pragma unroll
            for (int ks = 0; ks < 4; ks++) {
                const int ko = ks * 16 + 2 * lc;
                unsigned a[4];
                a[0] = *(const unsigned*)&Pmp[(wm + lr) * APH + ko];
                a[1] = *(const unsigned*)&Pmp[(wm + lr + 8) * APH + ko];
                a[2] = *(const unsigned*)&Pmp[(wm + lr) * APH + ko + 8];
                a[3] = *(const unsigned*)&Pmp[(wm + lr + 8) * APH + ko + 8];
                #pragma unroll
                for (int nj = 0; nj < 5; nj++) {
                    int cn = wnp + nj * 8 + lr;
                    unsigned bb[2];
                    bb[0] = *(const unsigned*)&Vt[cn * VTS + ko];
                    bb[1] = *(const unsigned*)&Vt[cn * VTS + ko + 8];
                    mma_f16(co[hh][nj], a, bb);
                }
            }
        }
        __syncthreads();

        if (more) split_kv();
    }

    // Epilogue: write half ctx
    if (myg == 0) {
        #pragma unroll
        for (int hh = 0; hh < 4; hh++) cr[hh][myrow] = 1.f / ll[hh];
    }
    __syncthreads();
    #pragma unroll
    for (int hh = 0; hh < 4; hh++) {
        float i0 = cr[hh][wm + lr], i1 = cr[hh][wm + lr + 8];
        size_t ro0 = ((size_t)(b * S_ + q0 + wm + lr)) * (H_ * D_) + (h0 + hh) * D_;
        size_t ro1 = ((size_t)(b * S_ + q0 + wm + lr + 8)) * (H_ * D_) + (h0 + hh) * D_;
        #pragma unroll
        for (int nj = 0; nj < 5; nj++) {
            int col = wnp + nj * 8 + 2 * lc;
            *(__half2*)(O + ro0 + col) =
                __floats2half2_rn(co[hh][nj][0] * i0, co[hh][nj][1] * i0);
            *(__half2*)(O + ro1 + col) =
                __floats2half2_rn(co[hh][nj][2] * i1, co[hh][nj][3] * i1);
        }
    }
}

// ---------------------------------------------------------------------------
// Launch
// ---------------------------------------------------------------------------
extern "C" void kernel_launch(void* const* d_in, const int* in_sizes, int n_in,
                              void* d_out, int out_size)
{
    const float* hs   = (const float*)d_in[0];
    const float* cosf = (const float*)d_in[1];
    const float* sinf = (const float*)d_in[2];
    const float* Wq   = (const float*)d_in[3];
    const float* Wk   = (const float*)d_in[4];
    const float* Wv   = (const float*)d_in[5];
    const float* Wo   = (const float*)d_in[6];
    float* out = (float*)d_out;

    float *Qp, *Kp, *Vp;
    __half *Cph, *HSh, *WqT, *WkT, *WvT, *WoT;
    cudaGetSymbolAddress((void**)&Qp,  g_Q);
    cudaGetSymbolAddress((void**)&Kp,  g_K);
    cudaGetSymbolAddress((void**)&Vp,  g_V);
    cudaGetSymbolAddress((void**)&Cph, g_ctx_h);
    cudaGetSymbolAddress((void**)&HSh, g_hs_h);
    cudaGetSymbolAddress((void**)&WqT, g_WqT);
    cudaGetSymbolAddress((void**)&WkT, g_WkT);
    cudaGetSymbolAddress((void**)&WvT, g_WvT);
    cudaGetSymbolAddress((void**)&WoT, g_WoT);

    // Pre-passes
    {
        int n4 = (int)((size_t)BS_ * HID_ / 4);
        convert_half<<<(n4 + 255) / 256, 256>>>(
            (const float4*)hs, (__half2*)HSh, n4);
        dim3 tb(32, 8);
        transpose_h<<<dim3(HID_ / 32, HID_ / 32), tb>>>(Wq, WqT, HID_, HID_);
        transpose_h<<<dim3((KV_ * D_) / 32, HID_ / 32), tb>>>(Wk, WkT, HID_, KV_ * D_);
        transpose_h<<<dim3((KV_ * D_) / 32, HID_ / 32), tb>>>(Wv, WvT, HID_, KV_ * D_);
        transpose_h<<<dim3(HID_ / 32, HID_ / 32), tb>>>(Wo, WoT, HID_, HID_);
    }

    cudaFuncSetAttribute(gemm_qkv_h,
                         cudaFuncAttributeMaxDynamicSharedMemorySize, GEMM_SMEM);
    cudaFuncSetAttribute(gemm_h,
                         cudaFuncAttributeMaxDynamicSharedMemorySize, GEMM_SMEM);

    // Fused QKV projection (fp16, 3-stage)
    {
        dim3 g(30, BS_ / 128);
        gemm_qkv_h<<<g, 256, GEMM_SMEM>>>(HSh, WqT, Qp, WkT, Kp, WvT, Vp);
    }

    // RoPE on Q and K (fp32)
    {
        size_t tq = (size_t)BS_ * H_ * 40;
        size_t tk = (size_t)BS_ * KV_ * 40;
        rope_kernel<<<(unsigned)((tq + 255) / 256), 256>>>(Qp, cosf, sinf, H_, tq);
        rope_kernel<<<(unsigned)((tk + 255) / 256), 256>>>(Kp, cosf, sinf, KV_, tk);
    }

    // Attention: 4 heads (full GQA group) per block
    {
        const int smem =
            (5 * 64 * AQH + 80 * VTS + 4 * 64 * APH) * 2   // halves
          + (4 * 64 * AP + 4 * 64) * 4;                     // floats
        cudaFuncSetAttribute(attn_mma4,
                             cudaFuncAttributeMaxDynamicSharedMemorySize, smem);
        dim3 ga(S_ / 64, B_ * KV_);              // (32, 16)
        attn_mma4<<<ga, 256, smem>>>(Qp, Kp, Vp, Cph);
    }

    // Output projection (fp16, 3-stage)
    {
        dim3 go(HID_ / 128, BS_ / 128);
        gemm_h<<<go, 256, GEMM_SMEM>>>(Cph, WoT, out, HID_, HID_);
    }
}

// round 15
// speedup vs baseline: 2.1343x; 1.0350x over previous
#include <cuda_runtime.h>
#include <cuda_fp16.h>
#include <math.h>

// Problem constants
#define B_   2
#define S_   2048
#define HID_ 2560
#define H_   32
#define KV_  8
#define D_   80
#define G_   4
#define BS_  (B_*S_)      // 4096 total rows

// Scratch (device globals)
__device__ float  g_Q[(size_t)BS_ * H_ * D_];
__device__ float  g_K[(size_t)BS_ * KV_ * D_];
__device__ float  g_V[(size_t)BS_ * KV_ * D_];
__device__ __half g_ctx_h[(size_t)BS_ * H_ * D_];
__device__ __half g_hs_h[(size_t)BS_ * HID_];
__device__ __half g_WqT[(size_t)HID_ * H_ * D_];   // [N=2560][K=2560]
__device__ __half g_WkT[(size_t)KV_ * D_ * HID_];  // [640][2560]
__device__ __half g_WvT[(size_t)KV_ * D_ * HID_];
__device__ __half g_WoT[(size_t)HID_ * H_ * D_];   // [2560][2560]

// ---------------------------------------------------------------------------
// Helpers
// ---------------------------------------------------------------------------
__device__ __forceinline__ unsigned smem_u32(const void* p) {
    return (unsigned)__cvta_generic_to_shared(p);
}
__device__ __forceinline__ void cp_async16(unsigned dst, const void* src) {
    asm volatile("cp.async.cg.shared.global [%0], [%1], 16;\n"
                 :: "r"(dst), "l"(src));
}
#define CP_COMMIT() asm volatile("cp.async.commit_group;\n" ::: "memory")
#define CP_WAIT1()  asm volatile("cp.async.wait_group 1;\n" ::: "memory")

__device__ __forceinline__ void mma_f16(float* c, const unsigned* a, const unsigned* b) {
    asm volatile(
        "mma.sync.aligned.m16n8k16.row.col.f32.f16.f16.f32 "
        "{%0,%1,%2,%3}, {%4,%5,%6,%7}, {%8,%9}, {%0,%1,%2,%3};\n"
        : "+f"(c[0]), "+f"(c[1]), "+f"(c[2]), "+f"(c[3])
        : "r"(a[0]), "r"(a[1]), "r"(a[2]), "r"(a[3]), "r"(b[0]), "r"(b[1]));
}

// ---------------------------------------------------------------------------
// Pre-passes: hs -> half ; weights -> transposed half [N][K]
// ---------------------------------------------------------------------------
__global__ void convert_half(const float4* __restrict__ in,
                             __half2* __restrict__ out, int n4)
{
    int i = blockIdx.x * blockDim.x + threadIdx.x;
    if (i < n4) {
        float4 v = in[i];
        out[2 * i]     = __floats2half2_rn(v.x, v.y);
        out[2 * i + 1] = __floats2half2_rn(v.z, v.w);
    }
}

__global__ void transpose_h(const float* __restrict__ W,
                            __half* __restrict__ WT, int Kd, int Nd)
{
    __shared__ float t[32][33];
    int n0 = blockIdx.x * 32, k0 = blockIdx.y * 32;
    int tx = threadIdx.x, ty = threadIdx.y;
    #pragma unroll
    for (int i = 0; i < 4; i++)
        t[ty + i * 8][tx] = W[(size_t)(k0 + ty + i * 8) * Nd + n0 + tx];
    __syncthreads();
    #pragma unroll
    for (int i = 0; i < 4; i++)
        WT[(size_t)(n0 + ty + i * 8) * Kd + k0 + tx] =
            __float2half_rn(t[tx][ty + i * 8]);
}

// ---------------------------------------------------------------------------
// FP16 tensor-core GEMM (round-11 proven config, untouched):
// 128x128 tile, BK=32 halves, 8 warps, 3-stage cp.async, 2 CTAs/SM.
// ---------------------------------------------------------------------------
#define HSTR 40
#define GSTG (128 * HSTR * 2)                    // halves per stage (A+B)
#define GEMM_SMEM (3 * GSTG * 2)                 // bytes = 61440

__device__ __forceinline__ void gemm_core_h(
    const __half* __restrict__ A, const __half* __restrict__ BT,
    float* __restrict__ C, int N, int K, int bm, int bn)
{
    extern __shared__ __half gsm[];

    const int tid  = threadIdx.x;
    const int lane = tid & 31;
    const int w    = tid >> 5;
    const int wm   = (w >> 2) * 64;
    const int wn   = (w & 3) * 32;
    const int lr   = lane >> 2;
    const int lc   = lane & 3;

    const int l_r = tid >> 2;
    const int l_c = (tid & 3) * 8;

    float acc[4][4][4];
    #pragma unroll
    for (int mi = 0; mi < 4; mi++)
        #pragma unroll
        for (int nj = 0; nj < 4; nj++)
            #pragma unroll
            for (int u = 0; u < 4; u++) acc[mi][nj][u] = 0.f;

    const int T = K / 32;

    auto load_tile = [&](int kt, int buf) {
        __half* as = gsm + buf * GSTG;
        __half* bs = as + 128 * HSTR;
        const __half* ag = A + (size_t)(bm + l_r) * K + kt * 32 + l_c;
        cp_async16(smem_u32(&as[l_r * HSTR + l_c]), ag);
        cp_async16(smem_u32(&as[(l_r + 64) * HSTR + l_c]), ag + (size_t)64 * K);
        const __half* bg = BT + (size_t)(bn + l_r) * K + kt * 32 + l_c;
        cp_async16(smem_u32(&bs[l_r * HSTR + l_c]), bg);
        cp_async16(smem_u32(&bs[(l_r + 64) * HSTR + l_c]), bg + (size_t)64 * K);
    };

    load_tile(0, 0); CP_COMMIT();
    load_tile(1, 1); CP_COMMIT();

    for (int kt = 0; kt < T; kt++) {
        const int buf = kt % 3;
        CP_WAIT1();
        __syncthreads();
        if (kt + 2 < T) load_tile(kt + 2, (kt + 2) % 3);
        CP_COMMIT();

        const __half* as = gsm + buf * GSTG;
        const __half* bs = as + 128 * HSTR;
        #pragma unroll
        for (int ks = 0; ks < 2; ks++) {
            const int ko = ks * 16 + 2 * lc;
            unsigned af[4][4], bf[4][2];
            #pragma unroll
            for (int mi = 0; mi < 4; mi++) {
                int r = wm + mi * 16 + lr;
                af[mi][0] = *(const unsigned*)&as[r * HSTR + ko];
                af[mi][1] = *(const unsigned*)&as[(r + 8) * HSTR + ko];
                af[mi][2] = *(const unsigned*)&as[r * HSTR + ko + 8];
                af[mi][3] = *(const unsigned*)&as[(r + 8) * HSTR + ko + 8];
            }
            #pragma unroll
            for (int nj = 0; nj < 4; nj++) {
                int cn = wn + nj * 8 + lr;
                bf[nj][0] = *(const unsigned*)&bs[cn * HSTR + ko];
                bf[nj][1] = *(const unsigned*)&bs[cn * HSTR + ko + 8];
            }
            #pragma unroll
            for (int mi = 0; mi < 4; mi++)
                #pragma unroll
                for (int nj = 0; nj < 4; nj++)
                    mma_f16(acc[mi][nj], af[mi], bf[nj]);
        }
    }

    #pragma unroll
    for (int mi = 0; mi < 4; mi++) {
        int r0 = bm + wm + mi * 16 + lr;
        #pragma unroll
        for (int nj = 0; nj < 4; nj++) {
            int cn = bn + wn + nj * 8 + 2 * lc;
            *(float2*)&C[(size_t)r0 * N + cn] =
                make_float2(acc[mi][nj][0], acc[mi][nj][1]);
            *(float2*)&C[(size_t)(r0 + 8) * N + cn] =
                make_float2(acc[mi][nj][2], acc[mi][nj][3]);
        }
    }
}

__global__ __launch_bounds__(256, 2) void gemm_h(
    const __half* __restrict__ A, const __half* __restrict__ BT,
    float* __restrict__ C, int N, int K)
{
    gemm_core_h(A, BT, C, N, K, blockIdx.y * 128, blockIdx.x * 128);
}

__global__ __launch_bounds__(256, 2) void gemm_qkv_h(
    const __half* __restrict__ A,
    const __half* __restrict__ WqT, float* __restrict__ Qo,
    const __half* __restrict__ WkT, float* __restrict__ Ko,
    const __half* __restrict__ WvT, float* __restrict__ Vo)
{
    const int bx = blockIdx.x;
    const int bm = blockIdx.y * 128;
    if (bx < 20)       gemm_core_h(A, WqT, Qo, HID_,     HID_, bm, bx * 128);
    else if (bx < 25)  gemm_core_h(A, WkT, Ko, KV_ * D_, HID_, bm, (bx - 20) * 128);
    else               gemm_core_h(A, WvT, Vo, KV_ * D_, HID_, bm, (bx - 25) * 128);
}

// ---------------------------------------------------------------------------
// RoPE (in-place, fp32) — K only now; Q's rope is fused into attention.
// ---------------------------------------------------------------------------
__global__ void rope_kernel(float* __restrict__ X,
                            const float* __restrict__ cosf,
                            const float* __restrict__ sinf,
                            int nheads, size_t total)
{
    size_t idx = (size_t)blockIdx.x * blockDim.x + threadIdx.x;
    if (idx >= total) return;
    int d = (int)(idx % 40);
    size_t t = idx / 40;
    int head = (int)(t % nheads);
    size_t row = t / nheads;
    int s = (int)(row % S_);

    float* base = X + row * ((size_t)nheads * D_) + (size_t)head * D_;
    float x1 = base[d];
    float x2 = base[d + 40];
    float c1 = cosf[(size_t)s * D_ + d];
    float s1 = sinf[(size_t)s * D_ + d];
    float c2 = cosf[(size_t)s * D_ + d + 40];
    float s2 = sinf[(size_t)s * D_ + d + 40];
    base[d]      = x1 * c1 - x2 * s1;
    base[d + 40] = x2 * c2 + x1 * s2;
}

// ---------------------------------------------------------------------------
// Flash attention: 4 heads/block; Q-rope FUSED into the prologue (same fp32
// ops as rope_kernel, then *rscale, then fp16 — bitwise identical to R14).
// Descending-work block order (q0 from reversed blockIdx.x) for LPT packing.
// QK/PV fp16 single-term; softmax fp32; register-staged K/V prefetch.
// ---------------------------------------------------------------------------
#define AQH 88   // half stride for Q/K tiles
#define VTS 72   // half stride (k-dim) for transposed V [d][k]
#define APH 72   // half stride for P tiles
#define AP  68   // float stride for raw score tiles

__device__ __forceinline__ unsigned h2u(__half a, __half b) {
    __half2 p = __halves2half2(a, b);
    return *(unsigned*)&p;
}

__global__ __launch_bounds__(256, 1) void attn_mma4(
    const float* __restrict__ Q, const float* __restrict__ K,
    const float* __restrict__ V, __half* __restrict__ O,
    const float* __restrict__ cosg, const float* __restrict__ sing)
{
    extern __shared__ char smb[];
    __half* Qh[4];
    Qh[0] = (__half*)smb;
    Qh[1] = Qh[0] + 64 * AQH;
    Qh[2] = Qh[1] + 64 * AQH;
    Qh[3] = Qh[2] + 64 * AQH;
    __half* Khh = Qh[3] + 64 * AQH;
    __half* Vt  = Khh + 64 * AQH;            // 80 rows (d) x VTS (k)
    __half* Pm[4];
    Pm[0] = Vt + 80 * VTS;
    Pm[1] = Pm[0] + 64 * APH;
    Pm[2] = Pm[1] + 64 * APH;
    Pm[3] = Pm[2] + 64 * APH;
    float* Sf[4];
    Sf[0] = (float*)(Pm[3] + 64 * APH);
    Sf[1] = Sf[0] + 64 * AP;
    Sf[2] = Sf[1] + 64 * AP;
    Sf[3] = Sf[2] + 64 * AP;
    float* cr[4];
    cr[0] = Sf[3] + 64 * AP;
    cr[1] = cr[0] + 64;
    cr[2] = cr[1] + 64;
    cr[3] = cr[2] + 64;

    const int tid  = threadIdx.x;
    const int lane = tid & 31;
    const int w    = tid >> 5;
    const int lr   = lane >> 2;
    const int lc   = lane & 3;
    const int wm   = (w >> 1) * 16;
    const int wnq  = (w & 1) * 32;
    const int wnp  = (w & 1) * 40;

    const int by  = blockIdx.y;              // 0..15
    const int b   = by >> 3;
    const int kvh = by & 7;
    const int h0  = kvh * G_;                // heads h0..h0+3
    // Descending-work order: largest q-tile (most ktiles) launches first.
    const int q0  = (int)(gridDim.x - 1 - blockIdx.x) * 64;
    const float rscale = 0.11180339887498949f;

    float4 kreg[5], vreg[5];

    auto load_kv = [&](int kt) {
        #pragma unroll
        for (int j = 0; j < 5; j++) {
            int i = tid + j * 256;
            int r = i / 20, c4 = (i % 20) * 4;
            size_t base = ((size_t)(b * S_ + kt + r)) * (KV_ * D_) + kvh * D_ + c4;
            kreg[j] = *(const float4*)(K + base);
            vreg[j] = *(const float4*)(V + base);
        }
    };
    auto split_kv = [&]() {
        #pragma unroll
        for (int j = 0; j < 5; j++) {
            int i = tid + j * 256;
            int r = i / 20, c4 = (i % 20) * 4;
            float4 kv = kreg[j], vv = vreg[j];
            *(uint2*)(Khh + r * AQH + c4) = make_uint2(
                h2u(__float2half_rn(kv.x), __float2half_rn(kv.y)),
                h2u(__float2half_rn(kv.z), __float2half_rn(kv.w)));
            Vt[(c4 + 0) * VTS + r] = __float2half_rn(vv.x);
            Vt[(c4 + 1) * VTS + r] = __float2half_rn(vv.y);
            Vt[(c4 + 2) * VTS + r] = __float2half_rn(vv.z);
            Vt[(c4 + 3) * VTS + r] = __float2half_rn(vv.w);
        }
    };

    load_kv(0);

    // Q: fused rope + scale + fp16 for all 4 heads.
    // i indexes (head, row, pair): 4 * 64 * 10 = 2560 -> exactly 10 iters/thread.
    for (int i = tid; i < 4 * 64 * 10; i += 256) {
        int p  = i % 10;          // pair index: d = 4p and 4p+40
        int t2 = i / 10;
        int r  = t2 % 64;
        int hh = t2 / 64;
        int d  = p * 4;
        const float* qb = Q + ((size_t)(b * S_ + q0 + r)) * (H_ * D_)
                            + (h0 + hh) * D_;
        float4 x1 = *(const float4*)(qb + d);
        float4 x2 = *(const float4*)(qb + d + 40);
        const float* cb = cosg + (size_t)(q0 + r) * D_;
        const float* sb = sing + (size_t)(q0 + r) * D_;
        float4 c1 = *(const float4*)(cb + d);
        float4 s1 = *(const float4*)(sb + d);
        float4 c2 = *(const float4*)(cb + d + 40);
        float4 s2 = *(const float4*)(sb + d + 40);
        // identical op order to rope_kernel, then *rscale, then fp16
        float y1x = (x1.x * c1.x - x2.x * s1.x) * rscale;
        float y1y = (x1.y * c1.y - x2.y * s1.y) * rscale;
        float y1z = (x1.z * c1.z - x2.z * s1.z) * rscale;
        float y1w = (x1.w * c1.w - x2.w * s1.w) * rscale;
        float y2x = (x2.x * c2.x + x1.x * s2.x) * rscale;
        float y2y = (x2.y * c2.y + x1.y * s2.y) * rscale;
        float y2z = (x2.z * c2.z + x1.z * s2.z) * rscale;
        float y2w = (x2.w * c2.w + x1.w * s2.w) * rscale;
        __half* qh = Qh[hh];
        *(uint2*)(qh + r * AQH + d) = make_uint2(
            h2u(__float2half_rn(y1x), __float2half_rn(y1y)),
            h2u(__float2half_rn(y1z), __float2half_rn(y1w)));
        *(uint2*)(qh + r * AQH + d + 40) = make_uint2(
            h2u(__float2half_rn(y2x), __float2half_rn(y2y)),
            h2u(__float2half_rn(y2z), __float2half_rn(y2w)));
    }
    split_kv();

    const int myrow = tid >> 2;
    const int myg   = tid & 3;
    float mm[4] = {-1e30f, -1e30f, -1e30f, -1e30f};
    float ll[4] = {0.f, 0.f, 0.f, 0.f};

    float co[4][5][4];
    #pragma unroll
    for (int hh = 0; hh < 4; hh++)
        #pragma unroll
        for (int nj = 0; nj < 5; nj++)
            #pragma unroll
            for (int u = 0; u < 4; u++) co[hh][nj][u] = 0.f;

    for (int k0 = 0; k0 <= q0; k0 += 64) {
        __syncthreads();

        // QK^T (fp16, single-term) for all heads
        #pragma unroll
        for (int hh = 0; hh < 4; hh++) {
            const __half* Qhp = Qh[hh];
            float* Ps = Sf[hh];

            float cq[4][4];
            #pragma unroll
            for (int nj = 0; nj < 4; nj++)
                #pragma unroll
                for (int u = 0; u < 4; u++) cq[nj][u] = 0.f;

            #pragma unroll
            for (int ks = 0; ks < 5; ks++) {
                const int ko = ks * 16 + 2 * lc;
                unsigned ah[4];
                ah[0] = *(const unsigned*)&Qhp[(wm + lr) * AQH + ko];
                ah[1] = *(const unsigned*)&Qhp[(wm + lr + 8) * AQH + ko];
                ah[2] = *(const unsigned*)&Qhp[(wm + lr) * AQH + ko + 8];
                ah[3] = *(const unsigned*)&Qhp[(wm + lr + 8) * AQH + ko + 8];
                #pragma unroll
                for (int nj = 0; nj < 4; nj++) {
                    int cn = wnq + nj * 8 + lr;
                    unsigned bh_[2];
                    bh_[0] = *(const unsigned*)&Khh[cn * AQH + ko];
                    bh_[1] = *(const unsigned*)&Khh[cn * AQH + ko + 8];
                    mma_f16(cq[nj], ah, bh_);
                }
            }

            #pragma unroll
            for (int nj = 0; nj < 4; nj++) {
                int col = wnq + nj * 8 + 2 * lc;
                int r0 = wm + lr, r1 = wm + lr + 8;
                Ps[r0 * AP + col]     = (k0 + col     <= q0 + r0) ? cq[nj][0] : -1e30f;
                Ps[r0 * AP + col + 1] = (k0 + col + 1 <= q0 + r0) ? cq[nj][1] : -1e30f;
                Ps[r1 * AP + col]     = (k0 + col     <= q0 + r1) ? cq[nj][2] : -1e30f;
                Ps[r1 * AP + col + 1] = (k0 + col + 1 <= q0 + r1) ? cq[nj][3] : -1e30f;
            }
        }
        __syncthreads();

        const int kn = k0 + 64;
        const bool more = (kn <= q0);
        if (more) load_kv(kn);

        // Online softmax (fp32 -> fp16 P), all heads
        #pragma unroll
        for (int hh = 0; hh < 4; hh++) {
            float* Ps = Sf[hh];
            __half* Pmp = Pm[hh];
            float s[16];
            #pragma unroll
            for (int j4 = 0; j4 < 4; j4++) {
                float4 v4 = *(const float4*)(Ps + myrow * AP + myg * 16 + j4 * 4);
                s[j4 * 4 + 0] = v4.x; s[j4 * 4 + 1] = v4.y;
                s[j4 * 4 + 2] = v4.z; s[j4 * 4 + 3] = v4.w;
            }
            float mx = s[0];
            #pragma unroll
            for (int j = 1; j < 16; j++) mx = fmaxf(mx, s[j]);
            mx = fmaxf(mx, __shfl_xor_sync(0xffffffffu, mx, 1));
            mx = fmaxf(mx, __shfl_xor_sync(0xffffffffu, mx, 2));
            float mnew = fmaxf(mm[hh], mx);
            float corr = __expf(mm[hh] - mnew);
            float rs = 0.f;
            #pragma unroll
            for (int j = 0; j < 16; j += 2) {
                float p0 = __expf(s[j] - mnew);
                float p1 = __expf(s[j + 1] - mnew);
                rs += p0 + p1;
                *(__half2*)(Pmp + myrow * APH + myg * 16 + j) =
                    __floats2half2_rn(p0, p1);
            }
            rs += __shfl_xor_sync(0xffffffffu, rs, 1);
            rs += __shfl_xor_sync(0xffffffffu, rs, 2);
            mm[hh] = mnew;
            ll[hh] = ll[hh] * corr + rs;
            if (myg == 0) cr[hh][myrow] = corr;
        }
        __syncthreads();

        // Rescale + PV (fp16 single-term), all heads
        #pragma unroll
        for (int hh = 0; hh < 4; hh++) {
            const __half* Pmp = Pm[hh];
            float c0 = cr[hh][wm + lr], c1 = cr[hh][wm + lr + 8];
            #pragma unroll
            for (int nj = 0; nj < 5; nj++) {
                co[hh][nj][0] *= c0; co[hh][nj][1] *= c0;
                co[hh][nj][2] *= c1; co[hh][nj][3] *= c1;
            }
            #pragma unroll
            for (int ks = 0; ks < 4; ks++) {
                const int ko = ks * 16 + 2 * lc;
                unsigned a[4];
                a[0] = *(const unsigned*)&Pmp[(wm + lr) * APH + ko];
                a[1] = *(const unsigned*)&Pmp[(wm + lr + 8) * APH + ko];
                a[2] = *(const unsigned*)&Pmp[(wm + lr) * APH + ko + 8];
                a[3] = *(const unsigned*)&Pmp[(wm + lr + 8) * APH + ko + 8];
                #pragma unroll
                for (int nj = 0; nj < 5; nj++) {
                    int cn = wnp + nj * 8 + lr;
                    unsigned bb[2];
                    bb[0] = *(const unsigned*)&Vt[cn * VTS + ko];
                    bb[1] = *(const unsigned*)&Vt[cn * VTS + ko + 8];
                    mma_f16(co[hh][nj], a, bb);
                }
            }
        }
        __syncthreads();

        if (more) split_kv();
    }

    // Epilogue: write half ctx
    if (myg == 0) {
        #pragma unroll
        for (int hh = 0; hh < 4; hh++) cr[hh][myrow] = 1.f / ll[hh];
    }
    __syncthreads();
    #pragma unroll
    for (int hh = 0; hh < 4; hh++) {
        float i0 = cr[hh][wm + lr], i1 = cr[hh][wm + lr + 8];
        size_t ro0 = ((size_t)(b * S_ + q0 + wm + lr)) * (H_ * D_) + (h0 + hh) * D_;
        size_t ro1 = ((size_t)(b * S_ + q0 + wm + lr + 8)) * (H_ * D_) + (h0 + hh) * D_;
        #pragma unroll
        for (int nj = 0; nj < 5; nj++) {
            int col = wnp + nj * 8 + 2 * lc;
            *(__half2*)(O + ro0 + col) =
                __floats2half2_rn(co[hh][nj][0] * i0, co[hh][nj][1] * i0);
            *(__half2*)(O + ro1 + col) =
                __floats2half2_rn(co[hh][nj][2] * i1, co[hh][nj][3] * i1);
        }
    }
}

// ---------------------------------------------------------------------------
// Launch
// ---------------------------------------------------------------------------
extern "C" void kernel_launch(void* const* d_in, const int* in_sizes, int n_in,
                              void* d_out, int out_size)
{
    const float* hs   = (const float*)d_in[0];
    const float* cosf = (const float*)d_in[1];
    const float* sinf = (const float*)d_in[2];
    const float* Wq   = (const float*)d_in[3];
    const float* Wk   = (const float*)d_in[4];
    const float* Wv   = (const float*)d_in[5];
    const float* Wo   = (const float*)d_in[6];
    float* out = (float*)d_out;

    float *Qp, *Kp, *Vp;
    __half *Cph, *HSh, *WqT, *WkT, *WvT, *WoT;
    cudaGetSymbolAddress((void**)&Qp,  g_Q);
    cudaGetSymbolAddress((void**)&Kp,  g_K);
    cudaGetSymbolAddress((void**)&Vp,  g_V);
    cudaGetSymbolAddress((void**)&Cph, g_ctx_h);
    cudaGetSymbolAddress((void**)&HSh, g_hs_h);
    cudaGetSymbolAddress((void**)&WqT, g_WqT);
    cudaGetSymbolAddress((void**)&WkT, g_WkT);
    cudaGetSymbolAddress((void**)&WvT, g_WvT);
    cudaGetSymbolAddress((void**)&WoT, g_WoT);

    // Pre-passes
    {
        int n4 = (int)((size_t)BS_ * HID_ / 4);
        convert_half<<<(n4 + 255) / 256, 256>>>(
            (const float4*)hs, (__half2*)HSh, n4);
        dim3 tb(32, 8);
        transpose_h<<<dim3(HID_ / 32, HID_ / 32), tb>>>(Wq, WqT, HID_, HID_);
        transpose_h<<<dim3((KV_ * D_) / 32, HID_ / 32), tb>>>(Wk, WkT, HID_, KV_ * D_);
        transpose_h<<<dim3((KV_ * D_) / 32, HID_ / 32), tb>>>(Wv, WvT, HID_, KV_ * D_);
        transpose_h<<<dim3(HID_ / 32, HID_ / 32), tb>>>(Wo, WoT, HID_, HID_);
    }

    cudaFuncSetAttribute(gemm_qkv_h,
                         cudaFuncAttributeMaxDynamicSharedMemorySize, GEMM_SMEM);
    cudaFuncSetAttribute(gemm_h,
                         cudaFuncAttributeMaxDynamicSharedMemorySize, GEMM_SMEM);

    // Fused QKV projection (fp16, 3-stage)
    {
        dim3 g(30, BS_ / 128);
        gemm_qkv_h<<<g, 256, GEMM_SMEM>>>(HSh, WqT, Qp, WkT, Kp, WvT, Vp);
    }

    // RoPE on K only (Q's rope fused into attention)
    {
        size_t tk = (size_t)BS_ * KV_ * 40;
        rope_kernel<<<(unsigned)((tk + 255) / 256), 256>>>(Kp, cosf, sinf, KV_, tk);
    }

    // Attention: 4 heads per block, fused Q-rope, LPT block order
    {
        const int smem =
            (5 * 64 * AQH + 80 * VTS + 4 * 64 * APH) * 2   // halves
          + (4 * 64 * AP + 4 * 64) * 4;                     // floats
        cudaFuncSetAttribute(attn_mma4,
                             cudaFuncAttributeMaxDynamicSharedMemorySize, smem);
        dim3 ga(S_ / 64, B_ * KV_);              // (32, 16)
        attn_mma4<<<ga, 256, smem>>>(Qp, Kp, Vp, Cph, cosf, sinf);
    }

    // Output projection (fp16, 3-stage)
    {
        dim3 go(HID_ / 128, BS_ / 128);
        gemm_h<<<go, 256, GEMM_SMEM>>>(Cph, WoT, out, HID_, HID_);
    }
}